// round 1
// baseline (speedup 1.0000x reference)
#include <cuda_runtime.h>

#define N_NODES 4096
#define F_IN    512
#define NHEADS  4
#define DHEAD   64

// ---------------- device scratch (no allocations allowed) ----------------
__device__ float    g_Wx[NHEADS * N_NODES * DHEAD];   // [h][n][d], 4 MB
__device__ float    g_ssrc[NHEADS * N_NODES];
__device__ float    g_sdst[NHEADS * N_NODES];
__device__ unsigned g_enc[2 * NHEADS];                // encoded per-head maxima: [0..3]=src, [4..7]=dst

// ---------------- helpers ----------------
// order-preserving float<->uint encoding for atomicMax
__device__ __forceinline__ unsigned fenc(float f) {
    unsigned u = __float_as_uint(f);
    return (u & 0x80000000u) ? ~u : (u | 0x80000000u);
}
__device__ __forceinline__ float fdec(unsigned u) {
    unsigned b = (u & 0x80000000u) ? (u & 0x7FFFFFFFu) : ~u;
    return __uint_as_float(b);
}

// fast exp(v) for v <= 0, FMA-pipe only (no MUFU). rel err ~2e-6.
__device__ __forceinline__ float fexp(float v) {
    float x = v * 1.4426950408889634f;          // log2(e)
    x = fmaxf(x, -126.0f);
    float kf = x + 12582912.0f;                 // 2^23 + 2^22 : round-to-nearest-int magic
    int   ki = __float_as_int(kf) - 0x4B400000; // integer part k
    float r  = x - (kf - 12582912.0f);          // r in [-0.5, 0.5]
    float p  = 1.3333558146e-3f;                // Taylor of 2^r
    p = fmaf(p, r, 9.6181291076e-3f);
    p = fmaf(p, r, 5.5504108664e-2f);
    p = fmaf(p, r, 2.4022650696e-1f);
    p = fmaf(p, r, 6.9314718056e-1f);
    p = fmaf(p, r, 1.0f);
    return __int_as_float(__float_as_int(p) + (ki << 23));
}

// ---------------- kernel 0: init encoded maxima ----------------
__global__ void k_init() {
    int t = threadIdx.x;
    if (t < 2 * NHEADS) g_enc[t] = 0u;          // encoded -inf
}

// ---------------- kernel 1: Wx[h][n][d] = x[n,:] @ W[h][:,d] ----------------
// grid (64, 4), 256 threads, 64x64 tile, 4x4 microtile
__global__ __launch_bounds__(256) void k_wx(const float* __restrict__ x,
                                            const float* __restrict__ W) {
    __shared__ float sx[64][33];
    __shared__ float sw[32][64];
    int h  = blockIdx.y;
    int n0 = blockIdx.x * 64;
    int tid = threadIdx.x;
    int tx = tid & 15, ty = tid >> 4;
    const float* Wh = W + (size_t)h * F_IN * DHEAD;

    float acc[4][4] = {};
    for (int k0 = 0; k0 < F_IN; k0 += 32) {
        #pragma unroll
        for (int it = 0; it < 8; it++) {                 // x tile 64x32
            int e = tid + it * 256; int r = e >> 5, c = e & 31;
            sx[r][c] = x[(size_t)(n0 + r) * F_IN + k0 + c];
        }
        #pragma unroll
        for (int it = 0; it < 8; it++) {                 // W tile 32x64
            int e = tid + it * 256; int r = e >> 6, c = e & 63;
            sw[r][c] = Wh[(size_t)(k0 + r) * DHEAD + c];
        }
        __syncthreads();
        #pragma unroll 8
        for (int k = 0; k < 32; k++) {
            float4 b = *(const float4*)&sw[k][tx * 4];
            #pragma unroll
            for (int m = 0; m < 4; m++) {
                float am = sx[ty * 4 + m][k];
                acc[m][0] = fmaf(am, b.x, acc[m][0]);
                acc[m][1] = fmaf(am, b.y, acc[m][1]);
                acc[m][2] = fmaf(am, b.z, acc[m][2]);
                acc[m][3] = fmaf(am, b.w, acc[m][3]);
            }
        }
        __syncthreads();
    }
    #pragma unroll
    for (int m = 0; m < 4; m++) {
        int n = n0 + ty * 4 + m;
        float4 o = make_float4(acc[m][0], acc[m][1], acc[m][2], acc[m][3]);
        *(float4*)&g_Wx[((size_t)h * N_NODES + n) * DHEAD + tx * 4] = o;
    }
}

// ---------------- kernel 2: s_src, s_dst + per-head maxima ----------------
// one warp per (h, n); grid 2048 blocks * 8 warps = 16384 = H*N
__global__ __launch_bounds__(256) void k_s(const float* __restrict__ a) {
    int warp = threadIdx.x >> 5, lane = threadIdx.x & 31;
    int idx = blockIdx.x * 8 + warp;
    int h = idx >> 12;              // /4096
    int n = idx & (N_NODES - 1);
    const float* wxr = g_Wx + ((size_t)h * N_NODES + n) * DHEAD;
    float w0 = wxr[lane], w1 = wxr[lane + 32];
    const float* ah = a + h * 2 * DHEAD;
    float ps = w0 * ah[lane]      + w1 * ah[lane + 32];
    float pd = w0 * ah[64 + lane] + w1 * ah[96 + lane];
    #pragma unroll
    for (int o = 16; o; o >>= 1) {
        ps += __shfl_xor_sync(0xFFFFFFFFu, ps, o);
        pd += __shfl_xor_sync(0xFFFFFFFFu, pd, o);
    }
    if (lane == 0) {
        g_ssrc[h * N_NODES + n] = ps;
        g_sdst[h * N_NODES + n] = pd;
        atomicMax(&g_enc[h],          fenc(ps));
        atomicMax(&g_enc[NHEADS + h], fenc(pd));
    }
}

// ---------------- kernel 3: fused masked-softmax attention + AV ----------------
// grid (32, 4): block = 128 query rows x 1 head. 256 threads.
// per 32-wide j tile: build p in SMEM (FMA-pipe exp), then 128x32x64 fp32 matmul.
__global__ __launch_bounds__(256) void k_attn(const int* __restrict__ adj,
                                              const float* __restrict__ bias,
                                              float* __restrict__ out) {
    __shared__ float s_p[128][33];
    __shared__ float s_wx[32][64];
    __shared__ float s_srcS[128];
    __shared__ float s_den[128];

    int h  = blockIdx.y;
    int i0 = blockIdx.x * 128;
    int tid = threadIdx.x;
    int tx = tid & 15, ty = tid >> 4;         // tx -> d group (4 cols), ty -> i group (8 rows)
    int jlane = tid & 31, iown = tid >> 5;    // p-gen mapping

    if (tid < 128) s_srcS[tid] = g_ssrc[h * N_NODES + i0 + tid];
    float Mh;
    {
        float sm = fdec(g_enc[h]);
        float tm = fdec(g_enc[NHEADS + h]);
        float v = sm + tm;
        Mh = fmaxf(v, 0.2f * v);              // leaky(smax+tmax) >= every logit
    }

    const float* wxh   = g_Wx   + (size_t)h * N_NODES * DHEAD;
    const float* sdsth = g_sdst + (size_t)h * N_NODES;

    float acc[8][4] = {};
    float rden = 0.0f;
    __syncthreads();

    for (int j0 = 0; j0 < N_NODES; j0 += 32) {
        // load Wx tile 32x64 (float4, coalesced)
        #pragma unroll
        for (int it = 0; it < 2; it++) {
            int e = tid + it * 256; int r = e >> 4, c4 = (e & 15) * 4;
            *(float4*)&s_wx[r][c4] = *(const float4*)&wxh[(size_t)(j0 + r) * DHEAD + c4];
        }
        // p generation: 128x32 values, FMA-pipe exp, masked by adj
        float tj = sdsth[j0 + jlane];
        #pragma unroll
        for (int r = 0; r < 16; r++) {
            int i = r * 8 + iown;
            int av = adj[(size_t)(i0 + i) * N_NODES + j0 + jlane];
            float v  = s_srcS[i] + tj;
            float lv = fmaxf(v, 0.2f * v);
            float p  = (av > 0) ? fexp(lv - Mh) : 0.0f;
            s_p[i][jlane] = p;
        }
        __syncthreads();

        // row sums for the softmax denominator
        if (tid < 128) {
            #pragma unroll 8
            for (int k = 0; k < 32; k++) rden += s_p[tid][k];
        }
        // 128x32x64 fp32 matmul: acc += p @ wx
        #pragma unroll 4
        for (int k = 0; k < 32; k++) {
            float4 b = *(const float4*)&s_wx[k][tx * 4];
            #pragma unroll
            for (int m = 0; m < 8; m++) {
                float pm = s_p[ty * 8 + m][k];
                acc[m][0] = fmaf(pm, b.x, acc[m][0]);
                acc[m][1] = fmaf(pm, b.y, acc[m][1]);
                acc[m][2] = fmaf(pm, b.z, acc[m][2]);
                acc[m][3] = fmaf(pm, b.w, acc[m][3]);
            }
        }
        __syncthreads();
    }

    if (tid < 128) s_den[tid] = 1.0f / rden;
    __syncthreads();

    float4 b4 = *(const float4*)&bias[h * DHEAD + tx * 4];
    #pragma unroll
    for (int m = 0; m < 8; m++) {
        int i = ty * 8 + m;
        float inv = s_den[i];
        float4 o;
        o.x = fmaxf(fmaf(acc[m][0], inv, b4.x), 0.0f);
        o.y = fmaxf(fmaf(acc[m][1], inv, b4.y), 0.0f);
        o.z = fmaxf(fmaf(acc[m][2], inv, b4.z), 0.0f);
        o.w = fmaxf(fmaf(acc[m][3], inv, b4.w), 0.0f);
        *(float4*)&out[(size_t)(i0 + i) * (NHEADS * DHEAD) + h * DHEAD + tx * 4] = o;
    }
}

// ---------------- launch ----------------
extern "C" void kernel_launch(void* const* d_in, const int* in_sizes, int n_in,
                              void* d_out, int out_size) {
    const float* x    = (const float*)d_in[0];   // [4096, 512]
    const int*   adj  = (const int*)  d_in[1];   // [4096, 4096]
    const float* W    = (const float*)d_in[2];   // [4, 512, 64]
    const float* a    = (const float*)d_in[3];   // [4, 128]
    const float* bias = (const float*)d_in[4];   // [256]
    float* out = (float*)d_out;                  // [4096, 256]

    k_init<<<1, 32>>>();
    k_wx  <<<dim3(64, NHEADS), 256>>>(x, W);
    k_s   <<<(NHEADS * N_NODES) / 8, 256>>>(a);
    k_attn<<<dim3(N_NODES / 128, NHEADS), 256>>>(adj, bias, out);
}

// round 4
// speedup vs baseline: 1.9532x; 1.9532x over previous
#include <cuda_runtime.h>
#include <cuda_bf16.h>
#include <stdint.h>

#define N_NODES 4096
#define F_IN    512
#define NHEADS  4
#define DHEAD   64

// ---------------- device scratch ----------------
__device__ float    g_Wx[NHEADS * N_NODES * DHEAD];   // [h][n][d] fp32, 4MB
__device__ float    g_ssrc[NHEADS * N_NODES];
__device__ float    g_sdst[NHEADS * N_NODES];
__device__ unsigned g_enc[2 * NHEADS];
__device__ __nv_bfloat16 g_WxT_hi[NHEADS * DHEAD * N_NODES]; // [h][d][n] bf16 hi
__device__ __nv_bfloat16 g_WxT_lo[NHEADS * DHEAD * N_NODES]; // residual lo

// ---------------- helpers ----------------
// pack two fp32 -> bf16x2: first arg -> LOW half, second -> HIGH half
__device__ __forceinline__ uint32_t pack_bf16x2(float lo, float hi) {
    uint32_t r;
    asm("cvt.rn.bf16x2.f32 %0, %1, %2;" : "=r"(r) : "f"(hi), "f"(lo));
    return r;
}
__device__ __forceinline__ float bf_lo_f(uint32_t w) { return __uint_as_float(w << 16); }
__device__ __forceinline__ float bf_hi_f(uint32_t w) { return __uint_as_float(w & 0xFFFF0000u); }

__device__ __forceinline__ unsigned fenc(float f) {
    unsigned u = __float_as_uint(f);
    return (u & 0x80000000u) ? ~u : (u | 0x80000000u);
}
__device__ __forceinline__ float fdec(unsigned u) {
    unsigned b = (u & 0x80000000u) ? (u & 0x7FFFFFFFu) : ~u;
    return __uint_as_float(b);
}

// FMA-pipe exp (no MUFU), rel err ~2e-6; valid for v <= 0
__device__ __forceinline__ float fexp(float v) {
    float x = v * 1.4426950408889634f;
    x = fmaxf(x, -126.0f);
    float kf = x + 12582912.0f;
    int   ki = __float_as_int(kf) - 0x4B400000;
    float r  = x - (kf - 12582912.0f);
    float p  = 1.3333558146e-3f;
    p = fmaf(p, r, 9.6181291076e-3f);
    p = fmaf(p, r, 5.5504108664e-2f);
    p = fmaf(p, r, 2.4022650696e-1f);
    p = fmaf(p, r, 6.9314718056e-1f);
    p = fmaf(p, r, 1.0f);
    return __int_as_float(__float_as_int(p) + (ki << 23));
}

// warp mma: D(16x8,f32) += A(16x16,bf16) * B(16x8,bf16)
__device__ __forceinline__ void mma_bf16(float* c, const uint32_t* a, uint32_t b0, uint32_t b1) {
    asm volatile(
        "mma.sync.aligned.m16n8k16.row.col.f32.bf16.bf16.f32 "
        "{%0,%1,%2,%3}, {%4,%5,%6,%7}, {%8,%9}, {%0,%1,%2,%3};"
        : "+f"(c[0]), "+f"(c[1]), "+f"(c[2]), "+f"(c[3])
        : "r"(a[0]), "r"(a[1]), "r"(a[2]), "r"(a[3]), "r"(b0), "r"(b1));
}

// ---------------- kernel 0 ----------------
__global__ void k_init() {
    int t = threadIdx.x;
    if (t < 2 * NHEADS) g_enc[t] = 0u;
}

// ---------------- kernel 1: Wx = x @ W per head ----------------
__global__ __launch_bounds__(256) void k_wx(const float* __restrict__ x,
                                            const float* __restrict__ W) {
    __shared__ __align__(16) float sx[64][33];
    __shared__ __align__(16) float sw[32][64];
    int h  = blockIdx.y;
    int n0 = blockIdx.x * 64;
    int tid = threadIdx.x;
    int tx = tid & 15, ty = tid >> 4;
    const float* Wh = W + (size_t)h * F_IN * DHEAD;

    float acc[4][4] = {};
    for (int k0 = 0; k0 < F_IN; k0 += 32) {
        #pragma unroll
        for (int it = 0; it < 8; it++) {
            int e = tid + it * 256; int r = e >> 5, c = e & 31;
            sx[r][c] = x[(size_t)(n0 + r) * F_IN + k0 + c];
        }
        #pragma unroll
        for (int it = 0; it < 8; it++) {
            int e = tid + it * 256; int r = e >> 6, c = e & 63;
            sw[r][c] = Wh[(size_t)(k0 + r) * DHEAD + c];
        }
        __syncthreads();
        #pragma unroll 8
        for (int k = 0; k < 32; k++) {
            float4 b = *(const float4*)&sw[k][tx * 4];
            #pragma unroll
            for (int m = 0; m < 4; m++) {
                float am = sx[ty * 4 + m][k];
                acc[m][0] = fmaf(am, b.x, acc[m][0]);
                acc[m][1] = fmaf(am, b.y, acc[m][1]);
                acc[m][2] = fmaf(am, b.z, acc[m][2]);
                acc[m][3] = fmaf(am, b.w, acc[m][3]);
            }
        }
        __syncthreads();
    }
    #pragma unroll
    for (int m = 0; m < 4; m++) {
        int n = n0 + ty * 4 + m;
        float4 o = make_float4(acc[m][0], acc[m][1], acc[m][2], acc[m][3]);
        *(float4*)&g_Wx[((size_t)h * N_NODES + n) * DHEAD + tx * 4] = o;
    }
}

// ---------------- kernel 2: s_src/s_dst + per-head maxima ----------------
__global__ __launch_bounds__(256) void k_s(const float* __restrict__ a) {
    int warp = threadIdx.x >> 5, lane = threadIdx.x & 31;
    int idx = blockIdx.x * 8 + warp;
    int h = idx >> 12;
    int n = idx & (N_NODES - 1);
    const float* wxr = g_Wx + ((size_t)h * N_NODES + n) * DHEAD;
    float w0 = wxr[lane], w1 = wxr[lane + 32];
    const float* ah = a + h * 2 * DHEAD;
    float ps = w0 * ah[lane]      + w1 * ah[lane + 32];
    float pd = w0 * ah[64 + lane] + w1 * ah[96 + lane];
    #pragma unroll
    for (int o = 16; o; o >>= 1) {
        ps += __shfl_xor_sync(0xFFFFFFFFu, ps, o);
        pd += __shfl_xor_sync(0xFFFFFFFFu, pd, o);
    }
    if (lane == 0) {
        g_ssrc[h * N_NODES + n] = ps;
        g_sdst[h * N_NODES + n] = pd;
        atomicMax(&g_enc[h],          fenc(ps));
        atomicMax(&g_enc[NHEADS + h], fenc(pd));
    }
}

// ---------------- kernel 2b: transpose Wx -> [h][d][n] bf16 hi/lo ----------------
__global__ __launch_bounds__(256) void k_trans() {
    __shared__ __align__(16) float s[64][65];   // 65-pad: conflict-free column reads
    int h = blockIdx.y, n0 = blockIdx.x * 64;
    int tid = threadIdx.x;
    #pragma unroll
    for (int k = 0; k < 4; k++) {
        int e = tid + k * 256; int r = e >> 4, c4 = (e & 15) * 4;
        // vector load from gmem (16B aligned), scalar stores into odd-stride smem
        float4 v = *(const float4*)&g_Wx[((size_t)h * N_NODES + n0 + r) * DHEAD + c4];
        s[r][c4 + 0] = v.x; s[r][c4 + 1] = v.y; s[r][c4 + 2] = v.z; s[r][c4 + 3] = v.w;
    }
    __syncthreads();
    int d = tid >> 2, nb = (tid & 3) * 16;
    uint32_t hw[8], lw[8];
    #pragma unroll
    for (int e = 0; e < 8; e++) {
        float f0 = s[nb + e * 2][d], f1 = s[nb + e * 2 + 1][d];
        uint32_t hp = pack_bf16x2(f0, f1);
        float r0 = f0 - bf_lo_f(hp), r1 = f1 - bf_hi_f(hp);
        hw[e] = hp;
        lw[e] = pack_bf16x2(r0, r1);
    }
    size_t base = ((size_t)h * DHEAD + d) * N_NODES + n0 + nb;
    *(uint4*)(g_WxT_hi + base)     = make_uint4(hw[0], hw[1], hw[2], hw[3]);
    *(uint4*)(g_WxT_hi + base + 8) = make_uint4(hw[4], hw[5], hw[6], hw[7]);
    *(uint4*)(g_WxT_lo + base)     = make_uint4(lw[0], lw[1], lw[2], lw[3]);
    *(uint4*)(g_WxT_lo + base + 8) = make_uint4(lw[4], lw[5], lw[6], lw[7]);
}

// ---------------- kernel 3: fused masked softmax + HMMA AV ----------------
// grid (32, 4). 256 threads = 8 warps; warp w owns rows [i0+16w, i0+16w+16).
// Per 64-wide j tile: p generated straight into m16n8k16 A fragments (bf16 hi/lo),
// B = WxT tile (hi/lo) staged in SMEM with pad-72 rows, reg-prefetched.
#define BPAD 72
__global__ __launch_bounds__(256) void k_attn(const int* __restrict__ adj,
                                              const float* __restrict__ bias,
                                              float* __restrict__ out) {
    __shared__ __align__(16) __nv_bfloat16 s_bh[64 * BPAD];
    __shared__ __align__(16) __nv_bfloat16 s_bl[64 * BPAD];
    __shared__ __align__(16) float s_sd[N_NODES];      // s_dst row for this head (16KB)

    const int tid = threadIdx.x, wid = tid >> 5, lane = tid & 31;
    const int g = lane >> 2, t2 = (lane & 3) * 2;
    const int h = blockIdx.y;
    const int i0 = blockIdx.x * 128;

    // cache s_dst for this head
    const float* sdh = g_sdst + (size_t)h * N_NODES;
    #pragma unroll
    for (int k = 0; k < 4; k++) {
        int e = tid + k * 256;
        *(float4*)&s_sd[e * 4] = *(const float4*)&sdh[e * 4];
    }

    float Mh;
    {
        float v = fdec(g_enc[h]) + fdec(g_enc[NHEADS + h]);
        Mh = fmaxf(v, 0.2f * v);
    }

    const int r0 = i0 + wid * 16 + g;        // this thread's two output rows
    const int r1 = r0 + 8;
    const float si0 = g_ssrc[h * N_NODES + r0];
    const float si1 = g_ssrc[h * N_NODES + r1];
    const int* adj0 = adj + (size_t)r0 * N_NODES;
    const int* adj1 = adj + (size_t)r1 * N_NODES;

    const __nv_bfloat16* bhip = g_WxT_hi + (size_t)h * DHEAD * N_NODES;
    const __nv_bfloat16* blop = g_WxT_lo + (size_t)h * DHEAD * N_NODES;

    // B prefetch mapping: 2 uint4 (hi) + 2 uint4 (lo) per thread
    const int e0 = tid * 2, e1 = tid * 2 + 1;
    const int pr0 = e0 >> 3, pc0 = (e0 & 7) * 8;
    const int pr1 = e1 >> 3, pc1 = (e1 & 7) * 8;

    uint4 nh0 = *(const uint4*)(bhip + (size_t)pr0 * N_NODES + pc0);
    uint4 nh1 = *(const uint4*)(bhip + (size_t)pr1 * N_NODES + pc1);
    uint4 nl0 = *(const uint4*)(blop + (size_t)pr0 * N_NODES + pc0);
    uint4 nl1 = *(const uint4*)(blop + (size_t)pr1 * N_NODES + pc1);

    float acc[8][4] = {};
    float den0 = 0.0f, den1 = 0.0f;

    for (int t = 0; t < 64; t++) {
        const int j0 = t * 64;
        __syncthreads();                     // readers of previous tile done
        *(uint4*)&s_bh[pr0 * BPAD + pc0] = nh0;
        *(uint4*)&s_bh[pr1 * BPAD + pc1] = nh1;
        *(uint4*)&s_bl[pr0 * BPAD + pc0] = nl0;
        *(uint4*)&s_bl[pr1 * BPAD + pc1] = nl1;
        if (t < 63) {
            int jn = j0 + 64;
            nh0 = *(const uint4*)(bhip + (size_t)pr0 * N_NODES + jn + pc0);
            nh1 = *(const uint4*)(bhip + (size_t)pr1 * N_NODES + jn + pc1);
            nl0 = *(const uint4*)(blop + (size_t)pr0 * N_NODES + jn + pc0);
            nl1 = *(const uint4*)(blop + (size_t)pr1 * N_NODES + jn + pc1);
        }
        __syncthreads();

        // ---- A fragments: p directly in mma layout, bf16 hi/lo ----
        uint32_t ahi[4][4], alo[4][4];
        #pragma unroll
        for (int kf = 0; kf < 4; kf++) {
            const int jb = j0 + kf * 16 + t2;
            int2 m0a = *(const int2*)(adj0 + jb);
            int2 m0b = *(const int2*)(adj0 + jb + 8);
            int2 m1a = *(const int2*)(adj1 + jb);
            int2 m1b = *(const int2*)(adj1 + jb + 8);
            float2 sdA = *(const float2*)&s_sd[jb];
            float2 sdB = *(const float2*)&s_sd[jb + 8];

            float v, lv;
            v = si0 + sdA.x; lv = fmaxf(v, 0.2f * v);
            float p00 = (m0a.x > 0) ? fexp(lv - Mh) : 0.0f;
            v = si0 + sdA.y; lv = fmaxf(v, 0.2f * v);
            float p01 = (m0a.y > 0) ? fexp(lv - Mh) : 0.0f;
            v = si0 + sdB.x; lv = fmaxf(v, 0.2f * v);
            float p08 = (m0b.x > 0) ? fexp(lv - Mh) : 0.0f;
            v = si0 + sdB.y; lv = fmaxf(v, 0.2f * v);
            float p09 = (m0b.y > 0) ? fexp(lv - Mh) : 0.0f;
            v = si1 + sdA.x; lv = fmaxf(v, 0.2f * v);
            float p10 = (m1a.x > 0) ? fexp(lv - Mh) : 0.0f;
            v = si1 + sdA.y; lv = fmaxf(v, 0.2f * v);
            float p11 = (m1a.y > 0) ? fexp(lv - Mh) : 0.0f;
            v = si1 + sdB.x; lv = fmaxf(v, 0.2f * v);
            float p18 = (m1b.x > 0) ? fexp(lv - Mh) : 0.0f;
            v = si1 + sdB.y; lv = fmaxf(v, 0.2f * v);
            float p19 = (m1b.y > 0) ? fexp(lv - Mh) : 0.0f;

            den0 += (p00 + p01) + (p08 + p09);
            den1 += (p10 + p11) + (p18 + p19);

            uint32_t h0 = pack_bf16x2(p00, p01);
            uint32_t h1 = pack_bf16x2(p10, p11);
            uint32_t h2 = pack_bf16x2(p08, p09);
            uint32_t h3 = pack_bf16x2(p18, p19);
            ahi[kf][0] = h0; ahi[kf][1] = h1; ahi[kf][2] = h2; ahi[kf][3] = h3;
            alo[kf][0] = pack_bf16x2(p00 - bf_lo_f(h0), p01 - bf_hi_f(h0));
            alo[kf][1] = pack_bf16x2(p10 - bf_lo_f(h1), p11 - bf_hi_f(h1));
            alo[kf][2] = pack_bf16x2(p08 - bf_lo_f(h2), p09 - bf_hi_f(h2));
            alo[kf][3] = pack_bf16x2(p18 - bf_lo_f(h3), p19 - bf_hi_f(h3));
        }

        // ---- 3-term MMA: acc += Ahi*Bhi + Alo*Bhi + Ahi*Blo ----
        #pragma unroll
        for (int nf = 0; nf < 8; nf++) {
            const int brow = (nf * 8 + g) * BPAD;
            #pragma unroll
            for (int kf = 0; kf < 4; kf++) {
                const int boff = brow + kf * 16 + t2;
                uint32_t bh0 = *(const uint32_t*)&s_bh[boff];
                uint32_t bh1 = *(const uint32_t*)&s_bh[boff + 8];
                uint32_t bl0 = *(const uint32_t*)&s_bl[boff];
                uint32_t bl1 = *(const uint32_t*)&s_bl[boff + 8];
                mma_bf16(acc[nf], ahi[kf], bh0, bh1);
                mma_bf16(acc[nf], alo[kf], bh0, bh1);
                mma_bf16(acc[nf], ahi[kf], bl0, bl1);
            }
        }
    }

    // ---- denominator: reduce over the 4 lanes of each quad ----
    den0 += __shfl_xor_sync(0xFFFFFFFFu, den0, 1);
    den0 += __shfl_xor_sync(0xFFFFFFFFu, den0, 2);
    den1 += __shfl_xor_sync(0xFFFFFFFFu, den1, 1);
    den1 += __shfl_xor_sync(0xFFFFFFFFu, den1, 2);
    const float inv0 = 1.0f / den0;
    const float inv1 = 1.0f / den1;

    // ---- epilogue: normalize + bias + relu ----
    float* orow0 = out + (size_t)r0 * (NHEADS * DHEAD) + h * DHEAD;
    float* orow1 = out + (size_t)r1 * (NHEADS * DHEAD) + h * DHEAD;
    #pragma unroll
    for (int nf = 0; nf < 8; nf++) {
        float2 b2 = *(const float2*)&bias[h * DHEAD + nf * 8 + t2];
        float2 o0, o1;
        o0.x = fmaxf(fmaf(acc[nf][0], inv0, b2.x), 0.0f);
        o0.y = fmaxf(fmaf(acc[nf][1], inv0, b2.y), 0.0f);
        o1.x = fmaxf(fmaf(acc[nf][2], inv1, b2.x), 0.0f);
        o1.y = fmaxf(fmaf(acc[nf][3], inv1, b2.y), 0.0f);
        *(float2*)(orow0 + nf * 8 + t2) = o0;
        *(float2*)(orow1 + nf * 8 + t2) = o1;
    }
}

// ---------------- launch ----------------
extern "C" void kernel_launch(void* const* d_in, const int* in_sizes, int n_in,
                              void* d_out, int out_size) {
    const float* x    = (const float*)d_in[0];
    const int*   adj  = (const int*)  d_in[1];
    const float* W    = (const float*)d_in[2];
    const float* a    = (const float*)d_in[3];
    const float* bias = (const float*)d_in[4];
    float* out = (float*)d_out;

    k_init <<<1, 32>>>();
    k_wx   <<<dim3(64, NHEADS), 256>>>(x, W);
    k_s    <<<(NHEADS * N_NODES) / 8, 256>>>(a);
    k_trans<<<dim3(64, NHEADS), 256>>>();
    k_attn <<<dim3(N_NODES / 128, NHEADS), 256>>>(adj, bias, out);
}

// round 5
// speedup vs baseline: 2.4849x; 1.2722x over previous
#include <cuda_runtime.h>
#include <cuda_bf16.h>
#include <stdint.h>

#define N_NODES 4096
#define F_IN    512
#define NHEADS  4
#define DHEAD   64

// ---------------- device scratch ----------------
__device__ float    g_Wx[NHEADS * N_NODES * DHEAD];   // [h][n][d] fp32, 4MB
__device__ float    g_ssrc[NHEADS * N_NODES];
__device__ float    g_sdst[NHEADS * N_NODES];
__device__ unsigned g_enc[2 * NHEADS];
__device__ __nv_bfloat16 g_WxT_hi[NHEADS * DHEAD * N_NODES]; // [h][d][n] bf16 hi
__device__ __nv_bfloat16 g_WxT_lo[NHEADS * DHEAD * N_NODES]; // residual lo

// ---------------- helpers ----------------
__device__ __forceinline__ uint32_t pack_bf16x2(float lo, float hi) {
    uint32_t r;
    asm("cvt.rn.bf16x2.f32 %0, %1, %2;" : "=r"(r) : "f"(hi), "f"(lo));
    return r;
}
__device__ __forceinline__ float bf_lo_f(uint32_t w) { return __uint_as_float(w << 16); }
__device__ __forceinline__ float bf_hi_f(uint32_t w) { return __uint_as_float(w & 0xFFFF0000u); }

__device__ __forceinline__ unsigned fenc(float f) {
    unsigned u = __float_as_uint(f);
    return (u & 0x80000000u) ? ~u : (u | 0x80000000u);
}
__device__ __forceinline__ float fdec(unsigned u) {
    unsigned b = (u & 0x80000000u) ? (u & 0x7FFFFFFFu) : ~u;
    return __uint_as_float(b);
}

// FMA-pipe exp (no MUFU), rel err ~2e-6; valid for v <= 0
__device__ __forceinline__ float fexp(float v) {
    float x = v * 1.4426950408889634f;
    x = fmaxf(x, -126.0f);
    float kf = x + 12582912.0f;
    int   ki = __float_as_int(kf) - 0x4B400000;
    float r  = x - (kf - 12582912.0f);
    float p  = 1.3333558146e-3f;
    p = fmaf(p, r, 9.6181291076e-3f);
    p = fmaf(p, r, 5.5504108664e-2f);
    p = fmaf(p, r, 2.4022650696e-1f);
    p = fmaf(p, r, 6.9314718056e-1f);
    p = fmaf(p, r, 1.0f);
    return __int_as_float(__float_as_int(p) + (ki << 23));
}

// warp mma: D(16x8,f32) += A(16x16,bf16) * B(16x8,bf16)
__device__ __forceinline__ void mma_bf16(float* c, const uint32_t* a, uint32_t b0, uint32_t b1) {
    asm volatile(
        "mma.sync.aligned.m16n8k16.row.col.f32.bf16.bf16.f32 "
        "{%0,%1,%2,%3}, {%4,%5,%6,%7}, {%8,%9}, {%0,%1,%2,%3};"
        : "+f"(c[0]), "+f"(c[1]), "+f"(c[2]), "+f"(c[3])
        : "r"(a[0]), "r"(a[1]), "r"(a[2]), "r"(a[3]), "r"(b0), "r"(b1));
}

// ---------------- kernel 0 ----------------
__global__ void k_init() {
    int t = threadIdx.x;
    if (t < 2 * NHEADS) g_enc[t] = 0u;
}

// ---------------- kernel 1: Wx = x @ W per head ----------------
__global__ __launch_bounds__(256) void k_wx(const float* __restrict__ x,
                                            const float* __restrict__ W) {
    __shared__ __align__(16) float sx[64][33];
    __shared__ __align__(16) float sw[32][64];
    int h  = blockIdx.y;
    int n0 = blockIdx.x * 64;
    int tid = threadIdx.x;
    int tx = tid & 15, ty = tid >> 4;
    const float* Wh = W + (size_t)h * F_IN * DHEAD;

    float acc[4][4] = {};
    for (int k0 = 0; k0 < F_IN; k0 += 32) {
        #pragma unroll
        for (int it = 0; it < 8; it++) {
            int e = tid + it * 256; int r = e >> 5, c = e & 31;
            sx[r][c] = x[(size_t)(n0 + r) * F_IN + k0 + c];
        }
        #pragma unroll
        for (int it = 0; it < 8; it++) {
            int e = tid + it * 256; int r = e >> 6, c = e & 63;
            sw[r][c] = Wh[(size_t)(k0 + r) * DHEAD + c];
        }
        __syncthreads();
        #pragma unroll 8
        for (int k = 0; k < 32; k++) {
            float4 b = *(const float4*)&sw[k][tx * 4];
            #pragma unroll
            for (int m = 0; m < 4; m++) {
                float am = sx[ty * 4 + m][k];
                acc[m][0] = fmaf(am, b.x, acc[m][0]);
                acc[m][1] = fmaf(am, b.y, acc[m][1]);
                acc[m][2] = fmaf(am, b.z, acc[m][2]);
                acc[m][3] = fmaf(am, b.w, acc[m][3]);
            }
        }
        __syncthreads();
    }
    #pragma unroll
    for (int m = 0; m < 4; m++) {
        int n = n0 + ty * 4 + m;
        float4 o = make_float4(acc[m][0], acc[m][1], acc[m][2], acc[m][3]);
        *(float4*)&g_Wx[((size_t)h * N_NODES + n) * DHEAD + tx * 4] = o;
    }
}

// ---------------- kernel 2: s_src/s_dst + per-head maxima ----------------
__global__ __launch_bounds__(256) void k_s(const float* __restrict__ a) {
    int warp = threadIdx.x >> 5, lane = threadIdx.x & 31;
    int idx = blockIdx.x * 8 + warp;
    int h = idx >> 12;
    int n = idx & (N_NODES - 1);
    const float* wxr = g_Wx + ((size_t)h * N_NODES + n) * DHEAD;
    float w0 = wxr[lane], w1 = wxr[lane + 32];
    const float* ah = a + h * 2 * DHEAD;
    float ps = w0 * ah[lane]      + w1 * ah[lane + 32];
    float pd = w0 * ah[64 + lane] + w1 * ah[96 + lane];
    #pragma unroll
    for (int o = 16; o; o >>= 1) {
        ps += __shfl_xor_sync(0xFFFFFFFFu, ps, o);
        pd += __shfl_xor_sync(0xFFFFFFFFu, pd, o);
    }
    if (lane == 0) {
        g_ssrc[h * N_NODES + n] = ps;
        g_sdst[h * N_NODES + n] = pd;
        atomicMax(&g_enc[h],          fenc(ps));
        atomicMax(&g_enc[NHEADS + h], fenc(pd));
    }
}

// ---------------- kernel 2b: transpose Wx -> [h][d][n] bf16 hi/lo ----------------
__global__ __launch_bounds__(256) void k_trans() {
    __shared__ __align__(16) float s[64][65];
    int h = blockIdx.y, n0 = blockIdx.x * 64;
    int tid = threadIdx.x;
    #pragma unroll
    for (int k = 0; k < 4; k++) {
        int e = tid + k * 256; int r = e >> 4, c4 = (e & 15) * 4;
        float4 v = *(const float4*)&g_Wx[((size_t)h * N_NODES + n0 + r) * DHEAD + c4];
        s[r][c4 + 0] = v.x; s[r][c4 + 1] = v.y; s[r][c4 + 2] = v.z; s[r][c4 + 3] = v.w;
    }
    __syncthreads();
    int d = tid >> 2, nb = (tid & 3) * 16;
    uint32_t hw[8], lw[8];
    #pragma unroll
    for (int e = 0; e < 8; e++) {
        float f0 = s[nb + e * 2][d], f1 = s[nb + e * 2 + 1][d];
        uint32_t hp = pack_bf16x2(f0, f1);
        float r0 = f0 - bf_lo_f(hp), r1 = f1 - bf_hi_f(hp);
        hw[e] = hp;
        lw[e] = pack_bf16x2(r0, r1);
    }
    size_t base = ((size_t)h * DHEAD + d) * N_NODES + n0 + nb;
    *(uint4*)(g_WxT_hi + base)     = make_uint4(hw[0], hw[1], hw[2], hw[3]);
    *(uint4*)(g_WxT_hi + base + 8) = make_uint4(hw[4], hw[5], hw[6], hw[7]);
    *(uint4*)(g_WxT_lo + base)     = make_uint4(lw[0], lw[1], lw[2], lw[3]);
    *(uint4*)(g_WxT_lo + base + 8) = make_uint4(lw[4], lw[5], lw[6], lw[7]);
}

// ---------------- kernel 3: fused masked softmax + HMMA AV ----------------
// Factorized exp: p = adj ? (sj >= -si ? Pi1*Ej1 : Pi2*Ej2) : 0.
// Ej1/Ej2 precomputed per CTA for all 4096 j (SMEM); Pi per thread.
#define BPAD 72
// dynamic SMEM layout
#define SMO_BH  0                         // 64*72 bf16 = 9216
#define SMO_BL  9216                      // 9216
#define SMO_SD  18432                     // 4096 floats = 16384
#define SMO_E   34816                     // 4096 float2 = 32768
#define SMO_TOT 67584

__global__ __launch_bounds__(256) void k_attn(const int* __restrict__ adj,
                                              const float* __restrict__ bias,
                                              float* __restrict__ out) {
    extern __shared__ __align__(16) char dsm[];
    __nv_bfloat16* s_bh = (__nv_bfloat16*)(dsm + SMO_BH);
    __nv_bfloat16* s_bl = (__nv_bfloat16*)(dsm + SMO_BL);
    float*         s_sd = (float*)(dsm + SMO_SD);
    float*         s_e  = (float*)(dsm + SMO_E);   // [j]{Ej1, Ej2}

    const int tid = threadIdx.x, wid = tid >> 5, lane = tid & 31;
    const int g = lane >> 2, t2 = (lane & 3) * 2;
    const int h = blockIdx.y;
    const int i0 = blockIdx.x * 128;

    // per-head softmax bound factorization constants
    const float maxsrc = fdec(g_enc[h]);
    const float maxdst = fdec(g_enc[NHEADS + h]);
    const float S  = maxsrc + maxdst;
    const float Mh = fmaxf(S, 0.2f * S);
    const float r_  = Mh - 0.2f * S;               // >= 0
    const float c_  = 0.2f * maxsrc + 0.5f * r_;
    const float d_  = 0.2f * maxdst + 0.5f * r_;

    // pre-pass: s_sd[j] = sj ; s_e[2j] = exp(sj - maxdst) ; s_e[2j+1] = exp(0.2 sj - d_)
    const float* sdh = g_sdst + (size_t)h * N_NODES;
    #pragma unroll
    for (int k = 0; k < 4; k++) {
        int e = tid + k * 256;
        float4 v = *(const float4*)&sdh[e * 4];
        *(float4*)&s_sd[e * 4] = v;
        float4 o0, o1;
        o0.x = fexp(v.x - maxdst); o0.y = fexp(fmaf(0.2f, v.x, -d_));
        o0.z = fexp(v.y - maxdst); o0.w = fexp(fmaf(0.2f, v.y, -d_));
        o1.x = fexp(v.z - maxdst); o1.y = fexp(fmaf(0.2f, v.z, -d_));
        o1.z = fexp(v.w - maxdst); o1.w = fexp(fmaf(0.2f, v.w, -d_));
        *(float4*)&s_e[e * 8]     = o0;
        *(float4*)&s_e[e * 8 + 4] = o1;
    }

    const int r0 = i0 + wid * 16 + g;
    const int r1 = r0 + 8;
    const float si0 = g_ssrc[h * N_NODES + r0];
    const float si1 = g_ssrc[h * N_NODES + r1];
    const float th0 = -si0, th1 = -si1;
    const float Pi1_0 = fexp(si0 - maxsrc), Pi2_0 = fexp(fmaf(0.2f, si0, -c_));
    const float Pi1_1 = fexp(si1 - maxsrc), Pi2_1 = fexp(fmaf(0.2f, si1, -c_));
    const int* adj0 = adj + (size_t)r0 * N_NODES;
    const int* adj1 = adj + (size_t)r1 * N_NODES;

    const __nv_bfloat16* bhip = g_WxT_hi + (size_t)h * DHEAD * N_NODES;
    const __nv_bfloat16* blop = g_WxT_lo + (size_t)h * DHEAD * N_NODES;

    // B prefetch mapping
    const int e0 = tid * 2, e1 = tid * 2 + 1;
    const int pr0 = e0 >> 3, pc0 = (e0 & 7) * 8;
    const int pr1 = e1 >> 3, pc1 = (e1 & 7) * 8;

    uint4 nh0 = *(const uint4*)(bhip + (size_t)pr0 * N_NODES + pc0);
    uint4 nh1 = *(const uint4*)(bhip + (size_t)pr1 * N_NODES + pc1);
    uint4 nl0 = *(const uint4*)(blop + (size_t)pr0 * N_NODES + pc0);
    uint4 nl1 = *(const uint4*)(blop + (size_t)pr1 * N_NODES + pc1);

    float acc[8][4] = {};
    float den0 = 0.0f, den1 = 0.0f;

    for (int t = 0; t < 64; t++) {
        const int j0 = t * 64;
        __syncthreads();
        *(uint4*)&s_bh[pr0 * BPAD + pc0] = nh0;
        *(uint4*)&s_bh[pr1 * BPAD + pc1] = nh1;
        *(uint4*)&s_bl[pr0 * BPAD + pc0] = nl0;
        *(uint4*)&s_bl[pr1 * BPAD + pc1] = nl1;
        if (t < 63) {
            int jn = j0 + 64;
            nh0 = *(const uint4*)(bhip + (size_t)pr0 * N_NODES + jn + pc0);
            nh1 = *(const uint4*)(bhip + (size_t)pr1 * N_NODES + jn + pc1);
            nl0 = *(const uint4*)(blop + (size_t)pr0 * N_NODES + jn + pc0);
            nl1 = *(const uint4*)(blop + (size_t)pr1 * N_NODES + jn + pc1);
        }
        __syncthreads();

        // ---- A fragments: factorized p, bf16 hi/lo ----
        uint32_t ahi[4][4], alo[4][4];
        #pragma unroll
        for (int kf = 0; kf < 4; kf++) {
            const int jb = j0 + kf * 16 + t2;
            int2 m0a = *(const int2*)(adj0 + jb);
            int2 m0b = *(const int2*)(adj0 + jb + 8);
            int2 m1a = *(const int2*)(adj1 + jb);
            int2 m1b = *(const int2*)(adj1 + jb + 8);
            float2 sdA = *(const float2*)&s_sd[jb];
            float2 sdB = *(const float2*)&s_sd[jb + 8];
            float4 eA = *(const float4*)&s_e[jb * 2];        // {E1,E2}(jb), {E1,E2}(jb+1)
            float4 eB = *(const float4*)&s_e[(jb + 8) * 2];

            bool cA0 = (sdA.x >= th0), cA1 = (sdA.y >= th0);
            bool cB0 = (sdB.x >= th0), cB1 = (sdB.y >= th0);
            float p00 = (m0a.x > 0) ? (cA0 ? Pi1_0 * eA.x : Pi2_0 * eA.y) : 0.0f;
            float p01 = (m0a.y > 0) ? (cA1 ? Pi1_0 * eA.z : Pi2_0 * eA.w) : 0.0f;
            float p08 = (m0b.x > 0) ? (cB0 ? Pi1_0 * eB.x : Pi2_0 * eB.y) : 0.0f;
            float p09 = (m0b.y > 0) ? (cB1 ? Pi1_0 * eB.z : Pi2_0 * eB.w) : 0.0f;

            bool dA0 = (sdA.x >= th1), dA1 = (sdA.y >= th1);
            bool dB0 = (sdB.x >= th1), dB1 = (sdB.y >= th1);
            float p10 = (m1a.x > 0) ? (dA0 ? Pi1_1 * eA.x : Pi2_1 * eA.y) : 0.0f;
            float p11 = (m1a.y > 0) ? (dA1 ? Pi1_1 * eA.z : Pi2_1 * eA.w) : 0.0f;
            float p18 = (m1b.x > 0) ? (dB0 ? Pi1_1 * eB.x : Pi2_1 * eB.y) : 0.0f;
            float p19 = (m1b.y > 0) ? (dB1 ? Pi1_1 * eB.z : Pi2_1 * eB.w) : 0.0f;

            den0 += (p00 + p01) + (p08 + p09);
            den1 += (p10 + p11) + (p18 + p19);

            uint32_t h0 = pack_bf16x2(p00, p01);
            uint32_t h1 = pack_bf16x2(p10, p11);
            uint32_t h2 = pack_bf16x2(p08, p09);
            uint32_t h3 = pack_bf16x2(p18, p19);
            ahi[kf][0] = h0; ahi[kf][1] = h1; ahi[kf][2] = h2; ahi[kf][3] = h3;
            alo[kf][0] = pack_bf16x2(p00 - bf_lo_f(h0), p01 - bf_hi_f(h0));
            alo[kf][1] = pack_bf16x2(p10 - bf_lo_f(h1), p11 - bf_hi_f(h1));
            alo[kf][2] = pack_bf16x2(p08 - bf_lo_f(h2), p09 - bf_hi_f(h2));
            alo[kf][3] = pack_bf16x2(p18 - bf_lo_f(h3), p19 - bf_hi_f(h3));
        }

        // ---- 3-term MMA: acc += Ahi*Bhi + Alo*Bhi + Ahi*Blo ----
        #pragma unroll
        for (int nf = 0; nf < 8; nf++) {
            const int brow = (nf * 8 + g) * BPAD;
            #pragma unroll
            for (int kf = 0; kf < 4; kf++) {
                const int boff = brow + kf * 16 + t2;
                uint32_t bh0 = *(const uint32_t*)&s_bh[boff];
                uint32_t bh1 = *(const uint32_t*)&s_bh[boff + 8];
                uint32_t bl0 = *(const uint32_t*)&s_bl[boff];
                uint32_t bl1 = *(const uint32_t*)&s_bl[boff + 8];
                mma_bf16(acc[nf], ahi[kf], bh0, bh1);
                mma_bf16(acc[nf], alo[kf], bh0, bh1);
                mma_bf16(acc[nf], ahi[kf], bl0, bl1);
            }
        }
    }

    // ---- denominator: reduce over the 4 lanes of each quad ----
    den0 += __shfl_xor_sync(0xFFFFFFFFu, den0, 1);
    den0 += __shfl_xor_sync(0xFFFFFFFFu, den0, 2);
    den1 += __shfl_xor_sync(0xFFFFFFFFu, den1, 1);
    den1 += __shfl_xor_sync(0xFFFFFFFFu, den1, 2);
    const float inv0 = 1.0f / den0;
    const float inv1 = 1.0f / den1;

    // ---- epilogue ----
    float* orow0 = out + (size_t)r0 * (NHEADS * DHEAD) + h * DHEAD;
    float* orow1 = out + (size_t)r1 * (NHEADS * DHEAD) + h * DHEAD;
    #pragma unroll
    for (int nf = 0; nf < 8; nf++) {
        float2 b2 = *(const float2*)&bias[h * DHEAD + nf * 8 + t2];
        float2 o0, o1;
        o0.x = fmaxf(fmaf(acc[nf][0], inv0, b2.x), 0.0f);
        o0.y = fmaxf(fmaf(acc[nf][1], inv0, b2.y), 0.0f);
        o1.x = fmaxf(fmaf(acc[nf][2], inv1, b2.x), 0.0f);
        o1.y = fmaxf(fmaf(acc[nf][3], inv1, b2.y), 0.0f);
        *(float2*)(orow0 + nf * 8 + t2) = o0;
        *(float2*)(orow1 + nf * 8 + t2) = o1;
    }
}

// ---------------- launch ----------------
extern "C" void kernel_launch(void* const* d_in, const int* in_sizes, int n_in,
                              void* d_out, int out_size) {
    const float* x    = (const float*)d_in[0];
    const int*   adj  = (const int*)  d_in[1];
    const float* W    = (const float*)d_in[2];
    const float* a    = (const float*)d_in[3];
    const float* bias = (const float*)d_in[4];
    float* out = (float*)d_out;

    cudaFuncSetAttribute(k_attn, cudaFuncAttributeMaxDynamicSharedMemorySize, SMO_TOT);

    k_init <<<1, 32>>>();
    k_wx   <<<dim3(64, NHEADS), 256>>>(x, W);
    k_s    <<<(NHEADS * N_NODES) / 8, 256>>>(a);
    k_trans<<<dim3(64, NHEADS), 256>>>();
    k_attn <<<dim3(N_NODES / 128, NHEADS), 256, SMO_TOT>>>(adj, bias, out);
}

// round 6
// speedup vs baseline: 2.7972x; 1.1257x over previous
#include <cuda_runtime.h>
#include <cuda_bf16.h>
#include <stdint.h>

#define N_NODES 4096
#define F_IN    512
#define NHEADS  4
#define DHEAD   64
#define BPAD    72

// ---------------- device scratch ----------------
__device__ float    g_Wx[NHEADS * N_NODES * DHEAD];          // [h][n][d] fp32
__device__ float    g_ssrc[NHEADS * N_NODES];
__device__ float    g_sdst[NHEADS * N_NODES];
__device__ unsigned g_enc[2 * NHEADS];
__device__ __nv_bfloat16 g_WxT_hi[NHEADS * DHEAD * N_NODES]; // [h][d][n]
__device__ __nv_bfloat16 g_WxT_lo[NHEADS * DHEAD * N_NODES];
__device__ __nv_bfloat16 g_xhi[N_NODES * F_IN];              // x bf16 hi
__device__ __nv_bfloat16 g_xlo[N_NODES * F_IN];              // x residual
__device__ __nv_bfloat16 g_WT_hi[NHEADS * DHEAD * F_IN];     // [h][d][k]
__device__ __nv_bfloat16 g_WT_lo[NHEADS * DHEAD * F_IN];
__device__ float2   g_E[NHEADS * N_NODES];                   // {Ej1, Ej2}
__device__ float4   g_P[NHEADS * N_NODES];                   // {Pi1, Pi2, Ti, 0}

// ---------------- helpers ----------------
__device__ __forceinline__ uint32_t pack_bf16x2(float lo, float hi) {
    uint32_t r;
    asm("cvt.rn.bf16x2.f32 %0, %1, %2;" : "=r"(r) : "f"(hi), "f"(lo));
    return r;
}
__device__ __forceinline__ float bf_lo_f(uint32_t w) { return __uint_as_float(w << 16); }
__device__ __forceinline__ float bf_hi_f(uint32_t w) { return __uint_as_float(w & 0xFFFF0000u); }

__device__ __forceinline__ unsigned fenc(float f) {
    unsigned u = __float_as_uint(f);
    return (u & 0x80000000u) ? ~u : (u | 0x80000000u);
}
__device__ __forceinline__ float fdec(unsigned u) {
    unsigned b = (u & 0x80000000u) ? (u & 0x7FFFFFFFu) : ~u;
    return __uint_as_float(b);
}

// FMA-pipe exp (no MUFU), rel err ~2e-6
__device__ __forceinline__ float fexp(float v) {
    float x = v * 1.4426950408889634f;
    x = fmaxf(x, -126.0f);
    float kf = x + 12582912.0f;
    int   ki = __float_as_int(kf) - 0x4B400000;
    float r  = x - (kf - 12582912.0f);
    float p  = 1.3333558146e-3f;
    p = fmaf(p, r, 9.6181291076e-3f);
    p = fmaf(p, r, 5.5504108664e-2f);
    p = fmaf(p, r, 2.4022650696e-1f);
    p = fmaf(p, r, 6.9314718056e-1f);
    p = fmaf(p, r, 1.0f);
    return __int_as_float(__float_as_int(p) + (ki << 23));
}

__device__ __forceinline__ void mma_bf16(float* c, const uint32_t* a, uint32_t b0, uint32_t b1) {
    asm volatile(
        "mma.sync.aligned.m16n8k16.row.col.f32.bf16.bf16.f32 "
        "{%0,%1,%2,%3}, {%4,%5,%6,%7}, {%8,%9}, {%0,%1,%2,%3};"
        : "+f"(c[0]), "+f"(c[1]), "+f"(c[2]), "+f"(c[3])
        : "r"(a[0]), "r"(a[1]), "r"(a[2]), "r"(a[3]), "r"(b0), "r"(b1));
}

// ---------------- kernel 0 ----------------
__global__ void k_init() {
    int t = threadIdx.x;
    if (t < 2 * NHEADS) g_enc[t] = 0u;
}

// ---------------- split x into bf16 hi/lo ----------------
__global__ __launch_bounds__(256) void k_xsplit(const float* __restrict__ x) {
    int i = (blockIdx.x * 256 + threadIdx.x) * 4;
    float4 v = *(const float4*)(x + i);
    uint32_t h0 = pack_bf16x2(v.x, v.y);
    uint32_t h1 = pack_bf16x2(v.z, v.w);
    uint32_t l0 = pack_bf16x2(v.x - bf_lo_f(h0), v.y - bf_hi_f(h0));
    uint32_t l1 = pack_bf16x2(v.z - bf_lo_f(h1), v.w - bf_hi_f(h1));
    *(uint2*)(g_xhi + i) = make_uint2(h0, h1);
    *(uint2*)(g_xlo + i) = make_uint2(l0, l1);
}

// ---------------- split+transpose W -> [h][d][k] bf16 hi/lo ----------------
__global__ __launch_bounds__(256) void k_wsplit(const float* __restrict__ W) {
    __shared__ __align__(16) float s[64][65];
    int h = blockIdx.y, k0 = blockIdx.x * 64;
    int tid = threadIdx.x;
    const float* Wh = W + (size_t)h * F_IN * DHEAD;
    #pragma unroll
    for (int k = 0; k < 4; k++) {
        int e = tid + k * 256; int r = e >> 4, c4 = (e & 15) * 4;
        float4 v = *(const float4*)&Wh[(size_t)(k0 + r) * DHEAD + c4];
        s[r][c4 + 0] = v.x; s[r][c4 + 1] = v.y; s[r][c4 + 2] = v.z; s[r][c4 + 3] = v.w;
    }
    __syncthreads();
    int d = tid >> 2, kb = (tid & 3) * 16;
    uint32_t hw[8], lw[8];
    #pragma unroll
    for (int e = 0; e < 8; e++) {
        float f0 = s[kb + e * 2][d], f1 = s[kb + e * 2 + 1][d];
        uint32_t hp = pack_bf16x2(f0, f1);
        hw[e] = hp;
        lw[e] = pack_bf16x2(f0 - bf_lo_f(hp), f1 - bf_hi_f(hp));
    }
    size_t base = ((size_t)h * DHEAD + d) * F_IN + k0 + kb;
    *(uint4*)(g_WT_hi + base)     = make_uint4(hw[0], hw[1], hw[2], hw[3]);
    *(uint4*)(g_WT_hi + base + 8) = make_uint4(hw[4], hw[5], hw[6], hw[7]);
    *(uint4*)(g_WT_lo + base)     = make_uint4(lw[0], lw[1], lw[2], lw[3]);
    *(uint4*)(g_WT_lo + base + 8) = make_uint4(lw[4], lw[5], lw[6], lw[7]);
}

// ---------------- kernel 1: Wx = x @ W per head, via HMMA 3-term ----------------
__global__ __launch_bounds__(256) void k_wx_mma() {
    __shared__ __align__(16) __nv_bfloat16 s_wh[64 * BPAD];
    __shared__ __align__(16) __nv_bfloat16 s_wl[64 * BPAD];
    const int tid = threadIdx.x, wid = tid >> 5, lane = tid & 31;
    const int g = lane >> 2, t2 = (lane & 3) * 2;
    const int h = blockIdx.y, i0 = blockIdx.x * 128;
    const int r0 = i0 + wid * 16 + g, r1 = r0 + 8;

    const __nv_bfloat16* wth = g_WT_hi + (size_t)h * DHEAD * F_IN;
    const __nv_bfloat16* wtl = g_WT_lo + (size_t)h * DHEAD * F_IN;

    const int e0 = tid * 2, e1 = tid * 2 + 1;
    const int pr0 = e0 >> 3, pc0 = (e0 & 7) * 8;
    const int pr1 = e1 >> 3, pc1 = (e1 & 7) * 8;

    uint4 nh0 = *(const uint4*)(wth + (size_t)pr0 * F_IN + pc0);
    uint4 nh1 = *(const uint4*)(wth + (size_t)pr1 * F_IN + pc1);
    uint4 nl0 = *(const uint4*)(wtl + (size_t)pr0 * F_IN + pc0);
    uint4 nl1 = *(const uint4*)(wtl + (size_t)pr1 * F_IN + pc1);

    float acc[8][4] = {};
    for (int c = 0; c < 8; c++) {
        const int kc = c * 64;
        __syncthreads();
        *(uint4*)&s_wh[pr0 * BPAD + pc0] = nh0;
        *(uint4*)&s_wh[pr1 * BPAD + pc1] = nh1;
        *(uint4*)&s_wl[pr0 * BPAD + pc0] = nl0;
        *(uint4*)&s_wl[pr1 * BPAD + pc1] = nl1;
        if (c < 7) {
            int kn = kc + 64;
            nh0 = *(const uint4*)(wth + (size_t)pr0 * F_IN + kn + pc0);
            nh1 = *(const uint4*)(wth + (size_t)pr1 * F_IN + kn + pc1);
            nl0 = *(const uint4*)(wtl + (size_t)pr0 * F_IN + kn + pc0);
            nl1 = *(const uint4*)(wtl + (size_t)pr1 * F_IN + kn + pc1);
        }
        __syncthreads();

        uint32_t ahi[4][4], alo[4][4];
        #pragma unroll
        for (int kf = 0; kf < 4; kf++) {
            int k = kc + kf * 16 + t2;
            ahi[kf][0] = *(const uint32_t*)&g_xhi[(size_t)r0 * F_IN + k];
            ahi[kf][1] = *(const uint32_t*)&g_xhi[(size_t)r1 * F_IN + k];
            ahi[kf][2] = *(const uint32_t*)&g_xhi[(size_t)r0 * F_IN + k + 8];
            ahi[kf][3] = *(const uint32_t*)&g_xhi[(size_t)r1 * F_IN + k + 8];
            alo[kf][0] = *(const uint32_t*)&g_xlo[(size_t)r0 * F_IN + k];
            alo[kf][1] = *(const uint32_t*)&g_xlo[(size_t)r1 * F_IN + k];
            alo[kf][2] = *(const uint32_t*)&g_xlo[(size_t)r0 * F_IN + k + 8];
            alo[kf][3] = *(const uint32_t*)&g_xlo[(size_t)r1 * F_IN + k + 8];
        }
        #pragma unroll
        for (int nf = 0; nf < 8; nf++) {
            const int brow = (nf * 8 + g) * BPAD;
            #pragma unroll
            for (int kf = 0; kf < 4; kf++) {
                const int boff = brow + kf * 16 + t2;
                uint32_t bh0 = *(const uint32_t*)&s_wh[boff];
                uint32_t bh1 = *(const uint32_t*)&s_wh[boff + 8];
                uint32_t bl0 = *(const uint32_t*)&s_wl[boff];
                uint32_t bl1 = *(const uint32_t*)&s_wl[boff + 8];
                mma_bf16(acc[nf], ahi[kf], bh0, bh1);
                mma_bf16(acc[nf], alo[kf], bh0, bh1);
                mma_bf16(acc[nf], ahi[kf], bl0, bl1);
            }
        }
    }
    float* o0 = g_Wx + ((size_t)h * N_NODES + r0) * DHEAD;
    float* o1 = g_Wx + ((size_t)h * N_NODES + r1) * DHEAD;
    #pragma unroll
    for (int nf = 0; nf < 8; nf++) {
        *(float2*)(o0 + nf * 8 + t2) = make_float2(acc[nf][0], acc[nf][1]);
        *(float2*)(o1 + nf * 8 + t2) = make_float2(acc[nf][2], acc[nf][3]);
    }
}

// ---------------- kernel 2: s_src/s_dst + per-head maxima ----------------
__global__ __launch_bounds__(256) void k_s(const float* __restrict__ a) {
    int warp = threadIdx.x >> 5, lane = threadIdx.x & 31;
    int idx = blockIdx.x * 8 + warp;
    int h = idx >> 12;
    int n = idx & (N_NODES - 1);
    const float* wxr = g_Wx + ((size_t)h * N_NODES + n) * DHEAD;
    float w0 = wxr[lane], w1 = wxr[lane + 32];
    const float* ah = a + h * 2 * DHEAD;
    float ps = w0 * ah[lane]      + w1 * ah[lane + 32];
    float pd = w0 * ah[64 + lane] + w1 * ah[96 + lane];
    #pragma unroll
    for (int o = 16; o; o >>= 1) {
        ps += __shfl_xor_sync(0xFFFFFFFFu, ps, o);
        pd += __shfl_xor_sync(0xFFFFFFFFu, pd, o);
    }
    if (lane == 0) {
        g_ssrc[h * N_NODES + n] = ps;
        g_sdst[h * N_NODES + n] = pd;
        atomicMax(&g_enc[h],          fenc(ps));
        atomicMax(&g_enc[NHEADS + h], fenc(pd));
    }
}

// ---------------- kernel 2b: transpose Wx -> [h][d][n] bf16 hi/lo ----------------
__global__ __launch_bounds__(256) void k_trans() {
    __shared__ __align__(16) float s[64][65];
    int h = blockIdx.y, n0 = blockIdx.x * 64;
    int tid = threadIdx.x;
    #pragma unroll
    for (int k = 0; k < 4; k++) {
        int e = tid + k * 256; int r = e >> 4, c4 = (e & 15) * 4;
        float4 v = *(const float4*)&g_Wx[((size_t)h * N_NODES + n0 + r) * DHEAD + c4];
        s[r][c4 + 0] = v.x; s[r][c4 + 1] = v.y; s[r][c4 + 2] = v.z; s[r][c4 + 3] = v.w;
    }
    __syncthreads();
    int d = tid >> 2, nb = (tid & 3) * 16;
    uint32_t hw[8], lw[8];
    #pragma unroll
    for (int e = 0; e < 8; e++) {
        float f0 = s[nb + e * 2][d], f1 = s[nb + e * 2 + 1][d];
        uint32_t hp = pack_bf16x2(f0, f1);
        hw[e] = hp;
        lw[e] = pack_bf16x2(f0 - bf_lo_f(hp), f1 - bf_hi_f(hp));
    }
    size_t base = ((size_t)h * DHEAD + d) * N_NODES + n0 + nb;
    *(uint4*)(g_WxT_hi + base)     = make_uint4(hw[0], hw[1], hw[2], hw[3]);
    *(uint4*)(g_WxT_hi + base + 8) = make_uint4(hw[4], hw[5], hw[6], hw[7]);
    *(uint4*)(g_WxT_lo + base)     = make_uint4(lw[0], lw[1], lw[2], lw[3]);
    *(uint4*)(g_WxT_lo + base + 8) = make_uint4(lw[4], lw[5], lw[6], lw[7]);
}

// ---------------- kernel 2c: E/P tables per head ----------------
__global__ __launch_bounds__(1024) void k_prep() {
    int h = blockIdx.x, tid = threadIdx.x;
    const float maxsrc = fdec(g_enc[h]);
    const float maxdst = fdec(g_enc[NHEADS + h]);
    const float S  = maxsrc + maxdst;
    const float Mh = fmaxf(S, 0.2f * S);
    const float r_ = Mh - 0.2f * S;
    const float c_ = 0.2f * maxsrc + 0.5f * r_;
    const float d_ = 0.2f * maxdst + 0.5f * r_;
    #pragma unroll
    for (int k = 0; k < 4; k++) {
        int j = tid + k * 1024;
        float sj = g_sdst[h * N_NODES + j];
        g_E[h * N_NODES + j] = make_float2(fexp(sj - maxdst), fexp(fmaf(0.2f, sj, -d_)));
        float si = g_ssrc[h * N_NODES + j];
        g_P[h * N_NODES + j] = make_float4(fexp(si - maxsrc), fexp(fmaf(0.2f, si, -c_)),
                                           fexp(-si - maxdst), 0.0f);
    }
}

// ---------------- kernel 3: fused masked softmax + HMMA AV, split-K ----------------
// grid (64, 4): i-tile 64 rows. 8 warps: warps 0-3 handle j[0,32) of each tile,
// warps 4-7 handle j[32,64) for the SAME rows; partials merged via SMEM at end.
__global__ __launch_bounds__(256, 2) void k_attn(const int* __restrict__ adj,
                                                 const float* __restrict__ bias,
                                                 float* __restrict__ out) {
    __shared__ __align__(16) char sraw[18432 + 256];
    __nv_bfloat16* s_bh = (__nv_bfloat16*)sraw;
    __nv_bfloat16* s_bl = (__nv_bfloat16*)(sraw + 9216);
    float* s_acc = (float*)sraw;              // reused after main loop (16KB <= 18KB)
    float* s_dn  = (float*)(sraw + 18432);    // 64 floats

    const int tid = threadIdx.x, wid = tid >> 5, lane = tid & 31;
    const int g = lane >> 2, t2 = (lane & 3) * 2;
    const int wg = wid & 3, half = wid >> 2;
    const int h = blockIdx.y, i0 = blockIdx.x * 64;

    const int r0 = i0 + wg * 16 + g, r1 = r0 + 8;
    const float4 P0 = g_P[h * N_NODES + r0];
    const float4 P1 = g_P[h * N_NODES + r1];
    const int* adj0 = adj + (size_t)r0 * N_NODES + half * 32;
    const int* adj1 = adj + (size_t)r1 * N_NODES + half * 32;
    const float2* Eh = g_E + h * N_NODES;

    const __nv_bfloat16* bhip = g_WxT_hi + (size_t)h * DHEAD * N_NODES;
    const __nv_bfloat16* blop = g_WxT_lo + (size_t)h * DHEAD * N_NODES;

    const int e0 = tid * 2, e1 = tid * 2 + 1;
    const int pr0 = e0 >> 3, pc0 = (e0 & 7) * 8;
    const int pr1 = e1 >> 3, pc1 = (e1 & 7) * 8;

    uint4 nh0 = *(const uint4*)(bhip + (size_t)pr0 * N_NODES + pc0);
    uint4 nh1 = *(const uint4*)(bhip + (size_t)pr1 * N_NODES + pc1);
    uint4 nl0 = *(const uint4*)(blop + (size_t)pr0 * N_NODES + pc0);
    uint4 nl1 = *(const uint4*)(blop + (size_t)pr1 * N_NODES + pc1);

    float acc[8][4] = {};
    float den0 = 0.0f, den1 = 0.0f;

    for (int t = 0; t < 64; t++) {
        const int j0 = t * 64;
        __syncthreads();
        *(uint4*)&s_bh[pr0 * BPAD + pc0] = nh0;
        *(uint4*)&s_bh[pr1 * BPAD + pc1] = nh1;
        *(uint4*)&s_bl[pr0 * BPAD + pc0] = nl0;
        *(uint4*)&s_bl[pr1 * BPAD + pc1] = nl1;
        if (t < 63) {
            int jn = j0 + 64;
            nh0 = *(const uint4*)(bhip + (size_t)pr0 * N_NODES + jn + pc0);
            nh1 = *(const uint4*)(bhip + (size_t)pr1 * N_NODES + jn + pc1);
            nl0 = *(const uint4*)(blop + (size_t)pr0 * N_NODES + jn + pc0);
            nl1 = *(const uint4*)(blop + (size_t)pr1 * N_NODES + jn + pc1);
        }
        __syncthreads();

        // ---- A fragments for this warp's j-half: 2 kf x (2 rows x 8 j) ----
        uint32_t ahi[2][4], alo[2][4];
        #pragma unroll
        for (int kf = 0; kf < 2; kf++) {
            const int jb = j0 + half * 32 + kf * 16 + t2;     // global j
            const int jl = kf * 16 + t2;                       // within half (adj ptr pre-offset)
            int2 m0a = *(const int2*)(adj0 + jl);
            int2 m0b = *(const int2*)(adj0 + jl + 8);
            int2 m1a = *(const int2*)(adj1 + jl);
            int2 m1b = *(const int2*)(adj1 + jl + 8);
            float4 eA = *(const float4*)&Eh[jb];               // {E1,E2}(jb), (jb+1)
            float4 eB = *(const float4*)&Eh[jb + 8];

            bool cA0 = (eA.x >= P0.z), cA1 = (eA.z >= P0.z);
            bool cB0 = (eB.x >= P0.z), cB1 = (eB.z >= P0.z);
            float p00 = (m0a.x > 0) ? (cA0 ? P0.x * eA.x : P0.y * eA.y) : 0.0f;
            float p01 = (m0a.y > 0) ? (cA1 ? P0.x * eA.z : P0.y * eA.w) : 0.0f;
            float p08 = (m0b.x > 0) ? (cB0 ? P0.x * eB.x : P0.y * eB.y) : 0.0f;
            float p09 = (m0b.y > 0) ? (cB1 ? P0.x * eB.z : P0.y * eB.w) : 0.0f;

            bool dA0 = (eA.x >= P1.z), dA1 = (eA.z >= P1.z);
            bool dB0 = (eB.x >= P1.z), dB1 = (eB.z >= P1.z);
            float p10 = (m1a.x > 0) ? (dA0 ? P1.x * eA.x : P1.y * eA.y) : 0.0f;
            float p11 = (m1a.y > 0) ? (dA1 ? P1.x * eA.z : P1.y * eA.w) : 0.0f;
            float p18 = (m1b.x > 0) ? (dB0 ? P1.x * eB.x : P1.y * eB.y) : 0.0f;
            float p19 = (m1b.y > 0) ? (dB1 ? P1.x * eB.z : P1.y * eB.w) : 0.0f;

            den0 += (p00 + p01) + (p08 + p09);
            den1 += (p10 + p11) + (p18 + p19);

            uint32_t h0 = pack_bf16x2(p00, p01);
            uint32_t h1 = pack_bf16x2(p10, p11);
            uint32_t h2 = pack_bf16x2(p08, p09);
            uint32_t h3 = pack_bf16x2(p18, p19);
            ahi[kf][0] = h0; ahi[kf][1] = h1; ahi[kf][2] = h2; ahi[kf][3] = h3;
            alo[kf][0] = pack_bf16x2(p00 - bf_lo_f(h0), p01 - bf_hi_f(h0));
            alo[kf][1] = pack_bf16x2(p10 - bf_lo_f(h1), p11 - bf_hi_f(h1));
            alo[kf][2] = pack_bf16x2(p08 - bf_lo_f(h2), p09 - bf_hi_f(h2));
            alo[kf][3] = pack_bf16x2(p18 - bf_lo_f(h3), p19 - bf_hi_f(h3));
        }

        // ---- 3-term MMA on this warp's k-half ----
        #pragma unroll
        for (int nf = 0; nf < 8; nf++) {
            const int brow = (nf * 8 + g) * BPAD + half * 32;
            #pragma unroll
            for (int kf = 0; kf < 2; kf++) {
                const int boff = brow + kf * 16 + t2;
                uint32_t bh0 = *(const uint32_t*)&s_bh[boff];
                uint32_t bh1 = *(const uint32_t*)&s_bh[boff + 8];
                uint32_t bl0 = *(const uint32_t*)&s_bl[boff];
                uint32_t bl1 = *(const uint32_t*)&s_bl[boff + 8];
                mma_bf16(acc[nf], ahi[kf], bh0, bh1);
                mma_bf16(acc[nf], alo[kf], bh0, bh1);
                mma_bf16(acc[nf], ahi[kf], bl0, bl1);
            }
        }

        // move adj pointers forward one tile
        adj0 += 64; adj1 += 64;
    }

    // quad-reduce denominators (full row-sum over this warp's 32-j half)
    den0 += __shfl_xor_sync(0xFFFFFFFFu, den0, 1);
    den0 += __shfl_xor_sync(0xFFFFFFFFu, den0, 2);
    den1 += __shfl_xor_sync(0xFFFFFFFFu, den1, 1);
    den1 += __shfl_xor_sync(0xFFFFFFFFu, den1, 2);

    __syncthreads();                      // B smem no longer needed
    if (half == 1) {
        if ((lane & 3) == 0) {
            s_dn[wg * 16 + g]     = den0;
            s_dn[wg * 16 + g + 8] = den1;
        }
        #pragma unroll
        for (int nf = 0; nf < 8; nf++) {
            *(float2*)&s_acc[(wg * 16 + g) * 64 + nf * 8 + t2]     = make_float2(acc[nf][0], acc[nf][1]);
            *(float2*)&s_acc[(wg * 16 + g + 8) * 64 + nf * 8 + t2] = make_float2(acc[nf][2], acc[nf][3]);
        }
    }
    __syncthreads();
    if (half == 0) {
        const float inv0 = 1.0f / (den0 + s_dn[wg * 16 + g]);
        const float inv1 = 1.0f / (den1 + s_dn[wg * 16 + g + 8]);
        float* orow0 = out + (size_t)r0 * (NHEADS * DHEAD) + h * DHEAD;
        float* orow1 = out + (size_t)r1 * (NHEADS * DHEAD) + h * DHEAD;
        #pragma unroll
        for (int nf = 0; nf < 8; nf++) {
            float2 x0 = *(const float2*)&s_acc[(wg * 16 + g) * 64 + nf * 8 + t2];
            float2 x1 = *(const float2*)&s_acc[(wg * 16 + g + 8) * 64 + nf * 8 + t2];
            float2 b2 = *(const float2*)&bias[h * DHEAD + nf * 8 + t2];
            float2 o0, o1;
            o0.x = fmaxf(fmaf(acc[nf][0] + x0.x, inv0, b2.x), 0.0f);
            o0.y = fmaxf(fmaf(acc[nf][1] + x0.y, inv0, b2.y), 0.0f);
            o1.x = fmaxf(fmaf(acc[nf][2] + x1.x, inv1, b2.x), 0.0f);
            o1.y = fmaxf(fmaf(acc[nf][3] + x1.y, inv1, b2.y), 0.0f);
            *(float2*)(orow0 + nf * 8 + t2) = o0;
            *(float2*)(orow1 + nf * 8 + t2) = o1;
        }
    }
}

// ---------------- launch ----------------
extern "C" void kernel_launch(void* const* d_in, const int* in_sizes, int n_in,
                              void* d_out, int out_size) {
    const float* x    = (const float*)d_in[0];
    const int*   adj  = (const int*)  d_in[1];
    const float* W    = (const float*)d_in[2];
    const float* a    = (const float*)d_in[3];
    const float* bias = (const float*)d_in[4];
    float* out = (float*)d_out;

    k_init  <<<1, 32>>>();
    k_xsplit<<<(N_NODES * F_IN) / 1024, 256>>>(x);
    k_wsplit<<<dim3(F_IN / 64, NHEADS), 256>>>(W);
    k_wx_mma<<<dim3(N_NODES / 128, NHEADS), 256>>>();
    k_s     <<<(NHEADS * N_NODES) / 8, 256>>>(a);
    k_trans <<<dim3(64, NHEADS), 256>>>();
    k_prep  <<<NHEADS, 1024>>>();
    k_attn  <<<dim3(N_NODES / 64, NHEADS), 256>>>(adj, bias, out);
}

// round 7
// speedup vs baseline: 2.9908x; 1.0692x over previous
#include <cuda_runtime.h>
#include <cuda_bf16.h>
#include <stdint.h>

#define N_NODES 4096
#define F_IN    512
#define NHEADS  4
#define DHEAD   64
#define BPAD    72

// ---------------- device scratch ----------------
__device__ float    g_Wx[NHEADS * N_NODES * DHEAD];
__device__ float    g_ssrc[NHEADS * N_NODES];
__device__ float    g_sdst[NHEADS * N_NODES];
__device__ unsigned g_enc[2 * NHEADS];
__device__ __nv_bfloat16 g_WxT_hi[NHEADS * DHEAD * N_NODES];
__device__ __nv_bfloat16 g_WxT_lo[NHEADS * DHEAD * N_NODES];
__device__ __nv_bfloat16 g_xhi[N_NODES * F_IN];
__device__ __nv_bfloat16 g_xlo[N_NODES * F_IN];
__device__ __nv_bfloat16 g_WT_hi[NHEADS * DHEAD * F_IN];
__device__ __nv_bfloat16 g_WT_lo[NHEADS * DHEAD * F_IN];
__device__ float2   g_E[NHEADS * N_NODES];       // {Ej1, Ej2}
__device__ float4   g_P[NHEADS * N_NODES];       // {Pi1, Pi2, Ti, 0}
__device__ uint32_t g_bits[N_NODES * 128];       // adj bitmask, 2MB

// ---------------- helpers ----------------
__device__ __forceinline__ uint32_t pack_bf16x2(float lo, float hi) {
    uint32_t r;
    asm("cvt.rn.bf16x2.f32 %0, %1, %2;" : "=r"(r) : "f"(hi), "f"(lo));
    return r;
}
__device__ __forceinline__ float bf_lo_f(uint32_t w) { return __uint_as_float(w << 16); }
__device__ __forceinline__ float bf_hi_f(uint32_t w) { return __uint_as_float(w & 0xFFFF0000u); }

__device__ __forceinline__ unsigned fenc(float f) {
    unsigned u = __float_as_uint(f);
    return (u & 0x80000000u) ? ~u : (u | 0x80000000u);
}
__device__ __forceinline__ float fdec(unsigned u) {
    unsigned b = (u & 0x80000000u) ? (u & 0x7FFFFFFFu) : ~u;
    return __uint_as_float(b);
}

__device__ __forceinline__ float fexp(float v) {
    float x = v * 1.4426950408889634f;
    x = fmaxf(x, -126.0f);
    float kf = x + 12582912.0f;
    int   ki = __float_as_int(kf) - 0x4B400000;
    float r  = x - (kf - 12582912.0f);
    float p  = 1.3333558146e-3f;
    p = fmaf(p, r, 9.6181291076e-3f);
    p = fmaf(p, r, 5.5504108664e-2f);
    p = fmaf(p, r, 2.4022650696e-1f);
    p = fmaf(p, r, 6.9314718056e-1f);
    p = fmaf(p, r, 1.0f);
    return __int_as_float(__float_as_int(p) + (ki << 23));
}

__device__ __forceinline__ void mma_bf16(float* c, const uint32_t* a, uint32_t b0, uint32_t b1) {
    asm volatile(
        "mma.sync.aligned.m16n8k16.row.col.f32.bf16.bf16.f32 "
        "{%0,%1,%2,%3}, {%4,%5,%6,%7}, {%8,%9}, {%0,%1,%2,%3};"
        : "+f"(c[0]), "+f"(c[1]), "+f"(c[2]), "+f"(c[3])
        : "r"(a[0]), "r"(a[1]), "r"(a[2]), "r"(a[3]), "r"(b0), "r"(b1));
}

// ---------------- kernel 0 ----------------
__global__ void k_init() {
    int t = threadIdx.x;
    if (t < 2 * NHEADS) g_enc[t] = 0u;
}

// ---------------- adj -> bitmask ----------------
__global__ __launch_bounds__(256) void k_bits(const int* __restrict__ adj) {
    int row = blockIdx.x;
    int wid = threadIdx.x >> 5, lane = threadIdx.x & 31;
    const int* arow = adj + (size_t)row * N_NODES;
    #pragma unroll
    for (int w = 0; w < 16; w++) {
        int word = wid * 16 + w;
        uint32_t m = __ballot_sync(0xFFFFFFFFu, arow[word * 32 + lane] > 0);
        if (lane == 0) g_bits[row * 128 + word] = m;
    }
}

// ---------------- split x into bf16 hi/lo ----------------
__global__ __launch_bounds__(256) void k_xsplit(const float* __restrict__ x) {
    int i = (blockIdx.x * 256 + threadIdx.x) * 4;
    float4 v = *(const float4*)(x + i);
    uint32_t h0 = pack_bf16x2(v.x, v.y);
    uint32_t h1 = pack_bf16x2(v.z, v.w);
    uint32_t l0 = pack_bf16x2(v.x - bf_lo_f(h0), v.y - bf_hi_f(h0));
    uint32_t l1 = pack_bf16x2(v.z - bf_lo_f(h1), v.w - bf_hi_f(h1));
    *(uint2*)(g_xhi + i) = make_uint2(h0, h1);
    *(uint2*)(g_xlo + i) = make_uint2(l0, l1);
}

// ---------------- split+transpose W -> [h][d][k] bf16 hi/lo ----------------
__global__ __launch_bounds__(256) void k_wsplit(const float* __restrict__ W) {
    __shared__ __align__(16) float s[64][65];
    int h = blockIdx.y, k0 = blockIdx.x * 64;
    int tid = threadIdx.x;
    const float* Wh = W + (size_t)h * F_IN * DHEAD;
    #pragma unroll
    for (int k = 0; k < 4; k++) {
        int e = tid + k * 256; int r = e >> 4, c4 = (e & 15) * 4;
        float4 v = *(const float4*)&Wh[(size_t)(k0 + r) * DHEAD + c4];
        s[r][c4 + 0] = v.x; s[r][c4 + 1] = v.y; s[r][c4 + 2] = v.z; s[r][c4 + 3] = v.w;
    }
    __syncthreads();
    int d = tid >> 2, kb = (tid & 3) * 16;
    uint32_t hw[8], lw[8];
    #pragma unroll
    for (int e = 0; e < 8; e++) {
        float f0 = s[kb + e * 2][d], f1 = s[kb + e * 2 + 1][d];
        uint32_t hp = pack_bf16x2(f0, f1);
        hw[e] = hp;
        lw[e] = pack_bf16x2(f0 - bf_lo_f(hp), f1 - bf_hi_f(hp));
    }
    size_t base = ((size_t)h * DHEAD + d) * F_IN + k0 + kb;
    *(uint4*)(g_WT_hi + base)     = make_uint4(hw[0], hw[1], hw[2], hw[3]);
    *(uint4*)(g_WT_hi + base + 8) = make_uint4(hw[4], hw[5], hw[6], hw[7]);
    *(uint4*)(g_WT_lo + base)     = make_uint4(lw[0], lw[1], lw[2], lw[3]);
    *(uint4*)(g_WT_lo + base + 8) = make_uint4(lw[4], lw[5], lw[6], lw[7]);
}

// ---------------- kernel 1: Wx = x @ W per head, split-K HMMA ----------------
// grid (64, 4): 64-row i-tile. warps 0-3: k[0,256); warps 4-7: k[256,512).
__global__ __launch_bounds__(256, 2) void k_wx_mma() {
    __shared__ __align__(16) char swraw[36864 + 256];
    __nv_bfloat16* s_wh = (__nv_bfloat16*)swraw;             // 128 rows x BPAD
    __nv_bfloat16* s_wl = (__nv_bfloat16*)(swraw + 18432);
    float* s_acc = (float*)swraw;
    float* s_dn_unused = (float*)(swraw + 36864); (void)s_dn_unused;

    const int tid = threadIdx.x, wid = tid >> 5, lane = tid & 31;
    const int g = lane >> 2, t2 = (lane & 3) * 2;
    const int wg = wid & 3, half = wid >> 2;
    const int h = blockIdx.y, i0 = blockIdx.x * 64;
    const int r0 = i0 + wg * 16 + g, r1 = r0 + 8;

    const __nv_bfloat16* wth = g_WT_hi + (size_t)h * DHEAD * F_IN;
    const __nv_bfloat16* wtl = g_WT_lo + (size_t)h * DHEAD * F_IN;

    float acc[8][4] = {};
    for (int chunk = 0; chunk < 4; chunk++) {
        const int kc = chunk * 64;
        __syncthreads();
        #pragma unroll
        for (int it = 0; it < 4; it++) {
            int e = tid + it * 256; int r = e >> 3, c = (e & 7) * 8;
            int d = r & 63, ks = (r >> 6) * 256 + kc + c;
            *(uint4*)&s_wh[r * BPAD + c] = *(const uint4*)&wth[(size_t)d * F_IN + ks];
            *(uint4*)&s_wl[r * BPAD + c] = *(const uint4*)&wtl[(size_t)d * F_IN + ks];
        }
        __syncthreads();

        uint32_t ahi[4][4], alo[4][4];
        #pragma unroll
        for (int kf = 0; kf < 4; kf++) {
            int k = half * 256 + kc + kf * 16 + t2;
            ahi[kf][0] = *(const uint32_t*)&g_xhi[(size_t)r0 * F_IN + k];
            ahi[kf][1] = *(const uint32_t*)&g_xhi[(size_t)r1 * F_IN + k];
            ahi[kf][2] = *(const uint32_t*)&g_xhi[(size_t)r0 * F_IN + k + 8];
            ahi[kf][3] = *(const uint32_t*)&g_xhi[(size_t)r1 * F_IN + k + 8];
            alo[kf][0] = *(const uint32_t*)&g_xlo[(size_t)r0 * F_IN + k];
            alo[kf][1] = *(const uint32_t*)&g_xlo[(size_t)r1 * F_IN + k];
            alo[kf][2] = *(const uint32_t*)&g_xlo[(size_t)r0 * F_IN + k + 8];
            alo[kf][3] = *(const uint32_t*)&g_xlo[(size_t)r1 * F_IN + k + 8];
        }
        #pragma unroll
        for (int nf = 0; nf < 8; nf++) {
            const int brow = (half * 64 + nf * 8 + g) * BPAD;
            #pragma unroll
            for (int kf = 0; kf < 4; kf++) {
                const int boff = brow + kf * 16 + t2;
                uint32_t bh0 = *(const uint32_t*)&s_wh[boff];
                uint32_t bh1 = *(const uint32_t*)&s_wh[boff + 8];
                uint32_t bl0 = *(const uint32_t*)&s_wl[boff];
                uint32_t bl1 = *(const uint32_t*)&s_wl[boff + 8];
                mma_bf16(acc[nf], ahi[kf], bh0, bh1);
                mma_bf16(acc[nf], alo[kf], bh0, bh1);
                mma_bf16(acc[nf], ahi[kf], bl0, bl1);
            }
        }
    }

    __syncthreads();
    if (half == 1) {
        #pragma unroll
        for (int nf = 0; nf < 8; nf++) {
            *(float2*)&s_acc[(wg * 16 + g) * 64 + nf * 8 + t2]       = make_float2(acc[nf][0], acc[nf][1]);
            *(float2*)&s_acc[(wg * 16 + g + 8) * 64 + nf * 8 + t2]   = make_float2(acc[nf][2], acc[nf][3]);
        }
    }
    __syncthreads();
    if (half == 0) {
        float* o0 = g_Wx + ((size_t)h * N_NODES + r0) * DHEAD;
        float* o1 = g_Wx + ((size_t)h * N_NODES + r1) * DHEAD;
        #pragma unroll
        for (int nf = 0; nf < 8; nf++) {
            float2 x0 = *(const float2*)&s_acc[(wg * 16 + g) * 64 + nf * 8 + t2];
            float2 x1 = *(const float2*)&s_acc[(wg * 16 + g + 8) * 64 + nf * 8 + t2];
            *(float2*)(o0 + nf * 8 + t2) = make_float2(acc[nf][0] + x0.x, acc[nf][1] + x0.y);
            *(float2*)(o1 + nf * 8 + t2) = make_float2(acc[nf][2] + x1.x, acc[nf][3] + x1.y);
        }
    }
}

// ---------------- kernel 2: s_src/s_dst + per-head maxima ----------------
__global__ __launch_bounds__(256) void k_s(const float* __restrict__ a) {
    int warp = threadIdx.x >> 5, lane = threadIdx.x & 31;
    int idx = blockIdx.x * 8 + warp;
    int h = idx >> 12;
    int n = idx & (N_NODES - 1);
    const float* wxr = g_Wx + ((size_t)h * N_NODES + n) * DHEAD;
    float w0 = wxr[lane], w1 = wxr[lane + 32];
    const float* ah = a + h * 2 * DHEAD;
    float ps = w0 * ah[lane]      + w1 * ah[lane + 32];
    float pd = w0 * ah[64 + lane] + w1 * ah[96 + lane];
    #pragma unroll
    for (int o = 16; o; o >>= 1) {
        ps += __shfl_xor_sync(0xFFFFFFFFu, ps, o);
        pd += __shfl_xor_sync(0xFFFFFFFFu, pd, o);
    }
    if (lane == 0) {
        g_ssrc[h * N_NODES + n] = ps;
        g_sdst[h * N_NODES + n] = pd;
        atomicMax(&g_enc[h],          fenc(ps));
        atomicMax(&g_enc[NHEADS + h], fenc(pd));
    }
}

// ---------------- kernel 2b: transpose Wx -> [h][d][n] bf16 hi/lo ----------------
__global__ __launch_bounds__(256) void k_trans() {
    __shared__ __align__(16) float s[64][65];
    int h = blockIdx.y, n0 = blockIdx.x * 64;
    int tid = threadIdx.x;
    #pragma unroll
    for (int k = 0; k < 4; k++) {
        int e = tid + k * 256; int r = e >> 4, c4 = (e & 15) * 4;
        float4 v = *(const float4*)&g_Wx[((size_t)h * N_NODES + n0 + r) * DHEAD + c4];
        s[r][c4 + 0] = v.x; s[r][c4 + 1] = v.y; s[r][c4 + 2] = v.z; s[r][c4 + 3] = v.w;
    }
    __syncthreads();
    int d = tid >> 2, nb = (tid & 3) * 16;
    uint32_t hw[8], lw[8];
    #pragma unroll
    for (int e = 0; e < 8; e++) {
        float f0 = s[nb + e * 2][d], f1 = s[nb + e * 2 + 1][d];
        uint32_t hp = pack_bf16x2(f0, f1);
        hw[e] = hp;
        lw[e] = pack_bf16x2(f0 - bf_lo_f(hp), f1 - bf_hi_f(hp));
    }
    size_t base = ((size_t)h * DHEAD + d) * N_NODES + n0 + nb;
    *(uint4*)(g_WxT_hi + base)     = make_uint4(hw[0], hw[1], hw[2], hw[3]);
    *(uint4*)(g_WxT_hi + base + 8) = make_uint4(hw[4], hw[5], hw[6], hw[7]);
    *(uint4*)(g_WxT_lo + base)     = make_uint4(lw[0], lw[1], lw[2], lw[3]);
    *(uint4*)(g_WxT_lo + base + 8) = make_uint4(lw[4], lw[5], lw[6], lw[7]);
}

// ---------------- kernel 2c: E/P tables per head ----------------
__global__ __launch_bounds__(1024) void k_prep() {
    int h = blockIdx.x, tid = threadIdx.x;
    const float maxsrc = fdec(g_enc[h]);
    const float maxdst = fdec(g_enc[NHEADS + h]);
    const float S  = maxsrc + maxdst;
    const float Mh = fmaxf(S, 0.2f * S);
    const float r_ = Mh - 0.2f * S;
    const float c_ = 0.2f * maxsrc + 0.5f * r_;
    const float d_ = 0.2f * maxdst + 0.5f * r_;
    #pragma unroll
    for (int k = 0; k < 4; k++) {
        int j = tid + k * 1024;
        float sj = g_sdst[h * N_NODES + j];
        g_E[h * N_NODES + j] = make_float2(fexp(sj - maxdst), fexp(fmaf(0.2f, sj, -d_)));
        float si = g_ssrc[h * N_NODES + j];
        g_P[h * N_NODES + j] = make_float4(fexp(si - maxsrc), fexp(fmaf(0.2f, si, -c_)),
                                           fexp(-si - maxdst), 0.0f);
    }
}

// ---------------- kernel 3: fused masked softmax + HMMA AV ----------------
// grid (64, 4), 8 warps: split-K over j-halves; ping-pong B buffers, 1 sync/tile;
// bitmask adjacency; all loads prefetched one tile ahead.
__global__ __launch_bounds__(256, 2) void k_attn(const float* __restrict__ bias,
                                                 float* __restrict__ out) {
    __shared__ __align__(16) char sraw[36864 + 256];
    // buf b: hi at b*18432, lo at b*18432+9216
    float* s_acc = (float*)sraw;
    float* s_dn  = (float*)(sraw + 36864);

    const int tid = threadIdx.x, wid = tid >> 5, lane = tid & 31;
    const int g = lane >> 2, t2 = (lane & 3) * 2;
    const int wg = wid & 3, half = wid >> 2;
    const int h = blockIdx.y, i0 = blockIdx.x * 64;

    const int r0 = i0 + wg * 16 + g, r1 = r0 + 8;
    const float4 P0 = g_P[h * N_NODES + r0];
    const float4 P1 = g_P[h * N_NODES + r1];
    const float2* Eh = g_E + h * N_NODES;
    const int jb0 = half * 32 + t2;           // j offset within tile for this thread

    const __nv_bfloat16* bhip = g_WxT_hi + (size_t)h * DHEAD * N_NODES;
    const __nv_bfloat16* blop = g_WxT_lo + (size_t)h * DHEAD * N_NODES;

    // B staging map: 2 uint4 hi + 2 lo per thread
    const int e0 = tid * 2, e1 = tid * 2 + 1;
    const int pr0 = e0 >> 3, pc0 = (e0 & 7) * 8;
    const int pr1 = e1 >> 3, pc1 = (e1 & 7) * 8;

    // ---- prologue: tile 0 ----
    uint32_t mc0 = g_bits[r0 * 128 + half];
    uint32_t mc1 = g_bits[r1 * 128 + half];
    float4 Ec0 = *(const float4*)&Eh[jb0];
    float4 Ec1 = *(const float4*)&Eh[jb0 + 8];
    float4 Ec2 = *(const float4*)&Eh[jb0 + 16];
    float4 Ec3 = *(const float4*)&Eh[jb0 + 24];
    {
        __nv_bfloat16* bh = (__nv_bfloat16*)sraw;
        __nv_bfloat16* bl = (__nv_bfloat16*)(sraw + 9216);
        *(uint4*)&bh[pr0 * BPAD + pc0] = *(const uint4*)(bhip + (size_t)pr0 * N_NODES + pc0);
        *(uint4*)&bh[pr1 * BPAD + pc1] = *(const uint4*)(bhip + (size_t)pr1 * N_NODES + pc1);
        *(uint4*)&bl[pr0 * BPAD + pc0] = *(const uint4*)(blop + (size_t)pr0 * N_NODES + pc0);
        *(uint4*)&bl[pr1 * BPAD + pc1] = *(const uint4*)(blop + (size_t)pr1 * N_NODES + pc1);
    }
    __syncthreads();

    float acc[8][4] = {};
    float den0 = 0.0f, den1 = 0.0f;

    for (int t = 0; t < 64; t++) {
        const int cur = t & 1;
        // prefetch tile t+1
        uint4 nh0, nh1, nl0, nl1;
        uint32_t mn0 = 0, mn1 = 0;
        float4 En0, En1, En2, En3;
        if (t < 63) {
            const int jn = (t + 1) * 64;
            nh0 = *(const uint4*)(bhip + (size_t)pr0 * N_NODES + jn + pc0);
            nh1 = *(const uint4*)(bhip + (size_t)pr1 * N_NODES + jn + pc1);
            nl0 = *(const uint4*)(blop + (size_t)pr0 * N_NODES + jn + pc0);
            nl1 = *(const uint4*)(blop + (size_t)pr1 * N_NODES + jn + pc1);
            mn0 = g_bits[r0 * 128 + (t + 1) * 2 + half];
            mn1 = g_bits[r1 * 128 + (t + 1) * 2 + half];
            En0 = *(const float4*)&Eh[jn + jb0];
            En1 = *(const float4*)&Eh[jn + jb0 + 8];
            En2 = *(const float4*)&Eh[jn + jb0 + 16];
            En3 = *(const float4*)&Eh[jn + jb0 + 24];
        }

        // ---- A fragments from bitmask + E tables ----
        uint32_t ahi[2][4], alo[2][4];
        #pragma unroll
        for (int kf = 0; kf < 2; kf++) {
            const float4 eA = kf ? Ec2 : Ec0;
            const float4 eB = kf ? Ec3 : Ec1;
            const uint32_t ma0 = mc0 >> (kf * 16 + t2);
            const uint32_t ma1 = mc1 >> (kf * 16 + t2);

            bool cA0 = (eA.x >= P0.z), cA1 = (eA.z >= P0.z);
            bool cB0 = (eB.x >= P0.z), cB1 = (eB.z >= P0.z);
            float p00 = (ma0 & 1u)   ? (cA0 ? P0.x * eA.x : P0.y * eA.y) : 0.0f;
            float p01 = (ma0 & 2u)   ? (cA1 ? P0.x * eA.z : P0.y * eA.w) : 0.0f;
            float p08 = (ma0 & 256u) ? (cB0 ? P0.x * eB.x : P0.y * eB.y) : 0.0f;
            float p09 = (ma0 & 512u) ? (cB1 ? P0.x * eB.z : P0.y * eB.w) : 0.0f;

            bool dA0 = (eA.x >= P1.z), dA1 = (eA.z >= P1.z);
            bool dB0 = (eB.x >= P1.z), dB1 = (eB.z >= P1.z);
            float p10 = (ma1 & 1u)   ? (dA0 ? P1.x * eA.x : P1.y * eA.y) : 0.0f;
            float p11 = (ma1 & 2u)   ? (dA1 ? P1.x * eA.z : P1.y * eA.w) : 0.0f;
            float p18 = (ma1 & 256u) ? (dB0 ? P1.x * eB.x : P1.y * eB.y) : 0.0f;
            float p19 = (ma1 & 512u) ? (dB1 ? P1.x * eB.z : P1.y * eB.w) : 0.0f;

            den0 += (p00 + p01) + (p08 + p09);
            den1 += (p10 + p11) + (p18 + p19);

            uint32_t h0 = pack_bf16x2(p00, p01);
            uint32_t h1 = pack_bf16x2(p10, p11);
            uint32_t h2 = pack_bf16x2(p08, p09);
            uint32_t h3 = pack_bf16x2(p18, p19);
            ahi[kf][0] = h0; ahi[kf][1] = h1; ahi[kf][2] = h2; ahi[kf][3] = h3;
            alo[kf][0] = pack_bf16x2(p00 - bf_lo_f(h0), p01 - bf_hi_f(h0));
            alo[kf][1] = pack_bf16x2(p10 - bf_lo_f(h1), p11 - bf_hi_f(h1));
            alo[kf][2] = pack_bf16x2(p08 - bf_lo_f(h2), p09 - bf_hi_f(h2));
            alo[kf][3] = pack_bf16x2(p18 - bf_lo_f(h3), p19 - bf_hi_f(h3));
        }

        // ---- MMAs from current buffer ----
        const __nv_bfloat16* cbh = (const __nv_bfloat16*)(sraw + cur * 18432);
        const __nv_bfloat16* cbl = cbh + 4608;
        #pragma unroll
        for (int nf = 0; nf < 8; nf++) {
            const int brow = (nf * 8 + g) * BPAD + half * 32;
            #pragma unroll
            for (int kf = 0; kf < 2; kf++) {
                const int boff = brow + kf * 16 + t2;
                uint32_t bh0 = *(const uint32_t*)&cbh[boff];
                uint32_t bh1 = *(const uint32_t*)&cbh[boff + 8];
                uint32_t bl0 = *(const uint32_t*)&cbl[boff];
                uint32_t bl1 = *(const uint32_t*)&cbl[boff + 8];
                mma_bf16(acc[nf], ahi[kf], bh0, bh1);
                mma_bf16(acc[nf], alo[kf], bh0, bh1);
                mma_bf16(acc[nf], ahi[kf], bl0, bl1);
            }
        }

        // ---- store prefetched tile into other buffer ----
        if (t < 63) {
            __nv_bfloat16* bh = (__nv_bfloat16*)(sraw + (1 - cur) * 18432);
            __nv_bfloat16* bl = bh + 4608;
            *(uint4*)&bh[pr0 * BPAD + pc0] = nh0;
            *(uint4*)&bh[pr1 * BPAD + pc1] = nh1;
            *(uint4*)&bl[pr0 * BPAD + pc0] = nl0;
            *(uint4*)&bl[pr1 * BPAD + pc1] = nl1;
            mc0 = mn0; mc1 = mn1;
            Ec0 = En0; Ec1 = En1; Ec2 = En2; Ec3 = En3;
        }
        __syncthreads();
    }

    // ---- merge halves ----
    den0 += __shfl_xor_sync(0xFFFFFFFFu, den0, 1);
    den0 += __shfl_xor_sync(0xFFFFFFFFu, den0, 2);
    den1 += __shfl_xor_sync(0xFFFFFFFFu, den1, 1);
    den1 += __shfl_xor_sync(0xFFFFFFFFu, den1, 2);

    if (half == 1) {
        if ((lane & 3) == 0) {
            s_dn[wg * 16 + g]     = den0;
            s_dn[wg * 16 + g + 8] = den1;
        }
        #pragma unroll
        for (int nf = 0; nf < 8; nf++) {
            *(float2*)&s_acc[(wg * 16 + g) * 64 + nf * 8 + t2]     = make_float2(acc[nf][0], acc[nf][1]);
            *(float2*)&s_acc[(wg * 16 + g + 8) * 64 + nf * 8 + t2] = make_float2(acc[nf][2], acc[nf][3]);
        }
    }
    __syncthreads();
    if (half == 0) {
        const float inv0 = 1.0f / (den0 + s_dn[wg * 16 + g]);
        const float inv1 = 1.0f / (den1 + s_dn[wg * 16 + g + 8]);
        float* orow0 = out + (size_t)r0 * (NHEADS * DHEAD) + h * DHEAD;
        float* orow1 = out + (size_t)r1 * (NHEADS * DHEAD) + h * DHEAD;
        #pragma unroll
        for (int nf = 0; nf < 8; nf++) {
            float2 x0 = *(const float2*)&s_acc[(wg * 16 + g) * 64 + nf * 8 + t2];
            float2 x1 = *(const float2*)&s_acc[(wg * 16 + g + 8) * 64 + nf * 8 + t2];
            float2 b2 = *(const float2*)&bias[h * DHEAD + nf * 8 + t2];
            float2 o0, o1;
            o0.x = fmaxf(fmaf(acc[nf][0] + x0.x, inv0, b2.x), 0.0f);
            o0.y = fmaxf(fmaf(acc[nf][1] + x0.y, inv0, b2.y), 0.0f);
            o1.x = fmaxf(fmaf(acc[nf][2] + x1.x, inv1, b2.x), 0.0f);
            o1.y = fmaxf(fmaf(acc[nf][3] + x1.y, inv1, b2.y), 0.0f);
            *(float2*)(orow0 + nf * 8 + t2) = o0;
            *(float2*)(orow1 + nf * 8 + t2) = o1;
        }
    }
}

// ---------------- launch ----------------
extern "C" void kernel_launch(void* const* d_in, const int* in_sizes, int n_in,
                              void* d_out, int out_size) {
    const float* x    = (const float*)d_in[0];
    const int*   adj  = (const int*)  d_in[1];
    const float* W    = (const float*)d_in[2];
    const float* a    = (const float*)d_in[3];
    const float* bias = (const float*)d_in[4];
    float* out = (float*)d_out;

    k_init  <<<1, 32>>>();
    k_bits  <<<N_NODES, 256>>>(adj);
    k_xsplit<<<(N_NODES * F_IN) / 1024, 256>>>(x);
    k_wsplit<<<dim3(F_IN / 64, NHEADS), 256>>>(W);
    k_wx_mma<<<dim3(N_NODES / 64, NHEADS), 256>>>();
    k_s     <<<(NHEADS * N_NODES) / 8, 256>>>(a);
    k_trans <<<dim3(64, NHEADS), 256>>>();
    k_prep  <<<NHEADS, 1024>>>();
    k_attn  <<<dim3(N_NODES / 64, NHEADS), 256>>>(bias, out);
}

// round 9
// speedup vs baseline: 3.3457x; 1.1187x over previous
#include <cuda_runtime.h>
#include <cuda_bf16.h>
#include <cuda_fp16.h>
#include <stdint.h>

#define N_NODES 4096
#define F_IN    512
#define NHEADS  4
#define DHEAD   64
#define BPAD    72

// ---------------- device scratch ----------------
__device__ float    g_Wx[NHEADS * N_NODES * DHEAD];
__device__ float    g_ssrc[NHEADS * N_NODES];
__device__ float    g_sdst[NHEADS * N_NODES];
__device__ unsigned g_enc[2 * NHEADS];
__device__ __half   g_WxT_hi[NHEADS * DHEAD * N_NODES];   // fp16 hi
__device__ __half   g_WxT_lo[NHEADS * DHEAD * N_NODES];   // fp16 residual
__device__ __nv_bfloat16 g_xhi[N_NODES * F_IN];
__device__ __nv_bfloat16 g_xlo[N_NODES * F_IN];
__device__ __nv_bfloat16 g_WT_hi[NHEADS * DHEAD * F_IN];
__device__ __nv_bfloat16 g_WT_lo[NHEADS * DHEAD * F_IN];
__device__ float2   g_E[NHEADS * N_NODES];       // {Ej1, Ej2}
__device__ float4   g_P[NHEADS * N_NODES];       // {Pi1', Pi2', Ti, 0} (per-row scaled)
__device__ uint32_t g_bits[N_NODES * 128];       // adj bitmask, 2MB

// ---------------- helpers ----------------
__device__ __forceinline__ uint32_t pack_bf16x2(float lo, float hi) {
    uint32_t r;
    asm("cvt.rn.bf16x2.f32 %0, %1, %2;" : "=r"(r) : "f"(hi), "f"(lo));
    return r;
}
__device__ __forceinline__ float bf_lo_f(uint32_t w) { return __uint_as_float(w << 16); }
__device__ __forceinline__ float bf_hi_f(uint32_t w) { return __uint_as_float(w & 0xFFFF0000u); }

__device__ __forceinline__ uint32_t pack_f16x2(float lo, float hi) {
    uint32_t r;
    asm("cvt.rn.f16x2.f32 %0, %1, %2;" : "=r"(r) : "f"(hi), "f"(lo));
    return r;
}
__device__ __forceinline__ float f16_lo_f(uint32_t w) {
    float f;
    asm("{.reg .f16 l, h; mov.b32 {l, h}, %1; cvt.f32.f16 %0, l;}" : "=f"(f) : "r"(w));
    return f;
}
__device__ __forceinline__ float f16_hi_f(uint32_t w) {
    float f;
    asm("{.reg .f16 l, h; mov.b32 {l, h}, %1; cvt.f32.f16 %0, h;}" : "=f"(f) : "r"(w));
    return f;
}

__device__ __forceinline__ unsigned fenc(float f) {
    unsigned u = __float_as_uint(f);
    return (u & 0x80000000u) ? ~u : (u | 0x80000000u);
}
__device__ __forceinline__ float fdec(unsigned u) {
    unsigned b = (u & 0x80000000u) ? (u & 0x7FFFFFFFu) : ~u;
    return __uint_as_float(b);
}

__device__ __forceinline__ float fexp(float v) {
    float x = v * 1.4426950408889634f;
    x = fmaxf(x, -126.0f);
    float kf = x + 12582912.0f;
    int   ki = __float_as_int(kf) - 0x4B400000;
    float r  = x - (kf - 12582912.0f);
    float p  = 1.3333558146e-3f;
    p = fmaf(p, r, 9.6181291076e-3f);
    p = fmaf(p, r, 5.5504108664e-2f);
    p = fmaf(p, r, 2.4022650696e-1f);
    p = fmaf(p, r, 6.9314718056e-1f);
    p = fmaf(p, r, 1.0f);
    return __int_as_float(__float_as_int(p) + (ki << 23));
}

__device__ __forceinline__ void mma_bf16(float* c, const uint32_t* a, uint32_t b0, uint32_t b1) {
    asm volatile(
        "mma.sync.aligned.m16n8k16.row.col.f32.bf16.bf16.f32 "
        "{%0,%1,%2,%3}, {%4,%5,%6,%7}, {%8,%9}, {%0,%1,%2,%3};"
        : "+f"(c[0]), "+f"(c[1]), "+f"(c[2]), "+f"(c[3])
        : "r"(a[0]), "r"(a[1]), "r"(a[2]), "r"(a[3]), "r"(b0), "r"(b1));
}
__device__ __forceinline__ void mma_f16(float* c, const uint32_t* a, uint32_t b0, uint32_t b1) {
    asm volatile(
        "mma.sync.aligned.m16n8k16.row.col.f32.f16.f16.f32 "
        "{%0,%1,%2,%3}, {%4,%5,%6,%7}, {%8,%9}, {%0,%1,%2,%3};"
        : "+f"(c[0]), "+f"(c[1]), "+f"(c[2]), "+f"(c[3])
        : "r"(a[0]), "r"(a[1]), "r"(a[2]), "r"(a[3]), "r"(b0), "r"(b1));
}

// ---------------- kernel 0 ----------------
__global__ void k_init() {
    int t = threadIdx.x;
    if (t < 2 * NHEADS) g_enc[t] = 0u;
}

// ---------------- adj -> bitmask ----------------
__global__ __launch_bounds__(256) void k_bits(const int* __restrict__ adj) {
    int row = blockIdx.x;
    int wid = threadIdx.x >> 5, lane = threadIdx.x & 31;
    const int* arow = adj + (size_t)row * N_NODES;
    #pragma unroll
    for (int w = 0; w < 16; w++) {
        int word = wid * 16 + w;
        uint32_t m = __ballot_sync(0xFFFFFFFFu, arow[word * 32 + lane] > 0);
        if (lane == 0) g_bits[row * 128 + word] = m;
    }
}

// ---------------- split x into bf16 hi/lo ----------------
__global__ __launch_bounds__(256) void k_xsplit(const float* __restrict__ x) {
    int i = (blockIdx.x * 256 + threadIdx.x) * 4;
    float4 v = *(const float4*)(x + i);
    uint32_t h0 = pack_bf16x2(v.x, v.y);
    uint32_t h1 = pack_bf16x2(v.z, v.w);
    uint32_t l0 = pack_bf16x2(v.x - bf_lo_f(h0), v.y - bf_hi_f(h0));
    uint32_t l1 = pack_bf16x2(v.z - bf_lo_f(h1), v.w - bf_hi_f(h1));
    *(uint2*)(g_xhi + i) = make_uint2(h0, h1);
    *(uint2*)(g_xlo + i) = make_uint2(l0, l1);
}

// ---------------- split+transpose W -> [h][d][k] bf16 hi/lo ----------------
__global__ __launch_bounds__(256) void k_wsplit(const float* __restrict__ W) {
    __shared__ __align__(16) float s[64][65];
    int h = blockIdx.y, k0 = blockIdx.x * 64;
    int tid = threadIdx.x;
    const float* Wh = W + (size_t)h * F_IN * DHEAD;
    #pragma unroll
    for (int k = 0; k < 4; k++) {
        int e = tid + k * 256; int r = e >> 4, c4 = (e & 15) * 4;
        float4 v = *(const float4*)&Wh[(size_t)(k0 + r) * DHEAD + c4];
        s[r][c4 + 0] = v.x; s[r][c4 + 1] = v.y; s[r][c4 + 2] = v.z; s[r][c4 + 3] = v.w;
    }
    __syncthreads();
    int d = tid >> 2, kb = (tid & 3) * 16;
    uint32_t hw[8], lw[8];
    #pragma unroll
    for (int e = 0; e < 8; e++) {
        float f0 = s[kb + e * 2][d], f1 = s[kb + e * 2 + 1][d];
        uint32_t hp = pack_bf16x2(f0, f1);
        hw[e] = hp;
        lw[e] = pack_bf16x2(f0 - bf_lo_f(hp), f1 - bf_hi_f(hp));
    }
    size_t base = ((size_t)h * DHEAD + d) * F_IN + k0 + kb;
    *(uint4*)(g_WT_hi + base)     = make_uint4(hw[0], hw[1], hw[2], hw[3]);
    *(uint4*)(g_WT_hi + base + 8) = make_uint4(hw[4], hw[5], hw[6], hw[7]);
    *(uint4*)(g_WT_lo + base)     = make_uint4(lw[0], lw[1], lw[2], lw[3]);
    *(uint4*)(g_WT_lo + base + 8) = make_uint4(lw[4], lw[5], lw[6], lw[7]);
}

// ---------------- kernel 1: Wx = x @ W per head, split-K HMMA ----------------
__global__ __launch_bounds__(256, 2) void k_wx_mma() {
    __shared__ __align__(16) char swraw[36864 + 256];
    __nv_bfloat16* s_wh = (__nv_bfloat16*)swraw;
    __nv_bfloat16* s_wl = (__nv_bfloat16*)(swraw + 18432);
    float* s_acc = (float*)swraw;

    const int tid = threadIdx.x, wid = tid >> 5, lane = tid & 31;
    const int g = lane >> 2, t2 = (lane & 3) * 2;
    const int wg = wid & 3, half = wid >> 2;
    const int h = blockIdx.y, i0 = blockIdx.x * 64;
    const int r0 = i0 + wg * 16 + g, r1 = r0 + 8;

    const __nv_bfloat16* wth = g_WT_hi + (size_t)h * DHEAD * F_IN;
    const __nv_bfloat16* wtl = g_WT_lo + (size_t)h * DHEAD * F_IN;

    float acc[8][4] = {};
    for (int chunk = 0; chunk < 4; chunk++) {
        const int kc = chunk * 64;
        __syncthreads();
        #pragma unroll
        for (int it = 0; it < 4; it++) {
            int e = tid + it * 256; int r = e >> 3, c = (e & 7) * 8;
            int d = r & 63, ks = (r >> 6) * 256 + kc + c;
            *(uint4*)&s_wh[r * BPAD + c] = *(const uint4*)&wth[(size_t)d * F_IN + ks];
            *(uint4*)&s_wl[r * BPAD + c] = *(const uint4*)&wtl[(size_t)d * F_IN + ks];
        }
        __syncthreads();

        uint32_t ahi[4][4], alo[4][4];
        #pragma unroll
        for (int kf = 0; kf < 4; kf++) {
            int k = half * 256 + kc + kf * 16 + t2;
            ahi[kf][0] = *(const uint32_t*)&g_xhi[(size_t)r0 * F_IN + k];
            ahi[kf][1] = *(const uint32_t*)&g_xhi[(size_t)r1 * F_IN + k];
            ahi[kf][2] = *(const uint32_t*)&g_xhi[(size_t)r0 * F_IN + k + 8];
            ahi[kf][3] = *(const uint32_t*)&g_xhi[(size_t)r1 * F_IN + k + 8];
            alo[kf][0] = *(const uint32_t*)&g_xlo[(size_t)r0 * F_IN + k];
            alo[kf][1] = *(const uint32_t*)&g_xlo[(size_t)r1 * F_IN + k];
            alo[kf][2] = *(const uint32_t*)&g_xlo[(size_t)r0 * F_IN + k + 8];
            alo[kf][3] = *(const uint32_t*)&g_xlo[(size_t)r1 * F_IN + k + 8];
        }
        #pragma unroll
        for (int nf = 0; nf < 8; nf++) {
            const int brow = (half * 64 + nf * 8 + g) * BPAD;
            #pragma unroll
            for (int kf = 0; kf < 4; kf++) {
                const int boff = brow + kf * 16 + t2;
                uint32_t bh0 = *(const uint32_t*)&s_wh[boff];
                uint32_t bh1 = *(const uint32_t*)&s_wh[boff + 8];
                uint32_t bl0 = *(const uint32_t*)&s_wl[boff];
                uint32_t bl1 = *(const uint32_t*)&s_wl[boff + 8];
                mma_bf16(acc[nf], ahi[kf], bh0, bh1);
                mma_bf16(acc[nf], alo[kf], bh0, bh1);
                mma_bf16(acc[nf], ahi[kf], bl0, bl1);
            }
        }
    }

    __syncthreads();
    if (half == 1) {
        #pragma unroll
        for (int nf = 0; nf < 8; nf++) {
            *(float2*)&s_acc[(wg * 16 + g) * 64 + nf * 8 + t2]     = make_float2(acc[nf][0], acc[nf][1]);
            *(float2*)&s_acc[(wg * 16 + g + 8) * 64 + nf * 8 + t2] = make_float2(acc[nf][2], acc[nf][3]);
        }
    }
    __syncthreads();
    if (half == 0) {
        float* o0 = g_Wx + ((size_t)h * N_NODES + r0) * DHEAD;
        float* o1 = g_Wx + ((size_t)h * N_NODES + r1) * DHEAD;
        #pragma unroll
        for (int nf = 0; nf < 8; nf++) {
            float2 x0 = *(const float2*)&s_acc[(wg * 16 + g) * 64 + nf * 8 + t2];
            float2 x1 = *(const float2*)&s_acc[(wg * 16 + g + 8) * 64 + nf * 8 + t2];
            *(float2*)(o0 + nf * 8 + t2) = make_float2(acc[nf][0] + x0.x, acc[nf][1] + x0.y);
            *(float2*)(o1 + nf * 8 + t2) = make_float2(acc[nf][2] + x1.x, acc[nf][3] + x1.y);
        }
    }
}

// ---------------- kernel 2: s_src/s_dst + per-head maxima ----------------
__global__ __launch_bounds__(256) void k_s(const float* __restrict__ a) {
    int warp = threadIdx.x >> 5, lane = threadIdx.x & 31;
    int idx = blockIdx.x * 8 + warp;
    int h = idx >> 12;
    int n = idx & (N_NODES - 1);
    const float* wxr = g_Wx + ((size_t)h * N_NODES + n) * DHEAD;
    float w0 = wxr[lane], w1 = wxr[lane + 32];
    const float* ah = a + h * 2 * DHEAD;
    float ps = w0 * ah[lane]      + w1 * ah[lane + 32];
    float pd = w0 * ah[64 + lane] + w1 * ah[96 + lane];
    #pragma unroll
    for (int o = 16; o; o >>= 1) {
        ps += __shfl_xor_sync(0xFFFFFFFFu, ps, o);
        pd += __shfl_xor_sync(0xFFFFFFFFu, pd, o);
    }
    if (lane == 0) {
        g_ssrc[h * N_NODES + n] = ps;
        g_sdst[h * N_NODES + n] = pd;
        atomicMax(&g_enc[h],          fenc(ps));
        atomicMax(&g_enc[NHEADS + h], fenc(pd));
    }
}

// ---------------- kernel 2b: transpose Wx -> [h][d][n] fp16 hi/lo ----------------
__global__ __launch_bounds__(256) void k_trans() {
    __shared__ __align__(16) float s[64][65];
    int h = blockIdx.y, n0 = blockIdx.x * 64;
    int tid = threadIdx.x;
    #pragma unroll
    for (int k = 0; k < 4; k++) {
        int e = tid + k * 256; int r = e >> 4, c4 = (e & 15) * 4;
        float4 v = *(const float4*)&g_Wx[((size_t)h * N_NODES + n0 + r) * DHEAD + c4];
        s[r][c4 + 0] = v.x; s[r][c4 + 1] = v.y; s[r][c4 + 2] = v.z; s[r][c4 + 3] = v.w;
    }
    __syncthreads();
    int d = tid >> 2, nb = (tid & 3) * 16;
    uint32_t hw[8], lw[8];
    #pragma unroll
    for (int e = 0; e < 8; e++) {
        float f0 = s[nb + e * 2][d], f1 = s[nb + e * 2 + 1][d];
        uint32_t hp = pack_f16x2(f0, f1);
        hw[e] = hp;
        lw[e] = pack_f16x2(f0 - f16_lo_f(hp), f1 - f16_hi_f(hp));
    }
    size_t base = ((size_t)h * DHEAD + d) * N_NODES + n0 + nb;
    *(uint4*)(g_WxT_hi + base)     = make_uint4(hw[0], hw[1], hw[2], hw[3]);
    *(uint4*)(g_WxT_hi + base + 8) = make_uint4(hw[4], hw[5], hw[6], hw[7]);
    *(uint4*)(g_WxT_lo + base)     = make_uint4(lw[0], lw[1], lw[2], lw[3]);
    *(uint4*)(g_WxT_lo + base + 8) = make_uint4(lw[4], lw[5], lw[6], lw[7]);
}

// ---------------- kernel 2c: E/P tables per head (per-row scaled) ----------------
__global__ __launch_bounds__(1024) void k_prep() {
    int h = blockIdx.x, tid = threadIdx.x;
    const float maxsrc = fdec(g_enc[h]);
    const float maxdst = fdec(g_enc[NHEADS + h]);
    const float S  = maxsrc + maxdst;
    const float Mh = fmaxf(S, 0.2f * S);
    const float r_ = Mh - 0.2f * S;            // >= 0
    const float c_ = 0.2f * maxsrc + 0.5f * r_;
    const float d_ = 0.2f * maxdst + 0.5f * r_;
    const float maxE2 = fexp(-0.5f * r_);      // max_j Ej2 (max_j Ej1 == 1)
    #pragma unroll
    for (int k = 0; k < 4; k++) {
        int j = tid + k * 1024;
        float sj = g_sdst[h * N_NODES + j];
        g_E[h * N_NODES + j] = make_float2(fexp(sj - maxdst), fexp(fmaf(0.2f, sj, -d_)));
        float si = g_ssrc[h * N_NODES + j];
        float Pi1 = fexp(si - maxsrc);
        float Pi2 = fexp(fmaf(0.2f, si, -c_));
        // per-row scale: bound on max_j p_ij; keeps scaled p in fp16 normal range
        float sc = 1.0f / fmaxf(Pi1, Pi2 * maxE2);
        g_P[h * N_NODES + j] = make_float4(Pi1 * sc, Pi2 * sc, fexp(-si - maxdst), 0.0f);
    }
}

// ---------------- kernel 3: fused masked softmax + HMMA AV, fp16 2-term ----------------
__global__ __launch_bounds__(256, 2) void k_attn(const float* __restrict__ bias,
                                                 float* __restrict__ out) {
    __shared__ __align__(16) char sraw[36864 + 256];
    float* s_acc = (float*)sraw;
    float* s_dn  = (float*)(sraw + 36864);

    const int tid = threadIdx.x, wid = tid >> 5, lane = tid & 31;
    const int g = lane >> 2, t2 = (lane & 3) * 2;
    const int wg = wid & 3, half = wid >> 2;
    const int h = blockIdx.y, i0 = blockIdx.x * 64;

    const int r0 = i0 + wg * 16 + g, r1 = r0 + 8;
    const float4 P0 = g_P[h * N_NODES + r0];
    const float4 P1 = g_P[h * N_NODES + r1];
    const float2* Eh = g_E + h * N_NODES;
    const int jb0 = half * 32 + t2;

    const __half* bhip = g_WxT_hi + (size_t)h * DHEAD * N_NODES;
    const __half* blop = g_WxT_lo + (size_t)h * DHEAD * N_NODES;

    const int e0 = tid * 2, e1 = tid * 2 + 1;
    const int pr0 = e0 >> 3, pc0 = (e0 & 7) * 8;
    const int pr1 = e1 >> 3, pc1 = (e1 & 7) * 8;

    uint32_t mc0 = g_bits[r0 * 128 + half];
    uint32_t mc1 = g_bits[r1 * 128 + half];
    float4 Ec0 = *(const float4*)&Eh[jb0];
    float4 Ec1 = *(const float4*)&Eh[jb0 + 8];
    float4 Ec2 = *(const float4*)&Eh[jb0 + 16];
    float4 Ec3 = *(const float4*)&Eh[jb0 + 24];
    {
        __half* bh = (__half*)sraw;
        __half* bl = (__half*)(sraw + 9216);
        *(uint4*)&bh[pr0 * BPAD + pc0] = *(const uint4*)(bhip + (size_t)pr0 * N_NODES + pc0);
        *(uint4*)&bh[pr1 * BPAD + pc1] = *(const uint4*)(bhip + (size_t)pr1 * N_NODES + pc1);
        *(uint4*)&bl[pr0 * BPAD + pc0] = *(const uint4*)(blop + (size_t)pr0 * N_NODES + pc0);
        *(uint4*)&bl[pr1 * BPAD + pc1] = *(const uint4*)(blop + (size_t)pr1 * N_NODES + pc1);
    }
    __syncthreads();

    float acc[8][4] = {};
    float den0 = 0.0f, den1 = 0.0f;

    for (int t = 0; t < 64; t++) {
        const int cur = t & 1;
        uint4 nh0, nh1, nl0, nl1;
        uint32_t mn0 = 0, mn1 = 0;
        float4 En0, En1, En2, En3;
        if (t < 63) {
            const int jn = (t + 1) * 64;
            nh0 = *(const uint4*)(bhip + (size_t)pr0 * N_NODES + jn + pc0);
            nh1 = *(const uint4*)(bhip + (size_t)pr1 * N_NODES + jn + pc1);
            nl0 = *(const uint4*)(blop + (size_t)pr0 * N_NODES + jn + pc0);
            nl1 = *(const uint4*)(blop + (size_t)pr1 * N_NODES + jn + pc1);
            mn0 = g_bits[r0 * 128 + (t + 1) * 2 + half];
            mn1 = g_bits[r1 * 128 + (t + 1) * 2 + half];
            En0 = *(const float4*)&Eh[jn + jb0];
            En1 = *(const float4*)&Eh[jn + jb0 + 8];
            En2 = *(const float4*)&Eh[jn + jb0 + 16];
            En3 = *(const float4*)&Eh[jn + jb0 + 24];
        }

        // ---- A fragments: per-row-scaled p as single fp16 ----
        uint32_t ahi[2][4];
        #pragma unroll
        for (int kf = 0; kf < 2; kf++) {
            const float4 eA = kf ? Ec2 : Ec0;
            const float4 eB = kf ? Ec3 : Ec1;
            const uint32_t ma0 = mc0 >> (kf * 16 + t2);
            const uint32_t ma1 = mc1 >> (kf * 16 + t2);

            bool cA0 = (eA.x >= P0.z), cA1 = (eA.z >= P0.z);
            bool cB0 = (eB.x >= P0.z), cB1 = (eB.z >= P0.z);
            float p00 = (ma0 & 1u)   ? (cA0 ? P0.x * eA.x : P0.y * eA.y) : 0.0f;
            float p01 = (ma0 & 2u)   ? (cA1 ? P0.x * eA.z : P0.y * eA.w) : 0.0f;
            float p08 = (ma0 & 256u) ? (cB0 ? P0.x * eB.x : P0.y * eB.y) : 0.0f;
            float p09 = (ma0 & 512u) ? (cB1 ? P0.x * eB.z : P0.y * eB.w) : 0.0f;

            bool dA0 = (eA.x >= P1.z), dA1 = (eA.z >= P1.z);
            bool dB0 = (eB.x >= P1.z), dB1 = (eB.z >= P1.z);
            float p10 = (ma1 & 1u)   ? (dA0 ? P1.x * eA.x : P1.y * eA.y) : 0.0f;
            float p11 = (ma1 & 2u)   ? (dA1 ? P1.x * eA.z : P1.y * eA.w) : 0.0f;
            float p18 = (ma1 & 256u) ? (dB0 ? P1.x * eB.x : P1.y * eB.y) : 0.0f;
            float p19 = (ma1 & 512u) ? (dB1 ? P1.x * eB.z : P1.y * eB.w) : 0.0f;

            den0 += (p00 + p01) + (p08 + p09);
            den1 += (p10 + p11) + (p18 + p19);

            ahi[kf][0] = pack_f16x2(p00, p01);
            ahi[kf][1] = pack_f16x2(p10, p11);
            ahi[kf][2] = pack_f16x2(p08, p09);
            ahi[kf][3] = pack_f16x2(p18, p19);
        }

        // ---- 2-term MMAs: acc += A*Bhi + A*Blo ----
        const __half* cbh = (const __half*)(sraw + cur * 18432);
        const __half* cbl = cbh + 4608;
        #pragma unroll
        for (int nf = 0; nf < 8; nf++) {
            const int brow = (nf * 8 + g) * BPAD + half * 32;
            #pragma unroll
            for (int kf = 0; kf < 2; kf++) {
                const int boff = brow + kf * 16 + t2;
                uint32_t bh0 = *(const uint32_t*)&cbh[boff];
                uint32_t bh1 = *(const uint32_t*)&cbh[boff + 8];
                uint32_t bl0 = *(const uint32_t*)&cbl[boff];
                uint32_t bl1 = *(const uint32_t*)&cbl[boff + 8];
                mma_f16(acc[nf], ahi[kf], bh0, bh1);
                mma_f16(acc[nf], ahi[kf], bl0, bl1);
            }
        }

        if (t < 63) {
            __half* bh = (__half*)(sraw + (1 - cur) * 18432);
            __half* bl = bh + 4608;
            *(uint4*)&bh[pr0 * BPAD + pc0] = nh0;
            *(uint4*)&bh[pr1 * BPAD + pc1] = nh1;
            *(uint4*)&bl[pr0 * BPAD + pc0] = nl0;
            *(uint4*)&bl[pr1 * BPAD + pc1] = nl1;
            mc0 = mn0; mc1 = mn1;
            Ec0 = En0; Ec1 = En1; Ec2 = En2; Ec3 = En3;
        }
        __syncthreads();
    }

    // ---- merge halves ----
    den0 += __shfl_xor_sync(0xFFFFFFFFu, den0, 1);
    den0 += __shfl_xor_sync(0xFFFFFFFFu, den0, 2);
    den1 += __shfl_xor_sync(0xFFFFFFFFu, den1, 1);
    den1 += __shfl_xor_sync(0xFFFFFFFFu, den1, 2);

    if (half == 1) {
        if ((lane & 3) == 0) {
            s_dn[wg * 16 + g]     = den0;
            s_dn[wg * 16 + g + 8] = den1;
        }
        #pragma unroll
        for (int nf = 0; nf < 8; nf++) {
            *(float2*)&s_acc[(wg * 16 + g) * 64 + nf * 8 + t2]     = make_float2(acc[nf][0], acc[nf][1]);
            *(float2*)&s_acc[(wg * 16 + g + 8) * 64 + nf * 8 + t2] = make_float2(acc[nf][2], acc[nf][3]);
        }
    }
    __syncthreads();
    if (half == 0) {
        const float inv0 = 1.0f / (den0 + s_dn[wg * 16 + g]);
        const float inv1 = 1.0f / (den1 + s_dn[wg * 16 + g + 8]);
        float* orow0 = out + (size_t)r0 * (NHEADS * DHEAD) + h * DHEAD;
        float* orow1 = out + (size_t)r1 * (NHEADS * DHEAD) + h * DHEAD;
        #pragma unroll
        for (int nf = 0; nf < 8; nf++) {
            float2 x0 = *(const float2*)&s_acc[(wg * 16 + g) * 64 + nf * 8 + t2];
            float2 x1 = *(const float2*)&s_acc[(wg * 16 + g + 8) * 64 + nf * 8 + t2];
            float2 b2 = *(const float2*)&bias[h * DHEAD + nf * 8 + t2];
            float2 o0, o1;
            o0.x = fmaxf(fmaf(acc[nf][0] + x0.x, inv0, b2.x), 0.0f);
            o0.y = fmaxf(fmaf(acc[nf][1] + x0.y, inv0, b2.y), 0.0f);
            o1.x = fmaxf(fmaf(acc[nf][2] + x1.x, inv1, b2.x), 0.0f);
            o1.y = fmaxf(fmaf(acc[nf][3] + x1.y, inv1, b2.y), 0.0f);
            *(float2*)(orow0 + nf * 8 + t2) = o0;
            *(float2*)(orow1 + nf * 8 + t2) = o1;
        }
    }
}

// ---------------- launch ----------------
extern "C" void kernel_launch(void* const* d_in, const int* in_sizes, int n_in,
                              void* d_out, int out_size) {
    const float* x    = (const float*)d_in[0];
    const int*   adj  = (const int*)  d_in[1];
    const float* W    = (const float*)d_in[2];
    const float* a    = (const float*)d_in[3];
    const float* bias = (const float*)d_in[4];
    float* out = (float*)d_out;

    k_init  <<<1, 32>>>();
    k_bits  <<<N_NODES, 256>>>(adj);
    k_xsplit<<<(N_NODES * F_IN) / 1024, 256>>>(x);
    k_wsplit<<<dim3(F_IN / 64, NHEADS), 256>>>(W);
    k_wx_mma<<<dim3(N_NODES / 64, NHEADS), 256>>>();
    k_s     <<<(NHEADS * N_NODES) / 8, 256>>>(a);
    k_trans <<<dim3(64, NHEADS), 256>>>();
    k_prep  <<<NHEADS, 1024>>>();
    k_attn  <<<dim3(N_NODES / 64, NHEADS), 256>>>(bias, out);
}

// round 10
// speedup vs baseline: 4.1976x; 1.2546x over previous
#include <cuda_runtime.h>
#include <cuda_bf16.h>
#include <cuda_fp16.h>
#include <stdint.h>

#define N_NODES 4096
#define F_IN    512
#define NHEADS  4
#define DHEAD   64
#define BPAD    72

// ---------------- device scratch ----------------
__device__ float    g_Wx[NHEADS * N_NODES * DHEAD];
__device__ float    g_ssrc[NHEADS * N_NODES];
__device__ float    g_sdst[NHEADS * N_NODES];
__device__ unsigned g_enc[2 * NHEADS];
__device__ __half   g_WxT[NHEADS * DHEAD * N_NODES];      // fp16 (single term)
__device__ __nv_bfloat16 g_xhi[N_NODES * F_IN];
__device__ __nv_bfloat16 g_xlo[N_NODES * F_IN];
__device__ __nv_bfloat16 g_WT_hi[NHEADS * DHEAD * F_IN];
__device__ __nv_bfloat16 g_WT_lo[NHEADS * DHEAD * F_IN];
__device__ float2   g_E[NHEADS * N_NODES];       // {Ej1, Ej2}
__device__ float4   g_P[NHEADS * N_NODES];       // {Pi1', Pi2', Ti, 0} per-row scaled
__device__ uint32_t g_bits[N_NODES * 128];       // adj bitmask, 2MB

// ---------------- helpers ----------------
__device__ __forceinline__ uint32_t pack_bf16x2(float lo, float hi) {
    uint32_t r;
    asm("cvt.rn.bf16x2.f32 %0, %1, %2;" : "=r"(r) : "f"(hi), "f"(lo));
    return r;
}
__device__ __forceinline__ float bf_lo_f(uint32_t w) { return __uint_as_float(w << 16); }
__device__ __forceinline__ float bf_hi_f(uint32_t w) { return __uint_as_float(w & 0xFFFF0000u); }

__device__ __forceinline__ uint32_t pack_f16x2(float lo, float hi) {
    uint32_t r;
    asm("cvt.rn.f16x2.f32 %0, %1, %2;" : "=r"(r) : "f"(hi), "f"(lo));
    return r;
}

__device__ __forceinline__ unsigned fenc(float f) {
    unsigned u = __float_as_uint(f);
    return (u & 0x80000000u) ? ~u : (u | 0x80000000u);
}
__device__ __forceinline__ float fdec(unsigned u) {
    unsigned b = (u & 0x80000000u) ? (u & 0x7FFFFFFFu) : ~u;
    return __uint_as_float(b);
}

__device__ __forceinline__ float fexp(float v) {
    float x = v * 1.4426950408889634f;
    x = fmaxf(x, -126.0f);
    float kf = x + 12582912.0f;
    int   ki = __float_as_int(kf) - 0x4B400000;
    float r  = x - (kf - 12582912.0f);
    float p  = 1.3333558146e-3f;
    p = fmaf(p, r, 9.6181291076e-3f);
    p = fmaf(p, r, 5.5504108664e-2f);
    p = fmaf(p, r, 2.4022650696e-1f);
    p = fmaf(p, r, 6.9314718056e-1f);
    p = fmaf(p, r, 1.0f);
    return __int_as_float(__float_as_int(p) + (ki << 23));
}

__device__ __forceinline__ void mma_bf16(float* c, const uint32_t* a, uint32_t b0, uint32_t b1) {
    asm volatile(
        "mma.sync.aligned.m16n8k16.row.col.f32.bf16.bf16.f32 "
        "{%0,%1,%2,%3}, {%4,%5,%6,%7}, {%8,%9}, {%0,%1,%2,%3};"
        : "+f"(c[0]), "+f"(c[1]), "+f"(c[2]), "+f"(c[3])
        : "r"(a[0]), "r"(a[1]), "r"(a[2]), "r"(a[3]), "r"(b0), "r"(b1));
}
__device__ __forceinline__ void mma_f16(float* c, const uint32_t* a, uint32_t b0, uint32_t b1) {
    asm volatile(
        "mma.sync.aligned.m16n8k16.row.col.f32.f16.f16.f32 "
        "{%0,%1,%2,%3}, {%4,%5,%6,%7}, {%8,%9}, {%0,%1,%2,%3};"
        : "+f"(c[0]), "+f"(c[1]), "+f"(c[2]), "+f"(c[3])
        : "r"(a[0]), "r"(a[1]), "r"(a[2]), "r"(a[3]), "r"(b0), "r"(b1));
}

// ---------------- kernel 0 ----------------
__global__ void k_init() {
    int t = threadIdx.x;
    if (t < 2 * NHEADS) g_enc[t] = 0u;
}

// ---------------- adj -> bitmask ----------------
__global__ __launch_bounds__(256) void k_bits(const int* __restrict__ adj) {
    int row = blockIdx.x;
    int wid = threadIdx.x >> 5, lane = threadIdx.x & 31;
    const int* arow = adj + (size_t)row * N_NODES;
    #pragma unroll
    for (int w = 0; w < 16; w++) {
        int word = wid * 16 + w;
        uint32_t m = __ballot_sync(0xFFFFFFFFu, arow[word * 32 + lane] > 0);
        if (lane == 0) g_bits[row * 128 + word] = m;
    }
}

// ---------------- split x into bf16 hi/lo ----------------
__global__ __launch_bounds__(256) void k_xsplit(const float* __restrict__ x) {
    int i = (blockIdx.x * 256 + threadIdx.x) * 4;
    float4 v = *(const float4*)(x + i);
    uint32_t h0 = pack_bf16x2(v.x, v.y);
    uint32_t h1 = pack_bf16x2(v.z, v.w);
    uint32_t l0 = pack_bf16x2(v.x - bf_lo_f(h0), v.y - bf_hi_f(h0));
    uint32_t l1 = pack_bf16x2(v.z - bf_lo_f(h1), v.w - bf_hi_f(h1));
    *(uint2*)(g_xhi + i) = make_uint2(h0, h1);
    *(uint2*)(g_xlo + i) = make_uint2(l0, l1);
}

// ---------------- split+transpose W -> [h][d][k] bf16 hi/lo ----------------
__global__ __launch_bounds__(256) void k_wsplit(const float* __restrict__ W) {
    __shared__ __align__(16) float s[64][65];
    int h = blockIdx.y, k0 = blockIdx.x * 64;
    int tid = threadIdx.x;
    const float* Wh = W + (size_t)h * F_IN * DHEAD;
    #pragma unroll
    for (int k = 0; k < 4; k++) {
        int e = tid + k * 256; int r = e >> 4, c4 = (e & 15) * 4;
        float4 v = *(const float4*)&Wh[(size_t)(k0 + r) * DHEAD + c4];
        s[r][c4 + 0] = v.x; s[r][c4 + 1] = v.y; s[r][c4 + 2] = v.z; s[r][c4 + 3] = v.w;
    }
    __syncthreads();
    int d = tid >> 2, kb = (tid & 3) * 16;
    uint32_t hw[8], lw[8];
    #pragma unroll
    for (int e = 0; e < 8; e++) {
        float f0 = s[kb + e * 2][d], f1 = s[kb + e * 2 + 1][d];
        uint32_t hp = pack_bf16x2(f0, f1);
        hw[e] = hp;
        lw[e] = pack_bf16x2(f0 - bf_lo_f(hp), f1 - bf_hi_f(hp));
    }
    size_t base = ((size_t)h * DHEAD + d) * F_IN + k0 + kb;
    *(uint4*)(g_WT_hi + base)     = make_uint4(hw[0], hw[1], hw[2], hw[3]);
    *(uint4*)(g_WT_hi + base + 8) = make_uint4(hw[4], hw[5], hw[6], hw[7]);
    *(uint4*)(g_WT_lo + base)     = make_uint4(lw[0], lw[1], lw[2], lw[3]);
    *(uint4*)(g_WT_lo + base + 8) = make_uint4(lw[4], lw[5], lw[6], lw[7]);
}

// ---------------- kernel 1: Wx = x @ W per head, split-K HMMA ----------------
__global__ __launch_bounds__(256, 2) void k_wx_mma() {
    __shared__ __align__(16) char swraw[36864 + 256];
    __nv_bfloat16* s_wh = (__nv_bfloat16*)swraw;
    __nv_bfloat16* s_wl = (__nv_bfloat16*)(swraw + 18432);
    float* s_acc = (float*)swraw;

    const int tid = threadIdx.x, wid = tid >> 5, lane = tid & 31;
    const int g = lane >> 2, t2 = (lane & 3) * 2;
    const int wg = wid & 3, half = wid >> 2;
    const int h = blockIdx.y, i0 = blockIdx.x * 64;
    const int r0 = i0 + wg * 16 + g, r1 = r0 + 8;

    const __nv_bfloat16* wth = g_WT_hi + (size_t)h * DHEAD * F_IN;
    const __nv_bfloat16* wtl = g_WT_lo + (size_t)h * DHEAD * F_IN;

    float acc[8][4] = {};
    for (int chunk = 0; chunk < 4; chunk++) {
        const int kc = chunk * 64;
        __syncthreads();
        #pragma unroll
        for (int it = 0; it < 4; it++) {
            int e = tid + it * 256; int r = e >> 3, c = (e & 7) * 8;
            int d = r & 63, ks = (r >> 6) * 256 + kc + c;
            *(uint4*)&s_wh[r * BPAD + c] = *(const uint4*)&wth[(size_t)d * F_IN + ks];
            *(uint4*)&s_wl[r * BPAD + c] = *(const uint4*)&wtl[(size_t)d * F_IN + ks];
        }
        __syncthreads();

        uint32_t ahi[4][4], alo[4][4];
        #pragma unroll
        for (int kf = 0; kf < 4; kf++) {
            int k = half * 256 + kc + kf * 16 + t2;
            ahi[kf][0] = *(const uint32_t*)&g_xhi[(size_t)r0 * F_IN + k];
            ahi[kf][1] = *(const uint32_t*)&g_xhi[(size_t)r1 * F_IN + k];
            ahi[kf][2] = *(const uint32_t*)&g_xhi[(size_t)r0 * F_IN + k + 8];
            ahi[kf][3] = *(const uint32_t*)&g_xhi[(size_t)r1 * F_IN + k + 8];
            alo[kf][0] = *(const uint32_t*)&g_xlo[(size_t)r0 * F_IN + k];
            alo[kf][1] = *(const uint32_t*)&g_xlo[(size_t)r1 * F_IN + k];
            alo[kf][2] = *(const uint32_t*)&g_xlo[(size_t)r0 * F_IN + k + 8];
            alo[kf][3] = *(const uint32_t*)&g_xlo[(size_t)r1 * F_IN + k + 8];
        }
        #pragma unroll
        for (int nf = 0; nf < 8; nf++) {
            const int brow = (half * 64 + nf * 8 + g) * BPAD;
            #pragma unroll
            for (int kf = 0; kf < 4; kf++) {
                const int boff = brow + kf * 16 + t2;
                uint32_t bh0 = *(const uint32_t*)&s_wh[boff];
                uint32_t bh1 = *(const uint32_t*)&s_wh[boff + 8];
                uint32_t bl0 = *(const uint32_t*)&s_wl[boff];
                uint32_t bl1 = *(const uint32_t*)&s_wl[boff + 8];
                mma_bf16(acc[nf], ahi[kf], bh0, bh1);
                mma_bf16(acc[nf], alo[kf], bh0, bh1);
                mma_bf16(acc[nf], ahi[kf], bl0, bl1);
            }
        }
    }

    __syncthreads();
    if (half == 1) {
        #pragma unroll
        for (int nf = 0; nf < 8; nf++) {
            *(float2*)&s_acc[(wg * 16 + g) * 64 + nf * 8 + t2]     = make_float2(acc[nf][0], acc[nf][1]);
            *(float2*)&s_acc[(wg * 16 + g + 8) * 64 + nf * 8 + t2] = make_float2(acc[nf][2], acc[nf][3]);
        }
    }
    __syncthreads();
    if (half == 0) {
        float* o0 = g_Wx + ((size_t)h * N_NODES + r0) * DHEAD;
        float* o1 = g_Wx + ((size_t)h * N_NODES + r1) * DHEAD;
        #pragma unroll
        for (int nf = 0; nf < 8; nf++) {
            float2 x0 = *(const float2*)&s_acc[(wg * 16 + g) * 64 + nf * 8 + t2];
            float2 x1 = *(const float2*)&s_acc[(wg * 16 + g + 8) * 64 + nf * 8 + t2];
            *(float2*)(o0 + nf * 8 + t2) = make_float2(acc[nf][0] + x0.x, acc[nf][1] + x0.y);
            *(float2*)(o1 + nf * 8 + t2) = make_float2(acc[nf][2] + x1.x, acc[nf][3] + x1.y);
        }
    }
}

// ---------------- kernel 2: s_src/s_dst + per-head maxima ----------------
__global__ __launch_bounds__(256) void k_s(const float* __restrict__ a) {
    int warp = threadIdx.x >> 5, lane = threadIdx.x & 31;
    int idx = blockIdx.x * 8 + warp;
    int h = idx >> 12;
    int n = idx & (N_NODES - 1);
    const float* wxr = g_Wx + ((size_t)h * N_NODES + n) * DHEAD;
    float w0 = wxr[lane], w1 = wxr[lane + 32];
    const float* ah = a + h * 2 * DHEAD;
    float ps = w0 * ah[lane]      + w1 * ah[lane + 32];
    float pd = w0 * ah[64 + lane] + w1 * ah[96 + lane];
    #pragma unroll
    for (int o = 16; o; o >>= 1) {
        ps += __shfl_xor_sync(0xFFFFFFFFu, ps, o);
        pd += __shfl_xor_sync(0xFFFFFFFFu, pd, o);
    }
    if (lane == 0) {
        g_ssrc[h * N_NODES + n] = ps;
        g_sdst[h * N_NODES + n] = pd;
        atomicMax(&g_enc[h],          fenc(ps));
        atomicMax(&g_enc[NHEADS + h], fenc(pd));
    }
}

// ---------------- kernel 2b: transpose Wx -> [h][d][n] fp16 ----------------
__global__ __launch_bounds__(256) void k_trans() {
    __shared__ __align__(16) float s[64][65];
    int h = blockIdx.y, n0 = blockIdx.x * 64;
    int tid = threadIdx.x;
    #pragma unroll
    for (int k = 0; k < 4; k++) {
        int e = tid + k * 256; int r = e >> 4, c4 = (e & 15) * 4;
        float4 v = *(const float4*)&g_Wx[((size_t)h * N_NODES + n0 + r) * DHEAD + c4];
        s[r][c4 + 0] = v.x; s[r][c4 + 1] = v.y; s[r][c4 + 2] = v.z; s[r][c4 + 3] = v.w;
    }
    __syncthreads();
    int d = tid >> 2, nb = (tid & 3) * 16;
    uint32_t hw[8];
    #pragma unroll
    for (int e = 0; e < 8; e++) {
        float f0 = s[nb + e * 2][d], f1 = s[nb + e * 2 + 1][d];
        hw[e] = pack_f16x2(f0, f1);
    }
    size_t base = ((size_t)h * DHEAD + d) * N_NODES + n0 + nb;
    *(uint4*)(g_WxT + base)     = make_uint4(hw[0], hw[1], hw[2], hw[3]);
    *(uint4*)(g_WxT + base + 8) = make_uint4(hw[4], hw[5], hw[6], hw[7]);
}

// ---------------- kernel 2c: E/P tables per head (per-row scaled) ----------------
__global__ __launch_bounds__(1024) void k_prep() {
    int h = blockIdx.x, tid = threadIdx.x;
    const float maxsrc = fdec(g_enc[h]);
    const float maxdst = fdec(g_enc[NHEADS + h]);
    const float S  = maxsrc + maxdst;
    const float Mh = fmaxf(S, 0.2f * S);
    const float r_ = Mh - 0.2f * S;
    const float c_ = 0.2f * maxsrc + 0.5f * r_;
    const float d_ = 0.2f * maxdst + 0.5f * r_;
    const float maxE2 = fexp(-0.5f * r_);
    #pragma unroll
    for (int k = 0; k < 4; k++) {
        int j = tid + k * 1024;
        float sj = g_sdst[h * N_NODES + j];
        g_E[h * N_NODES + j] = make_float2(fexp(sj - maxdst), fexp(fmaf(0.2f, sj, -d_)));
        float si = g_ssrc[h * N_NODES + j];
        float Pi1 = fexp(si - maxsrc);
        float Pi2 = fexp(fmaf(0.2f, si, -c_));
        float sc = 1.0f / fmaxf(Pi1, Pi2 * maxE2);
        g_P[h * N_NODES + j] = make_float4(Pi1 * sc, Pi2 * sc, fexp(-si - maxdst), 0.0f);
    }
}

// ---------------- kernel 3: fused masked softmax + HMMA AV, fp16 single-B ----------------
__global__ __launch_bounds__(256, 2) void k_attn(const float* __restrict__ bias,
                                                 float* __restrict__ out) {
    __shared__ __align__(16) char sraw[18432 + 256];
    float* s_acc = (float*)sraw;              // reused after main loop (16KB)
    float* s_dn  = (float*)(sraw + 18432);

    const int tid = threadIdx.x, wid = tid >> 5, lane = tid & 31;
    const int g = lane >> 2, t2 = (lane & 3) * 2;
    const int wg = wid & 3, half = wid >> 2;
    const int h = blockIdx.y, i0 = blockIdx.x * 64;

    const int r0 = i0 + wg * 16 + g, r1 = r0 + 8;
    const float4 P0 = g_P[h * N_NODES + r0];
    const float4 P1 = g_P[h * N_NODES + r1];
    const float2* Eh = g_E + h * N_NODES;
    const int jb0 = half * 32 + t2;

    const __half* bp = g_WxT + (size_t)h * DHEAD * N_NODES;

    const int e0 = tid * 2, e1 = tid * 2 + 1;
    const int pr0 = e0 >> 3, pc0 = (e0 & 7) * 8;
    const int pr1 = e1 >> 3, pc1 = (e1 & 7) * 8;

    uint32_t mc0 = g_bits[r0 * 128 + half];
    uint32_t mc1 = g_bits[r1 * 128 + half];
    float4 Ec0 = *(const float4*)&Eh[jb0];
    float4 Ec1 = *(const float4*)&Eh[jb0 + 8];
    float4 Ec2 = *(const float4*)&Eh[jb0 + 16];
    float4 Ec3 = *(const float4*)&Eh[jb0 + 24];
    {
        __half* bh = (__half*)sraw;
        *(uint4*)&bh[pr0 * BPAD + pc0] = *(const uint4*)(bp + (size_t)pr0 * N_NODES + pc0);
        *(uint4*)&bh[pr1 * BPAD + pc1] = *(const uint4*)(bp + (size_t)pr1 * N_NODES + pc1);
    }
    __syncthreads();

    float acc[8][4] = {};
    float den0 = 0.0f, den1 = 0.0f;

    for (int t = 0; t < 64; t++) {
        const int cur = t & 1;
        uint4 nh0, nh1;
        uint32_t mn0 = 0, mn1 = 0;
        float4 En0, En1, En2, En3;
        if (t < 63) {
            const int jn = (t + 1) * 64;
            nh0 = *(const uint4*)(bp + (size_t)pr0 * N_NODES + jn + pc0);
            nh1 = *(const uint4*)(bp + (size_t)pr1 * N_NODES + jn + pc1);
            mn0 = g_bits[r0 * 128 + (t + 1) * 2 + half];
            mn1 = g_bits[r1 * 128 + (t + 1) * 2 + half];
            En0 = *(const float4*)&Eh[jn + jb0];
            En1 = *(const float4*)&Eh[jn + jb0 + 8];
            En2 = *(const float4*)&Eh[jn + jb0 + 16];
            En3 = *(const float4*)&Eh[jn + jb0 + 24];
        }

        // ---- A fragments: per-row-scaled p as single fp16 ----
        uint32_t ahi[2][4];
        #pragma unroll
        for (int kf = 0; kf < 2; kf++) {
            const float4 eA = kf ? Ec2 : Ec0;
            const float4 eB = kf ? Ec3 : Ec1;
            const uint32_t ma0 = mc0 >> (kf * 16 + t2);
            const uint32_t ma1 = mc1 >> (kf * 16 + t2);

            bool cA0 = (eA.x >= P0.z), cA1 = (eA.z >= P0.z);
            bool cB0 = (eB.x >= P0.z), cB1 = (eB.z >= P0.z);
            float p00 = (ma0 & 1u)   ? (cA0 ? P0.x * eA.x : P0.y * eA.y) : 0.0f;
            float p01 = (ma0 & 2u)   ? (cA1 ? P0.x * eA.z : P0.y * eA.w) : 0.0f;
            float p08 = (ma0 & 256u) ? (cB0 ? P0.x * eB.x : P0.y * eB.y) : 0.0f;
            float p09 = (ma0 & 512u) ? (cB1 ? P0.x * eB.z : P0.y * eB.w) : 0.0f;

            bool dA0 = (eA.x >= P1.z), dA1 = (eA.z >= P1.z);
            bool dB0 = (eB.x >= P1.z), dB1 = (eB.z >= P1.z);
            float p10 = (ma1 & 1u)   ? (dA0 ? P1.x * eA.x : P1.y * eA.y) : 0.0f;
            float p11 = (ma1 & 2u)   ? (dA1 ? P1.x * eA.z : P1.y * eA.w) : 0.0f;
            float p18 = (ma1 & 256u) ? (dB0 ? P1.x * eB.x : P1.y * eB.y) : 0.0f;
            float p19 = (ma1 & 512u) ? (dB1 ? P1.x * eB.z : P1.y * eB.w) : 0.0f;

            den0 += (p00 + p01) + (p08 + p09);
            den1 += (p10 + p11) + (p18 + p19);

            ahi[kf][0] = pack_f16x2(p00, p01);
            ahi[kf][1] = pack_f16x2(p10, p11);
            ahi[kf][2] = pack_f16x2(p08, p09);
            ahi[kf][3] = pack_f16x2(p18, p19);
        }

        // ---- single-term MMAs: acc += A*B ----
        const __half* cbh = (const __half*)(sraw + cur * 9216);
        #pragma unroll
        for (int nf = 0; nf < 8; nf++) {
            const int brow = (nf * 8 + g) * BPAD + half * 32;
            #pragma unroll
            for (int kf = 0; kf < 2; kf++) {
                const int boff = brow + kf * 16 + t2;
                uint32_t bh0 = *(const uint32_t*)&cbh[boff];
                uint32_t bh1 = *(const uint32_t*)&cbh[boff + 8];
                mma_f16(acc[nf], ahi[kf], bh0, bh1);
            }
        }

        if (t < 63) {
            __half* bh = (__half*)(sraw + (1 - cur) * 9216);
            *(uint4*)&bh[pr0 * BPAD + pc0] = nh0;
            *(uint4*)&bh[pr1 * BPAD + pc1] = nh1;
            mc0 = mn0; mc1 = mn1;
            Ec0 = En0; Ec1 = En1; Ec2 = En2; Ec3 = En3;
        }
        __syncthreads();
    }

    // ---- merge halves ----
    den0 += __shfl_xor_sync(0xFFFFFFFFu, den0, 1);
    den0 += __shfl_xor_sync(0xFFFFFFFFu, den0, 2);
    den1 += __shfl_xor_sync(0xFFFFFFFFu, den1, 1);
    den1 += __shfl_xor_sync(0xFFFFFFFFu, den1, 2);

    if (half == 1) {
        if ((lane & 3) == 0) {
            s_dn[wg * 16 + g]     = den0;
            s_dn[wg * 16 + g + 8] = den1;
        }
        #pragma unroll
        for (int nf = 0; nf < 8; nf++) {
            *(float2*)&s_acc[(wg * 16 + g) * 64 + nf * 8 + t2]     = make_float2(acc[nf][0], acc[nf][1]);
            *(float2*)&s_acc[(wg * 16 + g + 8) * 64 + nf * 8 + t2] = make_float2(acc[nf][2], acc[nf][3]);
        }
    }
    __syncthreads();
    if (half == 0) {
        const float inv0 = 1.0f / (den0 + s_dn[wg * 16 + g]);
        const float inv1 = 1.0f / (den1 + s_dn[wg * 16 + g + 8]);
        float* orow0 = out + (size_t)r0 * (NHEADS * DHEAD) + h * DHEAD;
        float* orow1 = out + (size_t)r1 * (NHEADS * DHEAD) + h * DHEAD;
        #pragma unroll
        for (int nf = 0; nf < 8; nf++) {
            float2 x0 = *(const float2*)&s_acc[(wg * 16 + g) * 64 + nf * 8 + t2];
            float2 x1 = *(const float2*)&s_acc[(wg * 16 + g + 8) * 64 + nf * 8 + t2];
            float2 b2 = *(const float2*)&bias[h * DHEAD + nf * 8 + t2];
            float2 o0, o1;
            o0.x = fmaxf(fmaf(acc[nf][0] + x0.x, inv0, b2.x), 0.0f);
            o0.y = fmaxf(fmaf(acc[nf][1] + x0.y, inv0, b2.y), 0.0f);
            o1.x = fmaxf(fmaf(acc[nf][2] + x1.x, inv1, b2.x), 0.0f);
            o1.y = fmaxf(fmaf(acc[nf][3] + x1.y, inv1, b2.y), 0.0f);
            *(float2*)(orow0 + nf * 8 + t2) = o0;
            *(float2*)(orow1 + nf * 8 + t2) = o1;
        }
    }
}

// ---------------- launch ----------------
extern "C" void kernel_launch(void* const* d_in, const int* in_sizes, int n_in,
                              void* d_out, int out_size) {
    const float* x    = (const float*)d_in[0];
    const int*   adj  = (const int*)  d_in[1];
    const float* W    = (const float*)d_in[2];
    const float* a    = (const float*)d_in[3];
    const float* bias = (const float*)d_in[4];
    float* out = (float*)d_out;

    k_init  <<<1, 32>>>();
    k_bits  <<<N_NODES, 256>>>(adj);
    k_xsplit<<<(N_NODES * F_IN) / 1024, 256>>>(x);
    k_wsplit<<<dim3(F_IN / 64, NHEADS), 256>>>(W);
    k_wx_mma<<<dim3(N_NODES / 64, NHEADS), 256>>>();
    k_s     <<<(NHEADS * N_NODES) / 8, 256>>>(a);
    k_trans <<<dim3(64, NHEADS), 256>>>();
    k_prep  <<<NHEADS, 1024>>>();
    k_attn  <<<dim3(N_NODES / 64, NHEADS), 256>>>(bias, out);
}

// round 11
// speedup vs baseline: 4.3110x; 1.0270x over previous
#include <cuda_runtime.h>
#include <cuda_bf16.h>
#include <cuda_fp16.h>
#include <stdint.h>

#define N_NODES 4096
#define F_IN    512
#define NHEADS  4
#define DHEAD   64
#define BPAD    72

// ---------------- device scratch ----------------
__device__ float    g_Wx[NHEADS * N_NODES * DHEAD];
__device__ float    g_ssrc[NHEADS * N_NODES];
__device__ float    g_sdst[NHEADS * N_NODES];
__device__ unsigned g_enc[2 * NHEADS];
__device__ __half   g_WxT[NHEADS * DHEAD * N_NODES];      // fp16 single-term
__device__ __nv_bfloat16 g_xhi[N_NODES * F_IN];
__device__ __nv_bfloat16 g_xlo[N_NODES * F_IN];
__device__ __nv_bfloat16 g_WT_hi[NHEADS * DHEAD * F_IN];
__device__ __nv_bfloat16 g_WT_lo[NHEADS * DHEAD * F_IN];
__device__ float2   g_E[NHEADS * N_NODES];       // {Ej1, Ej2}
__device__ float4   g_P[NHEADS * N_NODES];       // {Pi1', Pi2', Ti, 0} per-row scaled
__device__ uint32_t g_bits[N_NODES * 128];       // adj bitmask, 2MB

// ---------------- helpers ----------------
__device__ __forceinline__ uint32_t pack_bf16x2(float lo, float hi) {
    uint32_t r;
    asm("cvt.rn.bf16x2.f32 %0, %1, %2;" : "=r"(r) : "f"(hi), "f"(lo));
    return r;
}
__device__ __forceinline__ float bf_lo_f(uint32_t w) { return __uint_as_float(w << 16); }
__device__ __forceinline__ float bf_hi_f(uint32_t w) { return __uint_as_float(w & 0xFFFF0000u); }

__device__ __forceinline__ uint32_t pack_f16x2(float lo, float hi) {
    uint32_t r;
    asm("cvt.rn.f16x2.f32 %0, %1, %2;" : "=r"(r) : "f"(hi), "f"(lo));
    return r;
}

__device__ __forceinline__ unsigned fenc(float f) {
    unsigned u = __float_as_uint(f);
    return (u & 0x80000000u) ? ~u : (u | 0x80000000u);
}
__device__ __forceinline__ float fdec(unsigned u) {
    unsigned b = (u & 0x80000000u) ? (u & 0x7FFFFFFFu) : ~u;
    return __uint_as_float(b);
}

__device__ __forceinline__ float fexp(float v) {
    float x = v * 1.4426950408889634f;
    x = fmaxf(x, -126.0f);
    float kf = x + 12582912.0f;
    int   ki = __float_as_int(kf) - 0x4B400000;
    float r  = x - (kf - 12582912.0f);
    float p  = 1.3333558146e-3f;
    p = fmaf(p, r, 9.6181291076e-3f);
    p = fmaf(p, r, 5.5504108664e-2f);
    p = fmaf(p, r, 2.4022650696e-1f);
    p = fmaf(p, r, 6.9314718056e-1f);
    p = fmaf(p, r, 1.0f);
    return __int_as_float(__float_as_int(p) + (ki << 23));
}

__device__ __forceinline__ void mma_bf16(float* c, const uint32_t* a, uint32_t b0, uint32_t b1) {
    asm volatile(
        "mma.sync.aligned.m16n8k16.row.col.f32.bf16.bf16.f32 "
        "{%0,%1,%2,%3}, {%4,%5,%6,%7}, {%8,%9}, {%0,%1,%2,%3};"
        : "+f"(c[0]), "+f"(c[1]), "+f"(c[2]), "+f"(c[3])
        : "r"(a[0]), "r"(a[1]), "r"(a[2]), "r"(a[3]), "r"(b0), "r"(b1));
}
__device__ __forceinline__ void mma_f16(float* c, const uint32_t* a, uint32_t b0, uint32_t b1) {
    asm volatile(
        "mma.sync.aligned.m16n8k16.row.col.f32.f16.f16.f32 "
        "{%0,%1,%2,%3}, {%4,%5,%6,%7}, {%8,%9}, {%0,%1,%2,%3};"
        : "+f"(c[0]), "+f"(c[1]), "+f"(c[2]), "+f"(c[3])
        : "r"(a[0]), "r"(a[1]), "r"(a[2]), "r"(a[3]), "r"(b0), "r"(b1));
}

// ---------------- kernel 0 ----------------
__global__ void k_init() {
    int t = threadIdx.x;
    if (t < 2 * NHEADS) g_enc[t] = 0u;
}

// ---------------- adj -> bitmask ----------------
__global__ __launch_bounds__(256) void k_bits(const int* __restrict__ adj) {
    int row = blockIdx.x;
    int wid = threadIdx.x >> 5, lane = threadIdx.x & 31;
    const int* arow = adj + (size_t)row * N_NODES;
    #pragma unroll
    for (int w = 0; w < 16; w++) {
        int word = wid * 16 + w;
        uint32_t m = __ballot_sync(0xFFFFFFFFu, arow[word * 32 + lane] > 0);
        if (lane == 0) g_bits[row * 128 + word] = m;
    }
}

// ---------------- split x into bf16 hi/lo ----------------
__global__ __launch_bounds__(256) void k_xsplit(const float* __restrict__ x) {
    int i = (blockIdx.x * 256 + threadIdx.x) * 4;
    float4 v = *(const float4*)(x + i);
    uint32_t h0 = pack_bf16x2(v.x, v.y);
    uint32_t h1 = pack_bf16x2(v.z, v.w);
    uint32_t l0 = pack_bf16x2(v.x - bf_lo_f(h0), v.y - bf_hi_f(h0));
    uint32_t l1 = pack_bf16x2(v.z - bf_lo_f(h1), v.w - bf_hi_f(h1));
    *(uint2*)(g_xhi + i) = make_uint2(h0, h1);
    *(uint2*)(g_xlo + i) = make_uint2(l0, l1);
}

// ---------------- split+transpose W -> [h][d][k] bf16 hi/lo ----------------
__global__ __launch_bounds__(256) void k_wsplit(const float* __restrict__ W) {
    __shared__ __align__(16) float s[64][65];
    int h = blockIdx.y, k0 = blockIdx.x * 64;
    int tid = threadIdx.x;
    const float* Wh = W + (size_t)h * F_IN * DHEAD;
    #pragma unroll
    for (int k = 0; k < 4; k++) {
        int e = tid + k * 256; int r = e >> 4, c4 = (e & 15) * 4;
        float4 v = *(const float4*)&Wh[(size_t)(k0 + r) * DHEAD + c4];
        s[r][c4 + 0] = v.x; s[r][c4 + 1] = v.y; s[r][c4 + 2] = v.z; s[r][c4 + 3] = v.w;
    }
    __syncthreads();
    int d = tid >> 2, kb = (tid & 3) * 16;
    uint32_t hw[8], lw[8];
    #pragma unroll
    for (int e = 0; e < 8; e++) {
        float f0 = s[kb + e * 2][d], f1 = s[kb + e * 2 + 1][d];
        uint32_t hp = pack_bf16x2(f0, f1);
        hw[e] = hp;
        lw[e] = pack_bf16x2(f0 - bf_lo_f(hp), f1 - bf_hi_f(hp));
    }
    size_t base = ((size_t)h * DHEAD + d) * F_IN + k0 + kb;
    *(uint4*)(g_WT_hi + base)     = make_uint4(hw[0], hw[1], hw[2], hw[3]);
    *(uint4*)(g_WT_hi + base + 8) = make_uint4(hw[4], hw[5], hw[6], hw[7]);
    *(uint4*)(g_WT_lo + base)     = make_uint4(lw[0], lw[1], lw[2], lw[3]);
    *(uint4*)(g_WT_lo + base + 8) = make_uint4(lw[4], lw[5], lw[6], lw[7]);
}

// ---------------- kernel 1: Wx = x @ W per head, split-K HMMA ----------------
__global__ __launch_bounds__(256, 2) void k_wx_mma() {
    __shared__ __align__(16) char swraw[36864 + 256];
    __nv_bfloat16* s_wh = (__nv_bfloat16*)swraw;
    __nv_bfloat16* s_wl = (__nv_bfloat16*)(swraw + 18432);
    float* s_acc = (float*)swraw;

    const int tid = threadIdx.x, wid = tid >> 5, lane = tid & 31;
    const int g = lane >> 2, t2 = (lane & 3) * 2;
    const int wg = wid & 3, half = wid >> 2;
    const int h = blockIdx.y, i0 = blockIdx.x * 64;
    const int r0 = i0 + wg * 16 + g, r1 = r0 + 8;

    const __nv_bfloat16* wth = g_WT_hi + (size_t)h * DHEAD * F_IN;
    const __nv_bfloat16* wtl = g_WT_lo + (size_t)h * DHEAD * F_IN;

    float acc[8][4] = {};
    for (int chunk = 0; chunk < 4; chunk++) {
        const int kc = chunk * 64;
        __syncthreads();
        #pragma unroll
        for (int it = 0; it < 4; it++) {
            int e = tid + it * 256; int r = e >> 3, c = (e & 7) * 8;
            int d = r & 63, ks = (r >> 6) * 256 + kc + c;
            *(uint4*)&s_wh[r * BPAD + c] = *(const uint4*)&wth[(size_t)d * F_IN + ks];
            *(uint4*)&s_wl[r * BPAD + c] = *(const uint4*)&wtl[(size_t)d * F_IN + ks];
        }
        __syncthreads();

        uint32_t ahi[4][4], alo[4][4];
        #pragma unroll
        for (int kf = 0; kf < 4; kf++) {
            int k = half * 256 + kc + kf * 16 + t2;
            ahi[kf][0] = *(const uint32_t*)&g_xhi[(size_t)r0 * F_IN + k];
            ahi[kf][1] = *(const uint32_t*)&g_xhi[(size_t)r1 * F_IN + k];
            ahi[kf][2] = *(const uint32_t*)&g_xhi[(size_t)r0 * F_IN + k + 8];
            ahi[kf][3] = *(const uint32_t*)&g_xhi[(size_t)r1 * F_IN + k + 8];
            alo[kf][0] = *(const uint32_t*)&g_xlo[(size_t)r0 * F_IN + k];
            alo[kf][1] = *(const uint32_t*)&g_xlo[(size_t)r1 * F_IN + k];
            alo[kf][2] = *(const uint32_t*)&g_xlo[(size_t)r0 * F_IN + k + 8];
            alo[kf][3] = *(const uint32_t*)&g_xlo[(size_t)r1 * F_IN + k + 8];
        }
        #pragma unroll
        for (int nf = 0; nf < 8; nf++) {
            const int brow = (half * 64 + nf * 8 + g) * BPAD;
            #pragma unroll
            for (int kf = 0; kf < 4; kf++) {
                const int boff = brow + kf * 16 + t2;
                uint32_t bh0 = *(const uint32_t*)&s_wh[boff];
                uint32_t bh1 = *(const uint32_t*)&s_wh[boff + 8];
                uint32_t bl0 = *(const uint32_t*)&s_wl[boff];
                uint32_t bl1 = *(const uint32_t*)&s_wl[boff + 8];
                mma_bf16(acc[nf], ahi[kf], bh0, bh1);
                mma_bf16(acc[nf], alo[kf], bh0, bh1);
                mma_bf16(acc[nf], ahi[kf], bl0, bl1);
            }
        }
    }

    __syncthreads();
    if (half == 1) {
        #pragma unroll
        for (int nf = 0; nf < 8; nf++) {
            *(float2*)&s_acc[(wg * 16 + g) * 64 + nf * 8 + t2]     = make_float2(acc[nf][0], acc[nf][1]);
            *(float2*)&s_acc[(wg * 16 + g + 8) * 64 + nf * 8 + t2] = make_float2(acc[nf][2], acc[nf][3]);
        }
    }
    __syncthreads();
    if (half == 0) {
        float* o0 = g_Wx + ((size_t)h * N_NODES + r0) * DHEAD;
        float* o1 = g_Wx + ((size_t)h * N_NODES + r1) * DHEAD;
        #pragma unroll
        for (int nf = 0; nf < 8; nf++) {
            float2 x0 = *(const float2*)&s_acc[(wg * 16 + g) * 64 + nf * 8 + t2];
            float2 x1 = *(const float2*)&s_acc[(wg * 16 + g + 8) * 64 + nf * 8 + t2];
            *(float2*)(o0 + nf * 8 + t2) = make_float2(acc[nf][0] + x0.x, acc[nf][1] + x0.y);
            *(float2*)(o1 + nf * 8 + t2) = make_float2(acc[nf][2] + x1.x, acc[nf][3] + x1.y);
        }
    }
}

// ---------------- kernel 2: s_src/s_dst + per-head maxima ----------------
__global__ __launch_bounds__(256) void k_s(const float* __restrict__ a) {
    int warp = threadIdx.x >> 5, lane = threadIdx.x & 31;
    int idx = blockIdx.x * 8 + warp;
    int h = idx >> 12;
    int n = idx & (N_NODES - 1);
    const float* wxr = g_Wx + ((size_t)h * N_NODES + n) * DHEAD;
    float w0 = wxr[lane], w1 = wxr[lane + 32];
    const float* ah = a + h * 2 * DHEAD;
    float ps = w0 * ah[lane]      + w1 * ah[lane + 32];
    float pd = w0 * ah[64 + lane] + w1 * ah[96 + lane];
    #pragma unroll
    for (int o = 16; o; o >>= 1) {
        ps += __shfl_xor_sync(0xFFFFFFFFu, ps, o);
        pd += __shfl_xor_sync(0xFFFFFFFFu, pd, o);
    }
    if (lane == 0) {
        g_ssrc[h * N_NODES + n] = ps;
        g_sdst[h * N_NODES + n] = pd;
        atomicMax(&g_enc[h],          fenc(ps));
        atomicMax(&g_enc[NHEADS + h], fenc(pd));
    }
}

// ---------------- kernel 2b: transpose Wx -> [h][d][n] fp16 ----------------
__global__ __launch_bounds__(256) void k_trans() {
    __shared__ __align__(16) float s[64][65];
    int h = blockIdx.y, n0 = blockIdx.x * 64;
    int tid = threadIdx.x;
    #pragma unroll
    for (int k = 0; k < 4; k++) {
        int e = tid + k * 256; int r = e >> 4, c4 = (e & 15) * 4;
        float4 v = *(const float4*)&g_Wx[((size_t)h * N_NODES + n0 + r) * DHEAD + c4];
        s[r][c4 + 0] = v.x; s[r][c4 + 1] = v.y; s[r][c4 + 2] = v.z; s[r][c4 + 3] = v.w;
    }
    __syncthreads();
    int d = tid >> 2, nb = (tid & 3) * 16;
    uint32_t hw[8];
    #pragma unroll
    for (int e = 0; e < 8; e++) {
        float f0 = s[nb + e * 2][d], f1 = s[nb + e * 2 + 1][d];
        hw[e] = pack_f16x2(f0, f1);
    }
    size_t base = ((size_t)h * DHEAD + d) * N_NODES + n0 + nb;
    *(uint4*)(g_WxT + base)     = make_uint4(hw[0], hw[1], hw[2], hw[3]);
    *(uint4*)(g_WxT + base + 8) = make_uint4(hw[4], hw[5], hw[6], hw[7]);
}

// ---------------- kernel 2c: E/P tables per head (per-row scaled) ----------------
__global__ __launch_bounds__(1024) void k_prep() {
    int h = blockIdx.x, tid = threadIdx.x;
    const float maxsrc = fdec(g_enc[h]);
    const float maxdst = fdec(g_enc[NHEADS + h]);
    const float S  = maxsrc + maxdst;
    const float Mh = fmaxf(S, 0.2f * S);
    const float r_ = Mh - 0.2f * S;
    const float c_ = 0.2f * maxsrc + 0.5f * r_;
    const float d_ = 0.2f * maxdst + 0.5f * r_;
    const float maxE2 = fexp(-0.5f * r_);
    #pragma unroll
    for (int k = 0; k < 4; k++) {
        int j = tid + k * 1024;
        float sj = g_sdst[h * N_NODES + j];
        g_E[h * N_NODES + j] = make_float2(fexp(sj - maxdst), fexp(fmaf(0.2f, sj, -d_)));
        float si = g_ssrc[h * N_NODES + j];
        float Pi1 = fexp(si - maxsrc);
        float Pi2 = fexp(fmaf(0.2f, si, -c_));
        float sc = 1.0f / fmaxf(Pi1, Pi2 * maxE2);
        g_P[h * N_NODES + j] = make_float4(Pi1 * sc, Pi2 * sc, fexp(-si - maxdst), 0.0f);
    }
}

// ---------------- kernel 3: MMA-first overlapped softmax-AV ----------------
// dynamic smem: [Bbuf0 9216 | Bbuf1 9216 | E table 32768] = 51200 B
// epilogue reuses Bbuf region: s_acc 16KB @0, s_dn @16384.
#define SME_E   18432
#define SME_TOT (18432 + 32768)

__global__ __launch_bounds__(256, 2) void k_attn(const float* __restrict__ bias,
                                                 float* __restrict__ out) {
    extern __shared__ __align__(16) char sraw[];
    float* sE    = (float*)(sraw + SME_E);
    float* s_acc = (float*)sraw;
    float* s_dn  = (float*)(sraw + 16384);

    const int tid = threadIdx.x, wid = tid >> 5, lane = tid & 31;
    const int g = lane >> 2, t2 = (lane & 3) * 2;
    const int wg = wid & 3, half = wid >> 2;
    const int h = blockIdx.y, i0 = blockIdx.x * 64;

    const int r0 = i0 + wg * 16 + g, r1 = r0 + 8;
    const float4 P0 = g_P[h * N_NODES + r0];
    const float4 P1 = g_P[h * N_NODES + r1];
    const int jb0 = half * 32 + t2;

    const __half* bp = g_WxT + (size_t)h * DHEAD * N_NODES;

    const int e0 = tid * 2, e1 = tid * 2 + 1;
    const int pr0 = e0 >> 3, pc0 = (e0 & 7) * 8;
    const int pr1 = e1 >> 3, pc1 = (e1 & 7) * 8;

    // ---- stage E table (4096 float2 = 2048 float4) ----
    {
        const float4* src = (const float4*)(g_E + h * N_NODES);
        float4* dst = (float4*)sE;
        #pragma unroll
        for (int k = 0; k < 8; k++) dst[tid + k * 256] = src[tid + k * 256];
    }
    // ---- stage B(0) ----
    {
        __half* bh = (__half*)sraw;
        *(uint4*)&bh[pr0 * BPAD + pc0] = *(const uint4*)(bp + (size_t)pr0 * N_NODES + pc0);
        *(uint4*)&bh[pr1 * BPAD + pc1] = *(const uint4*)(bp + (size_t)pr1 * N_NODES + pc1);
    }
    uint32_t mn0 = g_bits[r0 * 128 + half];          // bits(0)
    uint32_t mn1 = g_bits[r1 * 128 + half];
    __syncthreads();                                  // E + B(0) visible

    uint32_t aF[2][2][4];
    float den0 = 0.0f, den1 = 0.0f;

    // ---- pgen for tile jt into aF[buf] from smem E + bits (mn0/mn1) ----
    #define PGEN(jt, buf)                                                          \
    do {                                                                           \
        const int _j = (jt) * 64;                                                  \
        float4 EA0 = *(const float4*)&sE[(_j + jb0) * 2];                          \
        float4 EB0 = *(const float4*)&sE[(_j + jb0 + 8) * 2];                      \
        float4 EA1 = *(const float4*)&sE[(_j + jb0 + 16) * 2];                     \
        float4 EB1 = *(const float4*)&sE[(_j + jb0 + 24) * 2];                     \
        _Pragma("unroll")                                                          \
        for (int kf = 0; kf < 2; kf++) {                                           \
            const float4 eA = kf ? EA1 : EA0;                                      \
            const float4 eB = kf ? EB1 : EB0;                                      \
            const uint32_t ma0 = mn0 >> (kf * 16 + t2);                            \
            const uint32_t ma1 = mn1 >> (kf * 16 + t2);                            \
            bool cA0 = (eA.x >= P0.z), cA1 = (eA.z >= P0.z);                       \
            bool cB0 = (eB.x >= P0.z), cB1 = (eB.z >= P0.z);                       \
            float p00 = (ma0 & 1u)   ? (cA0 ? P0.x * eA.x : P0.y * eA.y) : 0.0f;   \
            float p01 = (ma0 & 2u)   ? (cA1 ? P0.x * eA.z : P0.y * eA.w) : 0.0f;   \
            float p08 = (ma0 & 256u) ? (cB0 ? P0.x * eB.x : P0.y * eB.y) : 0.0f;   \
            float p09 = (ma0 & 512u) ? (cB1 ? P0.x * eB.z : P0.y * eB.w) : 0.0f;   \
            bool dA0 = (eA.x >= P1.z), dA1 = (eA.z >= P1.z);                       \
            bool dB0 = (eB.x >= P1.z), dB1 = (eB.z >= P1.z);                       \
            float p10 = (ma1 & 1u)   ? (dA0 ? P1.x * eA.x : P1.y * eA.y) : 0.0f;   \
            float p11 = (ma1 & 2u)   ? (dA1 ? P1.x * eA.z : P1.y * eA.w) : 0.0f;   \
            float p18 = (ma1 & 256u) ? (dB0 ? P1.x * eB.x : P1.y * eB.y) : 0.0f;   \
            float p19 = (ma1 & 512u) ? (dB1 ? P1.x * eB.z : P1.y * eB.w) : 0.0f;   \
            den0 += (p00 + p01) + (p08 + p09);                                     \
            den1 += (p10 + p11) + (p18 + p19);                                     \
            aF[buf][kf][0] = pack_f16x2(p00, p01);                                 \
            aF[buf][kf][1] = pack_f16x2(p10, p11);                                 \
            aF[buf][kf][2] = pack_f16x2(p08, p09);                                 \
            aF[buf][kf][3] = pack_f16x2(p18, p19);                                 \
        }                                                                          \
    } while (0)

    PGEN(0, 0);                                       // A(0)

    // prefetch bits(1) + B(1)
    mn0 = g_bits[r0 * 128 + 2 + half];
    mn1 = g_bits[r1 * 128 + 2 + half];
    uint4 nh0 = *(const uint4*)(bp + (size_t)pr0 * N_NODES + 64 + pc0);
    uint4 nh1 = *(const uint4*)(bp + (size_t)pr1 * N_NODES + 64 + pc1);

    float acc[8][4] = {};

    #pragma unroll 2
    for (int t = 0; t < 64; t++) {
        const int cur = t & 1;

        // ---- MMA(t): issue first so tensor pipe overlaps the pgen below ----
        const __half* cbh = (const __half*)(sraw + cur * 9216);
        #pragma unroll
        for (int nf = 0; nf < 8; nf++) {
            const int brow = (nf * 8 + g) * BPAD + half * 32;
            #pragma unroll
            for (int kf = 0; kf < 2; kf++) {
                const int boff = brow + kf * 16 + t2;
                uint32_t bh0 = *(const uint32_t*)&cbh[boff];
                uint32_t bh1 = *(const uint32_t*)&cbh[boff + 8];
                mma_f16(acc[nf], aF[cur][kf], bh0, bh1);
            }
        }

        if (t < 63) {
            // ---- pgen A(t+1) (independent of MMA above; fills issue slots) ----
            PGEN(t + 1, 1 - cur);
            // ---- stage B(t+1) into other buffer ----
            __half* bh = (__half*)(sraw + (1 - cur) * 9216);
            *(uint4*)&bh[pr0 * BPAD + pc0] = nh0;
            *(uint4*)&bh[pr1 * BPAD + pc1] = nh1;
            if (t < 62) {
                const int jn2 = (t + 2) * 64;
                mn0 = g_bits[r0 * 128 + (t + 2) * 2 + half];
                mn1 = g_bits[r1 * 128 + (t + 2) * 2 + half];
                nh0 = *(const uint4*)(bp + (size_t)pr0 * N_NODES + jn2 + pc0);
                nh1 = *(const uint4*)(bp + (size_t)pr1 * N_NODES + jn2 + pc1);
            }
        }
        __syncthreads();
    }
    #undef PGEN

    // ---- merge halves ----
    den0 += __shfl_xor_sync(0xFFFFFFFFu, den0, 1);
    den0 += __shfl_xor_sync(0xFFFFFFFFu, den0, 2);
    den1 += __shfl_xor_sync(0xFFFFFFFFu, den1, 1);
    den1 += __shfl_xor_sync(0xFFFFFFFFu, den1, 2);

    if (half == 1) {
        if ((lane & 3) == 0) {
            s_dn[wg * 16 + g]     = den0;
            s_dn[wg * 16 + g + 8] = den1;
        }
        #pragma unroll
        for (int nf = 0; nf < 8; nf++) {
            *(float2*)&s_acc[(wg * 16 + g) * 64 + nf * 8 + t2]     = make_float2(acc[nf][0], acc[nf][1]);
            *(float2*)&s_acc[(wg * 16 + g + 8) * 64 + nf * 8 + t2] = make_float2(acc[nf][2], acc[nf][3]);
        }
    }
    __syncthreads();
    if (half == 0) {
        const float inv0 = 1.0f / (den0 + s_dn[wg * 16 + g]);
        const float inv1 = 1.0f / (den1 + s_dn[wg * 16 + g + 8]);
        float* orow0 = out + (size_t)r0 * (NHEADS * DHEAD) + h * DHEAD;
        float* orow1 = out + (size_t)r1 * (NHEADS * DHEAD) + h * DHEAD;
        #pragma unroll
        for (int nf = 0; nf < 8; nf++) {
            float2 x0 = *(const float2*)&s_acc[(wg * 16 + g) * 64 + nf * 8 + t2];
            float2 x1 = *(const float2*)&s_acc[(wg * 16 + g + 8) * 64 + nf * 8 + t2];
            float2 b2 = *(const float2*)&bias[h * DHEAD + nf * 8 + t2];
            float2 o0, o1;
            o0.x = fmaxf(fmaf(acc[nf][0] + x0.x, inv0, b2.x), 0.0f);
            o0.y = fmaxf(fmaf(acc[nf][1] + x0.y, inv0, b2.y), 0.0f);
            o1.x = fmaxf(fmaf(acc[nf][2] + x1.x, inv1, b2.x), 0.0f);
            o1.y = fmaxf(fmaf(acc[nf][3] + x1.y, inv1, b2.y), 0.0f);
            *(float2*)(orow0 + nf * 8 + t2) = o0;
            *(float2*)(orow1 + nf * 8 + t2) = o1;
        }
    }
}

// ---------------- launch ----------------
extern "C" void kernel_launch(void* const* d_in, const int* in_sizes, int n_in,
                              void* d_out, int out_size) {
    const float* x    = (const float*)d_in[0];
    const int*   adj  = (const int*)  d_in[1];
    const float* W    = (const float*)d_in[2];
    const float* a    = (const float*)d_in[3];
    const float* bias = (const float*)d_in[4];
    float* out = (float*)d_out;

    cudaFuncSetAttribute(k_attn, cudaFuncAttributeMaxDynamicSharedMemorySize, SME_TOT);

    k_init  <<<1, 32>>>();
    k_bits  <<<N_NODES, 256>>>(adj);
    k_xsplit<<<(N_NODES * F_IN) / 1024, 256>>>(x);
    k_wsplit<<<dim3(F_IN / 64, NHEADS), 256>>>(W);
    k_wx_mma<<<dim3(N_NODES / 64, NHEADS), 256>>>();
    k_s     <<<(NHEADS * N_NODES) / 8, 256>>>(a);
    k_trans <<<dim3(64, NHEADS), 256>>>();
    k_prep  <<<NHEADS, 1024>>>();
    k_attn  <<<dim3(N_NODES / 64, NHEADS), 256, SME_TOT>>>(bias, out);
}

// round 12
// speedup vs baseline: 5.5019x; 1.2762x over previous
#include <cuda_runtime.h>
#include <cuda_bf16.h>
#include <cuda_fp16.h>
#include <stdint.h>

#define N_NODES 4096
#define F_IN    512
#define NHEADS  4
#define DHEAD   64
#define BPAD    72

// ---------------- device scratch ----------------
__device__ float    g_Wx[NHEADS * N_NODES * DHEAD];
__device__ float    g_ssrc[NHEADS * N_NODES];
__device__ float    g_sdst[NHEADS * N_NODES];
__device__ unsigned g_enc[2 * NHEADS];
__device__ __half   g_WxT[NHEADS * DHEAD * N_NODES];      // fp16 single-term
__device__ __nv_bfloat16 g_xhi[N_NODES * F_IN];
__device__ __nv_bfloat16 g_xlo[N_NODES * F_IN];
__device__ __nv_bfloat16 g_WT_hi[NHEADS * DHEAD * F_IN];
__device__ __nv_bfloat16 g_WT_lo[NHEADS * DHEAD * F_IN];
__device__ float2   g_E[NHEADS * N_NODES];       // {Ej1, Ej2}
__device__ float4   g_P[NHEADS * N_NODES];       // {Pi1', Pi2', -, -} per-row scaled
__device__ uint32_t g_bits[N_NODES * 128];       // adj bitmask, 2MB

// ---------------- helpers ----------------
__device__ __forceinline__ uint32_t pack_bf16x2(float lo, float hi) {
    uint32_t r;
    asm("cvt.rn.bf16x2.f32 %0, %1, %2;" : "=r"(r) : "f"(hi), "f"(lo));
    return r;
}
__device__ __forceinline__ float bf_lo_f(uint32_t w) { return __uint_as_float(w << 16); }
__device__ __forceinline__ float bf_hi_f(uint32_t w) { return __uint_as_float(w & 0xFFFF0000u); }

__device__ __forceinline__ uint32_t pack_f16x2(float lo, float hi) {
    uint32_t r;
    asm("cvt.rn.f16x2.f32 %0, %1, %2;" : "=r"(r) : "f"(hi), "f"(lo));
    return r;
}

__device__ __forceinline__ unsigned fenc(float f) {
    unsigned u = __float_as_uint(f);
    return (u & 0x80000000u) ? ~u : (u | 0x80000000u);
}
__device__ __forceinline__ float fdec(unsigned u) {
    unsigned b = (u & 0x80000000u) ? (u & 0x7FFFFFFFu) : ~u;
    return __uint_as_float(b);
}

__device__ __forceinline__ uint32_t smem_u32(const void* p) {
    uint32_t a;
    asm("{ .reg .u64 t; cvta.to.shared.u64 t, %1; cvt.u32.u64 %0, t; }" : "=r"(a) : "l"(p));
    return a;
}

__device__ __forceinline__ float fexp(float v) {
    float x = v * 1.4426950408889634f;
    x = fmaxf(x, -126.0f);
    float kf = x + 12582912.0f;
    int   ki = __float_as_int(kf) - 0x4B400000;
    float r  = x - (kf - 12582912.0f);
    float p  = 1.3333558146e-3f;
    p = fmaf(p, r, 9.6181291076e-3f);
    p = fmaf(p, r, 5.5504108664e-2f);
    p = fmaf(p, r, 2.4022650696e-1f);
    p = fmaf(p, r, 6.9314718056e-1f);
    p = fmaf(p, r, 1.0f);
    return __int_as_float(__float_as_int(p) + (ki << 23));
}

__device__ __forceinline__ void mma_bf16(float* c, const uint32_t* a, uint32_t b0, uint32_t b1) {
    asm volatile(
        "mma.sync.aligned.m16n8k16.row.col.f32.bf16.bf16.f32 "
        "{%0,%1,%2,%3}, {%4,%5,%6,%7}, {%8,%9}, {%0,%1,%2,%3};"
        : "+f"(c[0]), "+f"(c[1]), "+f"(c[2]), "+f"(c[3])
        : "r"(a[0]), "r"(a[1]), "r"(a[2]), "r"(a[3]), "r"(b0), "r"(b1));
}
__device__ __forceinline__ void mma_f16(float* c, const uint32_t* a, uint32_t b0, uint32_t b1) {
    asm volatile(
        "mma.sync.aligned.m16n8k16.row.col.f32.f16.f16.f32 "
        "{%0,%1,%2,%3}, {%4,%5,%6,%7}, {%8,%9}, {%0,%1,%2,%3};"
        : "+f"(c[0]), "+f"(c[1]), "+f"(c[2]), "+f"(c[3])
        : "r"(a[0]), "r"(a[1]), "r"(a[2]), "r"(a[3]), "r"(b0), "r"(b1));
}
__device__ __forceinline__ void ldsm_x4(uint32_t& r0, uint32_t& r1, uint32_t& r2, uint32_t& r3,
                                        uint32_t addr) {
    asm volatile("ldmatrix.sync.aligned.m8n8.x4.shared.b16 {%0,%1,%2,%3}, [%4];"
                 : "=r"(r0), "=r"(r1), "=r"(r2), "=r"(r3) : "r"(addr));
}

// ---------------- kernel 0 ----------------
__global__ void k_init() {
    int t = threadIdx.x;
    if (t < 2 * NHEADS) g_enc[t] = 0u;
}

// ---------------- adj -> bitmask ----------------
__global__ __launch_bounds__(256) void k_bits(const int* __restrict__ adj) {
    int row = blockIdx.x;
    int wid = threadIdx.x >> 5, lane = threadIdx.x & 31;
    const int* arow = adj + (size_t)row * N_NODES;
    #pragma unroll
    for (int w = 0; w < 16; w++) {
        int word = wid * 16 + w;
        uint32_t m = __ballot_sync(0xFFFFFFFFu, arow[word * 32 + lane] > 0);
        if (lane == 0) g_bits[row * 128 + word] = m;
    }
}

// ---------------- split x into bf16 hi/lo ----------------
__global__ __launch_bounds__(256) void k_xsplit(const float* __restrict__ x) {
    int i = (blockIdx.x * 256 + threadIdx.x) * 4;
    float4 v = *(const float4*)(x + i);
    uint32_t h0 = pack_bf16x2(v.x, v.y);
    uint32_t h1 = pack_bf16x2(v.z, v.w);
    uint32_t l0 = pack_bf16x2(v.x - bf_lo_f(h0), v.y - bf_hi_f(h0));
    uint32_t l1 = pack_bf16x2(v.z - bf_lo_f(h1), v.w - bf_hi_f(h1));
    *(uint2*)(g_xhi + i) = make_uint2(h0, h1);
    *(uint2*)(g_xlo + i) = make_uint2(l0, l1);
}

// ---------------- split+transpose W -> [h][d][k] bf16 hi/lo ----------------
__global__ __launch_bounds__(256) void k_wsplit(const float* __restrict__ W) {
    __shared__ __align__(16) float s[64][65];
    int h = blockIdx.y, k0 = blockIdx.x * 64;
    int tid = threadIdx.x;
    const float* Wh = W + (size_t)h * F_IN * DHEAD;
    #pragma unroll
    for (int k = 0; k < 4; k++) {
        int e = tid + k * 256; int r = e >> 4, c4 = (e & 15) * 4;
        float4 v = *(const float4*)&Wh[(size_t)(k0 + r) * DHEAD + c4];
        s[r][c4 + 0] = v.x; s[r][c4 + 1] = v.y; s[r][c4 + 2] = v.z; s[r][c4 + 3] = v.w;
    }
    __syncthreads();
    int d = tid >> 2, kb = (tid & 3) * 16;
    uint32_t hw[8], lw[8];
    #pragma unroll
    for (int e = 0; e < 8; e++) {
        float f0 = s[kb + e * 2][d], f1 = s[kb + e * 2 + 1][d];
        uint32_t hp = pack_bf16x2(f0, f1);
        hw[e] = hp;
        lw[e] = pack_bf16x2(f0 - bf_lo_f(hp), f1 - bf_hi_f(hp));
    }
    size_t base = ((size_t)h * DHEAD + d) * F_IN + k0 + kb;
    *(uint4*)(g_WT_hi + base)     = make_uint4(hw[0], hw[1], hw[2], hw[3]);
    *(uint4*)(g_WT_hi + base + 8) = make_uint4(hw[4], hw[5], hw[6], hw[7]);
    *(uint4*)(g_WT_lo + base)     = make_uint4(lw[0], lw[1], lw[2], lw[3]);
    *(uint4*)(g_WT_lo + base + 8) = make_uint4(lw[4], lw[5], lw[6], lw[7]);
}

// ---------------- kernel 1: Wx = x @ W per head, split-K HMMA ----------------
__global__ __launch_bounds__(256, 2) void k_wx_mma() {
    __shared__ __align__(16) char swraw[36864 + 256];
    __nv_bfloat16* s_wh = (__nv_bfloat16*)swraw;
    __nv_bfloat16* s_wl = (__nv_bfloat16*)(swraw + 18432);
    float* s_acc = (float*)swraw;

    const int tid = threadIdx.x, wid = tid >> 5, lane = tid & 31;
    const int g = lane >> 2, t2 = (lane & 3) * 2;
    const int wg = wid & 3, half = wid >> 2;
    const int h = blockIdx.y, i0 = blockIdx.x * 64;
    const int r0 = i0 + wg * 16 + g, r1 = r0 + 8;

    const __nv_bfloat16* wth = g_WT_hi + (size_t)h * DHEAD * F_IN;
    const __nv_bfloat16* wtl = g_WT_lo + (size_t)h * DHEAD * F_IN;

    float acc[8][4] = {};
    for (int chunk = 0; chunk < 4; chunk++) {
        const int kc = chunk * 64;
        __syncthreads();
        #pragma unroll
        for (int it = 0; it < 4; it++) {
            int e = tid + it * 256; int r = e >> 3, c = (e & 7) * 8;
            int d = r & 63, ks = (r >> 6) * 256 + kc + c;
            *(uint4*)&s_wh[r * BPAD + c] = *(const uint4*)&wth[(size_t)d * F_IN + ks];
            *(uint4*)&s_wl[r * BPAD + c] = *(const uint4*)&wtl[(size_t)d * F_IN + ks];
        }
        __syncthreads();

        uint32_t ahi[4][4], alo[4][4];
        #pragma unroll
        for (int kf = 0; kf < 4; kf++) {
            int k = half * 256 + kc + kf * 16 + t2;
            ahi[kf][0] = *(const uint32_t*)&g_xhi[(size_t)r0 * F_IN + k];
            ahi[kf][1] = *(const uint32_t*)&g_xhi[(size_t)r1 * F_IN + k];
            ahi[kf][2] = *(const uint32_t*)&g_xhi[(size_t)r0 * F_IN + k + 8];
            ahi[kf][3] = *(const uint32_t*)&g_xhi[(size_t)r1 * F_IN + k + 8];
            alo[kf][0] = *(const uint32_t*)&g_xlo[(size_t)r0 * F_IN + k];
            alo[kf][1] = *(const uint32_t*)&g_xlo[(size_t)r1 * F_IN + k];
            alo[kf][2] = *(const uint32_t*)&g_xlo[(size_t)r0 * F_IN + k + 8];
            alo[kf][3] = *(const uint32_t*)&g_xlo[(size_t)r1 * F_IN + k + 8];
        }
        #pragma unroll
        for (int nf = 0; nf < 8; nf++) {
            const int brow = (half * 64 + nf * 8 + g) * BPAD;
            #pragma unroll
            for (int kf = 0; kf < 4; kf++) {
                const int boff = brow + kf * 16 + t2;
                uint32_t bh0 = *(const uint32_t*)&s_wh[boff];
                uint32_t bh1 = *(const uint32_t*)&s_wh[boff + 8];
                uint32_t bl0 = *(const uint32_t*)&s_wl[boff];
                uint32_t bl1 = *(const uint32_t*)&s_wl[boff + 8];
                mma_bf16(acc[nf], ahi[kf], bh0, bh1);
                mma_bf16(acc[nf], alo[kf], bh0, bh1);
                mma_bf16(acc[nf], ahi[kf], bl0, bl1);
            }
        }
    }

    __syncthreads();
    if (half == 1) {
        #pragma unroll
        for (int nf = 0; nf < 8; nf++) {
            *(float2*)&s_acc[(wg * 16 + g) * 64 + nf * 8 + t2]     = make_float2(acc[nf][0], acc[nf][1]);
            *(float2*)&s_acc[(wg * 16 + g + 8) * 64 + nf * 8 + t2] = make_float2(acc[nf][2], acc[nf][3]);
        }
    }
    __syncthreads();
    if (half == 0) {
        float* o0 = g_Wx + ((size_t)h * N_NODES + r0) * DHEAD;
        float* o1 = g_Wx + ((size_t)h * N_NODES + r1) * DHEAD;
        #pragma unroll
        for (int nf = 0; nf < 8; nf++) {
            float2 x0 = *(const float2*)&s_acc[(wg * 16 + g) * 64 + nf * 8 + t2];
            float2 x1 = *(const float2*)&s_acc[(wg * 16 + g + 8) * 64 + nf * 8 + t2];
            *(float2*)(o0 + nf * 8 + t2) = make_float2(acc[nf][0] + x0.x, acc[nf][1] + x0.y);
            *(float2*)(o1 + nf * 8 + t2) = make_float2(acc[nf][2] + x1.x, acc[nf][3] + x1.y);
        }
    }
}

// ---------------- kernel 2b: transpose Wx -> fp16 [h][d][n] + s_src/s_dst + maxima ----------------
__global__ __launch_bounds__(256) void k_trans(const float* __restrict__ a) {
    __shared__ __align__(16) float s[64][65];
    int h = blockIdx.y, n0 = blockIdx.x * 64;
    int tid = threadIdx.x, lane = tid & 31;
    #pragma unroll
    for (int k = 0; k < 4; k++) {
        int e = tid + k * 256; int r = e >> 4, c4 = (e & 15) * 4;
        float4 v = *(const float4*)&g_Wx[((size_t)h * N_NODES + n0 + r) * DHEAD + c4];
        s[r][c4 + 0] = v.x; s[r][c4 + 1] = v.y; s[r][c4 + 2] = v.z; s[r][c4 + 3] = v.w;
    }
    __syncthreads();
    // transpose + fp16 pack
    {
        int d = tid >> 2, nb = (tid & 3) * 16;
        uint32_t hw[8];
        #pragma unroll
        for (int e = 0; e < 8; e++) {
            float f0 = s[nb + e * 2][d], f1 = s[nb + e * 2 + 1][d];
            hw[e] = pack_f16x2(f0, f1);
        }
        size_t base = ((size_t)h * DHEAD + d) * N_NODES + n0 + nb;
        *(uint4*)(g_WxT + base)     = make_uint4(hw[0], hw[1], hw[2], hw[3]);
        *(uint4*)(g_WxT + base + 8) = make_uint4(hw[4], hw[5], hw[6], hw[7]);
    }
    // per-row s_src/s_dst (4 threads per row, 16 d each)
    {
        int row = tid >> 2, tg = tid & 3;
        const float* a1 = a + h * 2 * DHEAD;
        const float* a2 = a1 + DHEAD;
        float ps = 0.0f, pd = 0.0f;
        #pragma unroll
        for (int d = tg * 16; d < tg * 16 + 16; d++) {
            float w = s[row][d];
            ps = fmaf(w, a1[d], ps);
            pd = fmaf(w, a2[d], pd);
        }
        ps += __shfl_xor_sync(0xFFFFFFFFu, ps, 1);
        ps += __shfl_xor_sync(0xFFFFFFFFu, ps, 2);
        pd += __shfl_xor_sync(0xFFFFFFFFu, pd, 1);
        pd += __shfl_xor_sync(0xFFFFFFFFu, pd, 2);
        if (tg == 0) {
            g_ssrc[h * N_NODES + n0 + row] = ps;
            g_sdst[h * N_NODES + n0 + row] = pd;
            atomicMax(&g_enc[h],          fenc(ps));
            atomicMax(&g_enc[NHEADS + h], fenc(pd));
        }
    }
}

// ---------------- kernel 2c: E/P tables per head (per-row scaled) ----------------
__global__ __launch_bounds__(1024) void k_prep() {
    int h = blockIdx.x, tid = threadIdx.x;
    const float maxsrc = fdec(g_enc[h]);
    const float maxdst = fdec(g_enc[NHEADS + h]);
    const float S  = maxsrc + maxdst;
    const float Mh = fmaxf(S, 0.2f * S);
    const float r_ = Mh - 0.2f * S;
    const float c_ = 0.2f * maxsrc + 0.5f * r_;
    const float d_ = 0.2f * maxdst + 0.5f * r_;
    const float maxE2 = fexp(-0.5f * r_);
    #pragma unroll
    for (int k = 0; k < 4; k++) {
        int j = tid + k * 1024;
        float sj = g_sdst[h * N_NODES + j];
        g_E[h * N_NODES + j] = make_float2(fexp(sj - maxdst), fexp(fmaf(0.2f, sj, -d_)));
        float si = g_ssrc[h * N_NODES + j];
        float Pi1 = fexp(si - maxsrc);
        float Pi2 = fexp(fmaf(0.2f, si, -c_));
        float sc = 1.0f / fmaxf(Pi1, Pi2 * maxE2);
        g_P[h * N_NODES + j] = make_float4(Pi1 * sc, Pi2 * sc, 0.0f, 0.0f);
    }
}

// ---------------- kernel 3: staggered MMA/pgen overlap, ldmatrix B, max-trick p ----------------
#define SME_E   18432
#define SME_TOT (18432 + 32768)

__global__ __launch_bounds__(256, 2) void k_attn(const float* __restrict__ bias,
                                                 float* __restrict__ out) {
    extern __shared__ __align__(16) char sraw[];
    float* sE    = (float*)(sraw + SME_E);
    float* s_acc = (float*)sraw;
    float* s_dn  = (float*)(sraw + 16384);

    const int tid = threadIdx.x, wid = tid >> 5, lane = tid & 31;
    const int g = lane >> 2, t2 = (lane & 3) * 2;
    const int wg = wid & 3, half = wid >> 2;
    const int h = blockIdx.y, i0 = blockIdx.x * 64;

    const int r0 = i0 + wg * 16 + g, r1 = r0 + 8;
    const float4 P0 = g_P[h * N_NODES + r0];
    const float4 P1 = g_P[h * N_NODES + r1];
    const int jb0 = half * 32 + t2;

    const __half* bp = g_WxT + (size_t)h * DHEAD * N_NODES;

    const int e0 = tid * 2, e1 = tid * 2 + 1;
    const int pr0 = e0 >> 3, pc0 = (e0 & 7) * 8;
    const int pr1 = e1 >> 3, pc1 = (e1 & 7) * 8;

    // ldmatrix per-lane address base
    const uint32_t sb32 = smem_u32(sraw);
    const int mi = lane >> 3, ri = lane & 7;
    const uint32_t ldsm_lane =
        sb32 + (uint32_t)((((mi >> 1) * 8 + ri) * BPAD) * 2 + (mi & 1) * 16 + half * 64);

    // ---- stage E table ----
    {
        const float4* src = (const float4*)(g_E + h * N_NODES);
        float4* dst = (float4*)sE;
        #pragma unroll
        for (int k = 0; k < 8; k++) dst[tid + k * 256] = src[tid + k * 256];
    }
    // ---- stage B(0) ----
    {
        __half* bh = (__half*)sraw;
        *(uint4*)&bh[pr0 * BPAD + pc0] = *(const uint4*)(bp + (size_t)pr0 * N_NODES + pc0);
        *(uint4*)&bh[pr1 * BPAD + pc1] = *(const uint4*)(bp + (size_t)pr1 * N_NODES + pc1);
    }
    uint32_t mn0 = g_bits[r0 * 128 + half];
    uint32_t mn1 = g_bits[r1 * 128 + half];
    __syncthreads();

    uint32_t aF[2][2][4];
    float den0 = 0.0f, den1 = 0.0f;

    // p = mask ? max(P1*E1, P2*E2) : 0   (exact: exp monotone over leaky branches)
    #define PGEN(jt, buf)                                                          \
    do {                                                                           \
        const int _j = (jt) * 64;                                                  \
        float4 EA0 = *(const float4*)&sE[(_j + jb0) * 2];                          \
        float4 EB0 = *(const float4*)&sE[(_j + jb0 + 8) * 2];                      \
        float4 EA1 = *(const float4*)&sE[(_j + jb0 + 16) * 2];                     \
        float4 EB1 = *(const float4*)&sE[(_j + jb0 + 24) * 2];                     \
        _Pragma("unroll")                                                          \
        for (int kf = 0; kf < 2; kf++) {                                           \
            const float4 eA = kf ? EA1 : EA0;                                      \
            const float4 eB = kf ? EB1 : EB0;                                      \
            const uint32_t ma0 = mn0 >> (kf * 16 + t2);                            \
            const uint32_t ma1 = mn1 >> (kf * 16 + t2);                            \
            float p00 = (ma0 & 1u)   ? fmaxf(P0.x * eA.x, P0.y * eA.y) : 0.0f;     \
            float p01 = (ma0 & 2u)   ? fmaxf(P0.x * eA.z, P0.y * eA.w) : 0.0f;     \
            float p08 = (ma0 & 256u) ? fmaxf(P0.x * eB.x, P0.y * eB.y) : 0.0f;     \
            float p09 = (ma0 & 512u) ? fmaxf(P0.x * eB.z, P0.y * eB.w) : 0.0f;     \
            float p10 = (ma1 & 1u)   ? fmaxf(P1.x * eA.x, P1.y * eA.y) : 0.0f;     \
            float p11 = (ma1 & 2u)   ? fmaxf(P1.x * eA.z, P1.y * eA.w) : 0.0f;     \
            float p18 = (ma1 & 256u) ? fmaxf(P1.x * eB.x, P1.y * eB.y) : 0.0f;     \
            float p19 = (ma1 & 512u) ? fmaxf(P1.x * eB.z, P1.y * eB.w) : 0.0f;     \
            den0 += (p00 + p01) + (p08 + p09);                                     \
            den1 += (p10 + p11) + (p18 + p19);                                     \
            aF[buf][kf][0] = pack_f16x2(p00, p01);                                 \
            aF[buf][kf][1] = pack_f16x2(p10, p11);                                 \
            aF[buf][kf][2] = pack_f16x2(p08, p09);                                 \
            aF[buf][kf][3] = pack_f16x2(p18, p19);                                 \
        }                                                                          \
    } while (0)

    #define MMA_BLOCK(cur)                                                         \
    do {                                                                           \
        const uint32_t bbase = ldsm_lane + (cur) * 9216u;                          \
        _Pragma("unroll")                                                          \
        for (int nfp = 0; nfp < 4; nfp++) {                                        \
            _Pragma("unroll")                                                      \
            for (int kf = 0; kf < 2; kf++) {                                       \
                uint32_t b0, b1, b2, b3;                                           \
                ldsm_x4(b0, b1, b2, b3, bbase + nfp * 2304u + kf * 32u);           \
                mma_f16(acc[2 * nfp],     aF[cur][kf], b0, b1);                    \
                mma_f16(acc[2 * nfp + 1], aF[cur][kf], b2, b3);                    \
            }                                                                      \
        }                                                                          \
    } while (0)

    PGEN(0, 0);

    // prefetch bits(1) + B(1)
    mn0 = g_bits[r0 * 128 + 2 + half];
    mn1 = g_bits[r1 * 128 + 2 + half];
    uint4 nh0 = *(const uint4*)(bp + (size_t)pr0 * N_NODES + 64 + pc0);
    uint4 nh1 = *(const uint4*)(bp + (size_t)pr1 * N_NODES + 64 + pc1);

    float acc[8][4] = {};

    for (int t = 0; t < 64; t++) {
        const int cur = t & 1;

        if (half == 0) {
            MMA_BLOCK(cur);
            if (t < 63) PGEN(t + 1, 1 - cur);
        } else {
            if (t < 63) PGEN(t + 1, 1 - cur);
            MMA_BLOCK(cur);
        }

        if (t < 63) {
            __half* bh = (__half*)(sraw + (1 - cur) * 9216);
            *(uint4*)&bh[pr0 * BPAD + pc0] = nh0;
            *(uint4*)&bh[pr1 * BPAD + pc1] = nh1;
            if (t < 62) {
                const int jn2 = (t + 2) * 64;
                mn0 = g_bits[r0 * 128 + (t + 2) * 2 + half];
                mn1 = g_bits[r1 * 128 + (t + 2) * 2 + half];
                nh0 = *(const uint4*)(bp + (size_t)pr0 * N_NODES + jn2 + pc0);
                nh1 = *(const uint4*)(bp + (size_t)pr1 * N_NODES + jn2 + pc1);
            }
        }
        __syncthreads();
    }
    #undef PGEN
    #undef MMA_BLOCK

    // ---- merge halves ----
    den0 += __shfl_xor_sync(0xFFFFFFFFu, den0, 1);
    den0 += __shfl_xor_sync(0xFFFFFFFFu, den0, 2);
    den1 += __shfl_xor_sync(0xFFFFFFFFu, den1, 1);
    den1 += __shfl_xor_sync(0xFFFFFFFFu, den1, 2);

    if (half == 1) {
        if ((lane & 3) == 0) {
            s_dn[wg * 16 + g]     = den0;
            s_dn[wg * 16 + g + 8] = den1;
        }
        #pragma unroll
        for (int nf = 0; nf < 8; nf++) {
            *(float2*)&s_acc[(wg * 16 + g) * 64 + nf * 8 + t2]     = make_float2(acc[nf][0], acc[nf][1]);
            *(float2*)&s_acc[(wg * 16 + g + 8) * 64 + nf * 8 + t2] = make_float2(acc[nf][2], acc[nf][3]);
        }
    }
    __syncthreads();
    if (half == 0) {
        const float inv0 = 1.0f / (den0 + s_dn[wg * 16 + g]);
        const float inv1 = 1.0f / (den1 + s_dn[wg * 16 + g + 8]);
        float* orow0 = out + (size_t)r0 * (NHEADS * DHEAD) + h * DHEAD;
        float* orow1 = out + (size_t)r1 * (NHEADS * DHEAD) + h * DHEAD;
        #pragma unroll
        for (int nf = 0; nf < 8; nf++) {
            float2 x0 = *(const float2*)&s_acc[(wg * 16 + g) * 64 + nf * 8 + t2];
            float2 x1 = *(const float2*)&s_acc[(wg * 16 + g + 8) * 64 + nf * 8 + t2];
            float2 b2 = *(const float2*)&bias[h * DHEAD + nf * 8 + t2];
            float2 o0, o1;
            o0.x = fmaxf(fmaf(acc[nf][0] + x0.x, inv0, b2.x), 0.0f);
            o0.y = fmaxf(fmaf(acc[nf][1] + x0.y, inv0, b2.y), 0.0f);
            o1.x = fmaxf(fmaf(acc[nf][2] + x1.x, inv1, b2.x), 0.0f);
            o1.y = fmaxf(fmaf(acc[nf][3] + x1.y, inv1, b2.y), 0.0f);
            *(float2*)(orow0 + nf * 8 + t2) = o0;
            *(float2*)(orow1 + nf * 8 + t2) = o1;
        }
    }
}

// ---------------- launch ----------------
extern "C" void kernel_launch(void* const* d_in, const int* in_sizes, int n_in,
                              void* d_out, int out_size) {
    const float* x    = (const float*)d_in[0];
    const int*   adj  = (const int*)  d_in[1];
    const float* W    = (const float*)d_in[2];
    const float* a    = (const float*)d_in[3];
    const float* bias = (const float*)d_in[4];
    float* out = (float*)d_out;

    cudaFuncSetAttribute(k_attn, cudaFuncAttributeMaxDynamicSharedMemorySize, SME_TOT);

    k_init  <<<1, 32>>>();
    k_bits  <<<N_NODES, 256>>>(adj);
    k_xsplit<<<(N_NODES * F_IN) / 1024, 256>>>(x);
    k_wsplit<<<dim3(F_IN / 64, NHEADS), 256>>>(W);
    k_wx_mma<<<dim3(N_NODES / 64, NHEADS), 256>>>();
    k_trans <<<dim3(64, NHEADS), 256>>>(a);
    k_prep  <<<NHEADS, 1024>>>();
    k_attn  <<<dim3(N_NODES / 64, NHEADS), 256, SME_TOT>>>(bias, out);
}

// round 13
// speedup vs baseline: 6.0746x; 1.1041x over previous
#include <cuda_runtime.h>
#include <cuda_bf16.h>
#include <cuda_fp16.h>
#include <stdint.h>

#define N_NODES 4096
#define F_IN    512
#define NHEADS  4
#define DHEAD   64
#define BPAD    72

// ---------------- device scratch ----------------
__device__ float    g_ssrc[NHEADS * N_NODES];
__device__ float    g_sdst[NHEADS * N_NODES];
__device__ unsigned g_enc[2 * NHEADS];
__device__ __half   g_WxT[NHEADS * DHEAD * N_NODES];      // fp16 [h][d][n]
__device__ __nv_bfloat16 g_xhi[N_NODES * F_IN];
__device__ __nv_bfloat16 g_xlo[N_NODES * F_IN];
__device__ __nv_bfloat16 g_WT_hi[NHEADS * DHEAD * F_IN];
__device__ __nv_bfloat16 g_WT_lo[NHEADS * DHEAD * F_IN];
__device__ float2   g_E[NHEADS * N_NODES];       // {Ej1, Ej2}
__device__ float4   g_P[NHEADS * N_NODES];       // {Pi1', Pi2', -, -} per-row scaled
__device__ uint32_t g_bits[N_NODES * 128];       // adj bitmask, 2MB

// ---------------- helpers ----------------
__device__ __forceinline__ uint32_t pack_bf16x2(float lo, float hi) {
    uint32_t r;
    asm("cvt.rn.bf16x2.f32 %0, %1, %2;" : "=r"(r) : "f"(hi), "f"(lo));
    return r;
}
__device__ __forceinline__ float bf_lo_f(uint32_t w) { return __uint_as_float(w << 16); }
__device__ __forceinline__ float bf_hi_f(uint32_t w) { return __uint_as_float(w & 0xFFFF0000u); }

__device__ __forceinline__ uint32_t pack_f16x2(float lo, float hi) {
    uint32_t r;
    asm("cvt.rn.f16x2.f32 %0, %1, %2;" : "=r"(r) : "f"(hi), "f"(lo));
    return r;
}

__device__ __forceinline__ unsigned fenc(float f) {
    unsigned u = __float_as_uint(f);
    return (u & 0x80000000u) ? ~u : (u | 0x80000000u);
}
__device__ __forceinline__ float fdec(unsigned u) {
    unsigned b = (u & 0x80000000u) ? (u & 0x7FFFFFFFu) : ~u;
    return __uint_as_float(b);
}

__device__ __forceinline__ uint32_t smem_u32(const void* p) {
    uint32_t a;
    asm("{ .reg .u64 t; cvta.to.shared.u64 t, %1; cvt.u32.u64 %0, t; }" : "=r"(a) : "l"(p));
    return a;
}

__device__ __forceinline__ float fexp(float v) {
    float x = v * 1.4426950408889634f;
    x = fmaxf(x, -126.0f);
    float kf = x + 12582912.0f;
    int   ki = __float_as_int(kf) - 0x4B400000;
    float r  = x - (kf - 12582912.0f);
    float p  = 1.3333558146e-3f;
    p = fmaf(p, r, 9.6181291076e-3f);
    p = fmaf(p, r, 5.5504108664e-2f);
    p = fmaf(p, r, 2.4022650696e-1f);
    p = fmaf(p, r, 6.9314718056e-1f);
    p = fmaf(p, r, 1.0f);
    return __int_as_float(__float_as_int(p) + (ki << 23));
}

__device__ __forceinline__ void mma_bf16(float* c, const uint32_t* a, uint32_t b0, uint32_t b1) {
    asm volatile(
        "mma.sync.aligned.m16n8k16.row.col.f32.bf16.bf16.f32 "
        "{%0,%1,%2,%3}, {%4,%5,%6,%7}, {%8,%9}, {%0,%1,%2,%3};"
        : "+f"(c[0]), "+f"(c[1]), "+f"(c[2]), "+f"(c[3])
        : "r"(a[0]), "r"(a[1]), "r"(a[2]), "r"(a[3]), "r"(b0), "r"(b1));
}
__device__ __forceinline__ void mma_f16(float* c, const uint32_t* a, uint32_t b0, uint32_t b1) {
    asm volatile(
        "mma.sync.aligned.m16n8k16.row.col.f32.f16.f16.f32 "
        "{%0,%1,%2,%3}, {%4,%5,%6,%7}, {%8,%9}, {%0,%1,%2,%3};"
        : "+f"(c[0]), "+f"(c[1]), "+f"(c[2]), "+f"(c[3])
        : "r"(a[0]), "r"(a[1]), "r"(a[2]), "r"(a[3]), "r"(b0), "r"(b1));
}
__device__ __forceinline__ void ldsm_x4(uint32_t& r0, uint32_t& r1, uint32_t& r2, uint32_t& r3,
                                        uint32_t addr) {
    asm volatile("ldmatrix.sync.aligned.m8n8.x4.shared.b16 {%0,%1,%2,%3}, [%4];"
                 : "=r"(r0), "=r"(r1), "=r"(r2), "=r"(r3) : "r"(addr));
}

// ---------------- fused preprocessing: bits | xsplit | wsplit (+enc init) ----------------
// grid = 4096 (bits) + 2048 (xsplit) + 32 (wsplit) = 6176 blocks x 256 threads
__global__ __launch_bounds__(256) void k_pre(const int* __restrict__ adj,
                                             const float* __restrict__ x,
                                             const float* __restrict__ W) {
    __shared__ __align__(16) float s[64][65];
    const int bid = blockIdx.x, tid = threadIdx.x;

    if (bid == 0 && tid < 2 * NHEADS) g_enc[tid] = 0u;

    if (bid < 4096) {
        // ---- adj -> bitmask ----
        int wid = tid >> 5, lane = tid & 31;
        const int* arow = adj + (size_t)bid * N_NODES;
        #pragma unroll
        for (int w = 0; w < 16; w++) {
            int word = wid * 16 + w;
            uint32_t m = __ballot_sync(0xFFFFFFFFu, arow[word * 32 + lane] > 0);
            if (lane == 0) g_bits[bid * 128 + word] = m;
        }
    } else if (bid < 6144) {
        // ---- x -> bf16 hi/lo ----
        int i = ((bid - 4096) * 256 + tid) * 4;
        float4 v = *(const float4*)(x + i);
        uint32_t h0 = pack_bf16x2(v.x, v.y);
        uint32_t h1 = pack_bf16x2(v.z, v.w);
        uint32_t l0 = pack_bf16x2(v.x - bf_lo_f(h0), v.y - bf_hi_f(h0));
        uint32_t l1 = pack_bf16x2(v.z - bf_lo_f(h1), v.w - bf_hi_f(h1));
        *(uint2*)(g_xhi + i) = make_uint2(h0, h1);
        *(uint2*)(g_xlo + i) = make_uint2(l0, l1);
    } else {
        // ---- W split+transpose -> [h][d][k] bf16 hi/lo ----
        int b = bid - 6144;
        int k0 = (b & 7) * 64, h = b >> 3;
        const float* Wh = W + (size_t)h * F_IN * DHEAD;
        #pragma unroll
        for (int k = 0; k < 4; k++) {
            int e = tid + k * 256; int r = e >> 4, c4 = (e & 15) * 4;
            float4 v = *(const float4*)&Wh[(size_t)(k0 + r) * DHEAD + c4];
            s[r][c4 + 0] = v.x; s[r][c4 + 1] = v.y; s[r][c4 + 2] = v.z; s[r][c4 + 3] = v.w;
        }
        __syncthreads();
        int d = tid >> 2, kb = (tid & 3) * 16;
        uint32_t hw[8], lw[8];
        #pragma unroll
        for (int e = 0; e < 8; e++) {
            float f0 = s[kb + e * 2][d], f1 = s[kb + e * 2 + 1][d];
            uint32_t hp = pack_bf16x2(f0, f1);
            hw[e] = hp;
            lw[e] = pack_bf16x2(f0 - bf_lo_f(hp), f1 - bf_hi_f(hp));
        }
        size_t base = ((size_t)h * DHEAD + d) * F_IN + k0 + kb;
        *(uint4*)(g_WT_hi + base)     = make_uint4(hw[0], hw[1], hw[2], hw[3]);
        *(uint4*)(g_WT_hi + base + 8) = make_uint4(hw[4], hw[5], hw[6], hw[7]);
        *(uint4*)(g_WT_lo + base)     = make_uint4(lw[0], lw[1], lw[2], lw[3]);
        *(uint4*)(g_WT_lo + base + 8) = make_uint4(lw[4], lw[5], lw[6], lw[7]);
    }
}

// ---------------- kernel 1: Wx = x @ W per head, split-K HMMA; fused transpose+s epilogue ----------------
__global__ __launch_bounds__(256, 2) void k_wx_mma(const float* __restrict__ a) {
    __shared__ __align__(16) char swraw[36864 + 256];
    __nv_bfloat16* s_wh = (__nv_bfloat16*)swraw;
    __nv_bfloat16* s_wl = (__nv_bfloat16*)(swraw + 18432);
    float* s_t = (float*)swraw;                    // 64 x 65 fp32 (16.6KB) epilogue reuse

    const int tid = threadIdx.x, wid = tid >> 5, lane = tid & 31;
    const int g = lane >> 2, t2 = (lane & 3) * 2;
    const int wg = wid & 3, half = wid >> 2;
    const int h = blockIdx.y, i0 = blockIdx.x * 64;
    const int r0 = i0 + wg * 16 + g, r1 = r0 + 8;

    const __nv_bfloat16* wth = g_WT_hi + (size_t)h * DHEAD * F_IN;
    const __nv_bfloat16* wtl = g_WT_lo + (size_t)h * DHEAD * F_IN;

    float acc[8][4] = {};
    for (int chunk = 0; chunk < 4; chunk++) {
        const int kc = chunk * 64;
        __syncthreads();
        #pragma unroll
        for (int it = 0; it < 4; it++) {
            int e = tid + it * 256; int r = e >> 3, c = (e & 7) * 8;
            int d = r & 63, ks = (r >> 6) * 256 + kc + c;
            *(uint4*)&s_wh[r * BPAD + c] = *(const uint4*)&wth[(size_t)d * F_IN + ks];
            *(uint4*)&s_wl[r * BPAD + c] = *(const uint4*)&wtl[(size_t)d * F_IN + ks];
        }
        __syncthreads();

        uint32_t ahi[4][4], alo[4][4];
        #pragma unroll
        for (int kf = 0; kf < 4; kf++) {
            int k = half * 256 + kc + kf * 16 + t2;
            ahi[kf][0] = *(const uint32_t*)&g_xhi[(size_t)r0 * F_IN + k];
            ahi[kf][1] = *(const uint32_t*)&g_xhi[(size_t)r1 * F_IN + k];
            ahi[kf][2] = *(const uint32_t*)&g_xhi[(size_t)r0 * F_IN + k + 8];
            ahi[kf][3] = *(const uint32_t*)&g_xhi[(size_t)r1 * F_IN + k + 8];
            alo[kf][0] = *(const uint32_t*)&g_xlo[(size_t)r0 * F_IN + k];
            alo[kf][1] = *(const uint32_t*)&g_xlo[(size_t)r1 * F_IN + k];
            alo[kf][2] = *(const uint32_t*)&g_xlo[(size_t)r0 * F_IN + k + 8];
            alo[kf][3] = *(const uint32_t*)&g_xlo[(size_t)r1 * F_IN + k + 8];
        }
        #pragma unroll
        for (int nf = 0; nf < 8; nf++) {
            const int brow = (half * 64 + nf * 8 + g) * BPAD;
            #pragma unroll
            for (int kf = 0; kf < 4; kf++) {
                const int boff = brow + kf * 16 + t2;
                uint32_t bh0 = *(const uint32_t*)&s_wh[boff];
                uint32_t bh1 = *(const uint32_t*)&s_wh[boff + 8];
                uint32_t bl0 = *(const uint32_t*)&s_wl[boff];
                uint32_t bl1 = *(const uint32_t*)&s_wl[boff + 8];
                mma_bf16(acc[nf], ahi[kf], bh0, bh1);
                mma_bf16(acc[nf], alo[kf], bh0, bh1);
                mma_bf16(acc[nf], ahi[kf], bl0, bl1);
            }
        }
    }

    // ---- merge split-K halves into s_t (pad-65 rows) ----
    __syncthreads();
    if (half == 1) {
        #pragma unroll
        for (int nf = 0; nf < 8; nf++) {
            int c = nf * 8 + t2;
            s_t[(wg * 16 + g) * 65 + c]     = acc[nf][0];
            s_t[(wg * 16 + g) * 65 + c + 1] = acc[nf][1];
            s_t[(wg * 16 + g + 8) * 65 + c]     = acc[nf][2];
            s_t[(wg * 16 + g + 8) * 65 + c + 1] = acc[nf][3];
        }
    }
    __syncthreads();
    if (half == 0) {
        #pragma unroll
        for (int nf = 0; nf < 8; nf++) {
            int c = nf * 8 + t2;
            s_t[(wg * 16 + g) * 65 + c]     += acc[nf][0];
            s_t[(wg * 16 + g) * 65 + c + 1] += acc[nf][1];
            s_t[(wg * 16 + g + 8) * 65 + c]     += acc[nf][2];
            s_t[(wg * 16 + g + 8) * 65 + c + 1] += acc[nf][3];
        }
    }
    __syncthreads();

    // ---- fused k_trans: fp16 transposed write ----
    {
        int d = tid >> 2, nb = (tid & 3) * 16;
        uint32_t hw[8];
        #pragma unroll
        for (int e = 0; e < 8; e++) {
            float f0 = s_t[(nb + e * 2) * 65 + d];
            float f1 = s_t[(nb + e * 2 + 1) * 65 + d];
            hw[e] = pack_f16x2(f0, f1);
        }
        size_t base = ((size_t)h * DHEAD + d) * N_NODES + i0 + nb;
        *(uint4*)(g_WxT + base)     = make_uint4(hw[0], hw[1], hw[2], hw[3]);
        *(uint4*)(g_WxT + base + 8) = make_uint4(hw[4], hw[5], hw[6], hw[7]);
    }
    // ---- fused k_s: s_src/s_dst + per-head maxima ----
    {
        int row = tid >> 2, tg = tid & 3;
        const float* a1 = a + h * 2 * DHEAD;
        const float* a2 = a1 + DHEAD;
        float ps = 0.0f, pd = 0.0f;
        #pragma unroll
        for (int d = tg * 16; d < tg * 16 + 16; d++) {
            float w = s_t[row * 65 + d];
            ps = fmaf(w, a1[d], ps);
            pd = fmaf(w, a2[d], pd);
        }
        ps += __shfl_xor_sync(0xFFFFFFFFu, ps, 1);
        ps += __shfl_xor_sync(0xFFFFFFFFu, ps, 2);
        pd += __shfl_xor_sync(0xFFFFFFFFu, pd, 1);
        pd += __shfl_xor_sync(0xFFFFFFFFu, pd, 2);
        if (tg == 0) {
            g_ssrc[h * N_NODES + i0 + row] = ps;
            g_sdst[h * N_NODES + i0 + row] = pd;
            atomicMax(&g_enc[h],          fenc(ps));
            atomicMax(&g_enc[NHEADS + h], fenc(pd));
        }
    }
}

// ---------------- kernel 2c: E/P tables per head (per-row scaled) ----------------
__global__ __launch_bounds__(1024) void k_prep() {
    int h = blockIdx.x, tid = threadIdx.x;
    const float maxsrc = fdec(g_enc[h]);
    const float maxdst = fdec(g_enc[NHEADS + h]);
    const float S  = maxsrc + maxdst;
    const float Mh = fmaxf(S, 0.2f * S);
    const float r_ = Mh - 0.2f * S;
    const float c_ = 0.2f * maxsrc + 0.5f * r_;
    const float d_ = 0.2f * maxdst + 0.5f * r_;
    const float maxE2 = fexp(-0.5f * r_);
    #pragma unroll
    for (int k = 0; k < 4; k++) {
        int j = tid + k * 1024;
        float sj = g_sdst[h * N_NODES + j];
        g_E[h * N_NODES + j] = make_float2(fexp(sj - maxdst), fexp(fmaf(0.2f, sj, -d_)));
        float si = g_ssrc[h * N_NODES + j];
        float Pi1 = fexp(si - maxsrc);
        float Pi2 = fexp(fmaf(0.2f, si, -c_));
        float sc = 1.0f / fmaxf(Pi1, Pi2 * maxE2);
        g_P[h * N_NODES + j] = make_float4(Pi1 * sc, Pi2 * sc, 0.0f, 0.0f);
    }
}

// ---------------- kernel 3: staggered MMA/pgen overlap, ldmatrix B, max-trick p ----------------
#define SME_E   18432
#define SME_TOT (18432 + 32768)

__global__ __launch_bounds__(256, 2) void k_attn(const float* __restrict__ bias,
                                                 float* __restrict__ out) {
    extern __shared__ __align__(16) char sraw[];
    float* sE    = (float*)(sraw + SME_E);
    float* s_acc = (float*)sraw;
    float* s_dn  = (float*)(sraw + 16384);

    const int tid = threadIdx.x, wid = tid >> 5, lane = tid & 31;
    const int g = lane >> 2, t2 = (lane & 3) * 2;
    const int wg = wid & 3, half = wid >> 2;
    const int h = blockIdx.y, i0 = blockIdx.x * 64;

    const int r0 = i0 + wg * 16 + g, r1 = r0 + 8;
    const float4 P0 = g_P[h * N_NODES + r0];
    const float4 P1 = g_P[h * N_NODES + r1];
    const int jb0 = half * 32 + t2;

    const __half* bp = g_WxT + (size_t)h * DHEAD * N_NODES;

    const int e0 = tid * 2, e1 = tid * 2 + 1;
    const int pr0 = e0 >> 3, pc0 = (e0 & 7) * 8;
    const int pr1 = e1 >> 3, pc1 = (e1 & 7) * 8;

    const uint32_t sb32 = smem_u32(sraw);
    const int mi = lane >> 3, ri = lane & 7;
    const uint32_t ldsm_lane =
        sb32 + (uint32_t)((((mi >> 1) * 8 + ri) * BPAD) * 2 + (mi & 1) * 16 + half * 64);

    {
        const float4* src = (const float4*)(g_E + h * N_NODES);
        float4* dst = (float4*)sE;
        #pragma unroll
        for (int k = 0; k < 8; k++) dst[tid + k * 256] = src[tid + k * 256];
    }
    {
        __half* bh = (__half*)sraw;
        *(uint4*)&bh[pr0 * BPAD + pc0] = *(const uint4*)(bp + (size_t)pr0 * N_NODES + pc0);
        *(uint4*)&bh[pr1 * BPAD + pc1] = *(const uint4*)(bp + (size_t)pr1 * N_NODES + pc1);
    }
    uint32_t mn0 = g_bits[r0 * 128 + half];
    uint32_t mn1 = g_bits[r1 * 128 + half];
    __syncthreads();

    uint32_t aF[2][2][4];
    float den0 = 0.0f, den1 = 0.0f;

    #define PGEN(jt, buf)                                                          \
    do {                                                                           \
        const int _j = (jt) * 64;                                                  \
        float4 EA0 = *(const float4*)&sE[(_j + jb0) * 2];                          \
        float4 EB0 = *(const float4*)&sE[(_j + jb0 + 8) * 2];                      \
        float4 EA1 = *(const float4*)&sE[(_j + jb0 + 16) * 2];                     \
        float4 EB1 = *(const float4*)&sE[(_j + jb0 + 24) * 2];                     \
        _Pragma("unroll")                                                          \
        for (int kf = 0; kf < 2; kf++) {                                           \
            const float4 eA = kf ? EA1 : EA0;                                      \
            const float4 eB = kf ? EB1 : EB0;                                      \
            const uint32_t ma0 = mn0 >> (kf * 16 + t2);                            \
            const uint32_t ma1 = mn1 >> (kf * 16 + t2);                            \
            float p00 = (ma0 & 1u)   ? fmaxf(P0.x * eA.x, P0.y * eA.y) : 0.0f;     \
            float p01 = (ma0 & 2u)   ? fmaxf(P0.x * eA.z, P0.y * eA.w) : 0.0f;     \
            float p08 = (ma0 & 256u) ? fmaxf(P0.x * eB.x, P0.y * eB.y) : 0.0f;     \
            float p09 = (ma0 & 512u) ? fmaxf(P0.x * eB.z, P0.y * eB.w) : 0.0f;     \
            float p10 = (ma1 & 1u)   ? fmaxf(P1.x * eA.x, P1.y * eA.y) : 0.0f;     \
            float p11 = (ma1 & 2u)   ? fmaxf(P1.x * eA.z, P1.y * eA.w) : 0.0f;     \
            float p18 = (ma1 & 256u) ? fmaxf(P1.x * eB.x, P1.y * eB.y) : 0.0f;     \
            float p19 = (ma1 & 512u) ? fmaxf(P1.x * eB.z, P1.y * eB.w) : 0.0f;     \
            den0 += (p00 + p01) + (p08 + p09);                                     \
            den1 += (p10 + p11) + (p18 + p19);                                     \
            aF[buf][kf][0] = pack_f16x2(p00, p01);                                 \
            aF[buf][kf][1] = pack_f16x2(p10, p11);                                 \
            aF[buf][kf][2] = pack_f16x2(p08, p09);                                 \
            aF[buf][kf][3] = pack_f16x2(p18, p19);                                 \
        }                                                                          \
    } while (0)

    #define MMA_BLOCK(cur)                                                         \
    do {                                                                           \
        const uint32_t bbase = ldsm_lane + (cur) * 9216u;                          \
        _Pragma("unroll")                                                          \
        for (int nfp = 0; nfp < 4; nfp++) {                                        \
            _Pragma("unroll")                                                      \
            for (int kf = 0; kf < 2; kf++) {                                       \
                uint32_t b0, b1, b2, b3;                                           \
                ldsm_x4(b0, b1, b2, b3, bbase + nfp * 2304u + kf * 32u);           \
                mma_f16(acc[2 * nfp],     aF[cur][kf], b0, b1);                    \
                mma_f16(acc[2 * nfp + 1], aF[cur][kf], b2, b3);                    \
            }                                                                      \
        }                                                                          \
    } while (0)

    PGEN(0, 0);

    mn0 = g_bits[r0 * 128 + 2 + half];
    mn1 = g_bits[r1 * 128 + 2 + half];
    uint4 nh0 = *(const uint4*)(bp + (size_t)pr0 * N_NODES + 64 + pc0);
    uint4 nh1 = *(const uint4*)(bp + (size_t)pr1 * N_NODES + 64 + pc1);

    float acc[8][4] = {};

    for (int t = 0; t < 64; t++) {
        const int cur = t & 1;

        if (half == 0) {
            MMA_BLOCK(cur);
            if (t < 63) PGEN(t + 1, 1 - cur);
        } else {
            if (t < 63) PGEN(t + 1, 1 - cur);
            MMA_BLOCK(cur);
        }

        if (t < 63) {
            __half* bh = (__half*)(sraw + (1 - cur) * 9216);
            *(uint4*)&bh[pr0 * BPAD + pc0] = nh0;
            *(uint4*)&bh[pr1 * BPAD + pc1] = nh1;
            if (t < 62) {
                const int jn2 = (t + 2) * 64;
                mn0 = g_bits[r0 * 128 + (t + 2) * 2 + half];
                mn1 = g_bits[r1 * 128 + (t + 2) * 2 + half];
                nh0 = *(const uint4*)(bp + (size_t)pr0 * N_NODES + jn2 + pc0);
                nh1 = *(const uint4*)(bp + (size_t)pr1 * N_NODES + jn2 + pc1);
            }
        }
        __syncthreads();
    }
    #undef PGEN
    #undef MMA_BLOCK

    den0 += __shfl_xor_sync(0xFFFFFFFFu, den0, 1);
    den0 += __shfl_xor_sync(0xFFFFFFFFu, den0, 2);
    den1 += __shfl_xor_sync(0xFFFFFFFFu, den1, 1);
    den1 += __shfl_xor_sync(0xFFFFFFFFu, den1, 2);

    if (half == 1) {
        if ((lane & 3) == 0) {
            s_dn[wg * 16 + g]     = den0;
            s_dn[wg * 16 + g + 8] = den1;
        }
        #pragma unroll
        for (int nf = 0; nf < 8; nf++) {
            *(float2*)&s_acc[(wg * 16 + g) * 64 + nf * 8 + t2]     = make_float2(acc[nf][0], acc[nf][1]);
            *(float2*)&s_acc[(wg * 16 + g + 8) * 64 + nf * 8 + t2] = make_float2(acc[nf][2], acc[nf][3]);
        }
    }
    __syncthreads();
    if (half == 0) {
        const float inv0 = 1.0f / (den0 + s_dn[wg * 16 + g]);
        const float inv1 = 1.0f / (den1 + s_dn[wg * 16 + g + 8]);
        float* orow0 = out + (size_t)r0 * (NHEADS * DHEAD) + h * DHEAD;
        float* orow1 = out + (size_t)r1 * (NHEADS * DHEAD) + h * DHEAD;
        #pragma unroll
        for (int nf = 0; nf < 8; nf++) {
            float2 x0 = *(const float2*)&s_acc[(wg * 16 + g) * 64 + nf * 8 + t2];
            float2 x1 = *(const float2*)&s_acc[(wg * 16 + g + 8) * 64 + nf * 8 + t2];
            float2 b2 = *(const float2*)&bias[h * DHEAD + nf * 8 + t2];
            float2 o0, o1;
            o0.x = fmaxf(fmaf(acc[nf][0] + x0.x, inv0, b2.x), 0.0f);
            o0.y = fmaxf(fmaf(acc[nf][1] + x0.y, inv0, b2.y), 0.0f);
            o1.x = fmaxf(fmaf(acc[nf][2] + x1.x, inv1, b2.x), 0.0f);
            o1.y = fmaxf(fmaf(acc[nf][3] + x1.y, inv1, b2.y), 0.0f);
            *(float2*)(orow0 + nf * 8 + t2) = o0;
            *(float2*)(orow1 + nf * 8 + t2) = o1;
        }
    }
}

// ---------------- launch ----------------
extern "C" void kernel_launch(void* const* d_in, const int* in_sizes, int n_in,
                              void* d_out, int out_size) {
    const float* x    = (const float*)d_in[0];
    const int*   adj  = (const int*)  d_in[1];
    const float* W    = (const float*)d_in[2];
    const float* a    = (const float*)d_in[3];
    const float* bias = (const float*)d_in[4];
    float* out = (float*)d_out;

    cudaFuncSetAttribute(k_attn, cudaFuncAttributeMaxDynamicSharedMemorySize, SME_TOT);

    k_pre   <<<6176, 256>>>(adj, x, W);
    k_wx_mma<<<dim3(N_NODES / 64, NHEADS), 256>>>(a);
    k_prep  <<<NHEADS, 1024>>>();
    k_attn  <<<dim3(N_NODES / 64, NHEADS), 256, SME_TOT>>>(bias, out);
}